// round 10
// baseline (speedup 1.0000x reference)
#include <cuda_runtime.h>
#include <cuda_bf16.h>
#include <cstdint>
#include <math.h>

typedef unsigned int u32;
typedef unsigned long long u64;

// ---------------- problem constants ----------------
#define BB   4
#define CC   192
#define HH   64
#define WW   64
#define LL   (HH*WW)          // 4096
#define MM   (BB*LL)          // 16384
#define DI   384
#define DS   16
#define DTR  12
#define NDBL 44               // DTR + 2*DS
#define NC   32               // scan chunks
#define LC   (LL/NC)          // 128
#define SW   16               // scan smem window (timesteps)
#define NW   (LC/SW)          // 8 windows
#define KO   768              // out_proj extended K (= 2*DI)
#define LOG2E 1.4426950408889634f
#define LN2   0.6931471805599453f

// ---------------- scratch (device globals: allocation-free) ----------------
__device__ __align__(128) float g_xz [(size_t)MM*768];
__device__ __align__(128) float g_dbl[2][(size_t)MM*NDBL];
__device__ float g_hend  [2*BB*NC*DI*DS];
__device__ float g_pend  [2*BB*NC*DI*DS];
__device__ float g_hstart[2*BB*NC*DI*DS];

// bf16 hi/lo pairs for tensor-core GEMMs (k-contiguous natural layouts)
__device__ __align__(128) __nv_bfloat16 g_xnh[(size_t)MM*CC];
__device__ __align__(128) __nv_bfloat16 g_xnl[(size_t)MM*CC];
__device__ __align__(128) __nv_bfloat16 g_xsh[2][(size_t)MM*DI];
__device__ __align__(128) __nv_bfloat16 g_xsl[2][(size_t)MM*DI];
__device__ __align__(128) __nv_bfloat16 g_Gh [(size_t)MM*KO];   // [m][dir*DI + d]
__device__ __align__(128) __nv_bfloat16 g_Gl [(size_t)MM*KO];
__device__ __align__(128) __nv_bfloat16 g_wih[768*CC];
__device__ __align__(128) __nv_bfloat16 g_wil[768*CC];
__device__ __align__(128) __nv_bfloat16 g_wxh[128*DI];   // x_proj W padded 44->128 rows
__device__ __align__(128) __nv_bfloat16 g_wxl[128*DI];
__device__ __align__(128) __nv_bfloat16 g_woh[256*KO];   // out_proj W dup'd [Wo, Wo], padded 192->256
__device__ __align__(128) __nv_bfloat16 g_wol[256*KO];

__device__ __forceinline__ float ex2(float x){
    float r; asm("ex2.approx.ftz.f32 %0, %1;" : "=f"(r) : "f"(x)); return r;
}
__device__ __forceinline__ float silu_f(float x){
    return x / (1.f + __expf(-x));
}
__device__ __forceinline__ float sp_f(float v){   // softplus
    if (v > 15.f) return v;
    float e = ex2(v * LOG2E);
    return __log2f(1.f + e) * LN2;
}
__device__ __forceinline__ void split_bf16(float v, __nv_bfloat16& h, __nv_bfloat16& l){
    h = __float2bfloat16(v);
    l = __float2bfloat16(v - __bfloat162float(h));
}
__device__ __forceinline__ float b2f(__nv_bfloat16 v){ return __bfloat162float(v); }

// ---------------- packed f32x2 helpers (sm_103a FFMA2 via PTX) ----------------
__device__ __forceinline__ u64 pk2(float lo, float hi){
    u64 d; asm("mov.b64 %0, {%1,%2};" : "=l"(d) : "f"(lo), "f"(hi)); return d;
}
__device__ __forceinline__ void upk2(float& lo, float& hi, u64 v){
    asm("mov.b64 {%0,%1}, %2;" : "=f"(lo), "=f"(hi) : "l"(v));
}
__device__ __forceinline__ u64 fma2_(u64 a, u64 b, u64 c){
    u64 d; asm("fma.rn.f32x2 %0, %1, %2, %3;" : "=l"(d) : "l"(a), "l"(b), "l"(c)); return d;
}
__device__ __forceinline__ u64 mul2_(u64 a, u64 b){
    u64 d; asm("mul.rn.f32x2 %0, %1, %2;" : "=l"(d) : "l"(a), "l"(b)); return d;
}

// ---------------- PTX helpers ----------------
__device__ __forceinline__ void cpa16(u32 dst, const void* src){
    asm volatile("cp.async.ca.shared.global [%0], [%1], 16;" :: "r"(dst), "l"(src));
}
__device__ __forceinline__ void cp_commit(){
    asm volatile("cp.async.commit_group;");
}
__device__ __forceinline__ void cp_wait1(){
    asm volatile("cp.async.wait_group 1;");
}
__device__ __forceinline__ void cp_wait0(){
    asm volatile("cp.async.wait_group 0;");
}
__device__ __forceinline__ void ldsm4(u32& x0, u32& x1, u32& x2, u32& x3, u32 addr){
    asm volatile("ldmatrix.sync.aligned.m8n8.x4.shared.b16 {%0,%1,%2,%3}, [%4];"
                 : "=r"(x0), "=r"(x1), "=r"(x2), "=r"(x3) : "r"(addr));
}
__device__ __forceinline__ void mma16816(float& d0, float& d1, float& d2, float& d3,
                                         u32 a0, u32 a1, u32 a2, u32 a3,
                                         u32 v0, u32 v1){
    asm volatile("mma.sync.aligned.m16n8k16.row.col.f32.bf16.bf16.f32 "
                 "{%0,%1,%2,%3},{%4,%5,%6,%7},{%8,%9},{%0,%1,%2,%3};"
                 : "+f"(d0), "+f"(d1), "+f"(d2), "+f"(d3)
                 : "r"(a0), "r"(a1), "r"(a2), "r"(a3), "r"(v0), "r"(v1));
}

// ---------------- 1) LayerNorm over channels -> bf16 hi/lo ----------------
__global__ void ln_kernel(const float* __restrict__ x,
                          const float* __restrict__ w,
                          const float* __restrict__ bsh)
{
    int b = blockIdx.y, p0 = blockIdx.x * 32;
    int tx = threadIdx.x, ty = threadIdx.y;
    __shared__ float sx[CC][33];
    __shared__ float red[2][8][32];
    __shared__ float smu[32], srs[32];

    float s1 = 0.f, s2 = 0.f;
    for (int c = ty; c < CC; c += 8) {
        float v = x[((size_t)(b*CC + c))*LL + p0 + tx];
        sx[c][tx] = v; s1 += v; s2 += v*v;
    }
    red[0][ty][tx] = s1; red[1][ty][tx] = s2;
    __syncthreads();
    if (ty == 0) {
        float a = 0.f, q = 0.f;
        #pragma unroll
        for (int j = 0; j < 8; j++){ a += red[0][j][tx]; q += red[1][j][tx]; }
        float mu = a / CC;
        float var = q / CC - mu*mu;
        smu[tx] = mu; srs[tx] = rsqrtf(var + 1e-5f);
    }
    __syncthreads();
    int tid = ty*32 + tx;
    for (int e = tid; e < 32*CC; e += 256) {
        int pp = e / CC, cc = e % CC;
        float v = (sx[cc][pp] - smu[pp]) * srs[pp] * w[cc] + bsh[cc];
        size_t idx = ((size_t)(b*LL + p0 + pp))*CC + cc;
        __nv_bfloat16 h, l; split_bf16(v, h, l);
        g_xnh[idx] = h; g_xnl[idx] = l;
    }
}

// ---------------- weight conversion (hi/lo split + zero padding) ----------------
__global__ void cvt_weights(const float* __restrict__ wi,
                            const float* __restrict__ wx,
                            const float* __restrict__ wo)
{
    int stride = gridDim.x * blockDim.x;
    int t = blockIdx.x * blockDim.x + threadIdx.x;
    for (int e = t; e < 768*CC; e += stride) {
        __nv_bfloat16 h, l; split_bf16(wi[e], h, l);
        g_wih[e] = h; g_wil[e] = l;
    }
    for (int e = t; e < 128*DI; e += stride) {
        int n = e / DI, k = e % DI;
        float v = (n < NDBL) ? wx[n*DI + k] : 0.f;
        __nv_bfloat16 h, l; split_bf16(v, h, l);
        g_wxh[e] = h; g_wxl[e] = l;
    }
    for (int e = t; e < 256*KO; e += stride) {
        int n = e / KO, k = e % KO;
        float v = (n < CC) ? wo[n*DI + (k % DI)] : 0.f;   // duplicated K-halves
        __nv_bfloat16 h, l; split_bf16(v, h, l);
        g_woh[e] = h; g_wol[e] = l;
    }
}

// ---------------- tensor-core GEMM mainloop (shared by both kernels) ----------
#define ROWB   80
#define OFF_AH 0
#define OFF_AL (128*ROWB)
#define OFF_BH (2*128*ROWB)
#define OFF_BL (3*128*ROWB)
#define STAGEB (4*128*ROWB)
#define SMEM_TC (2*STAGEB)

__device__ __forceinline__ void tc_mainloop(
    const __nv_bfloat16* Ahp, const __nv_bfloat16* Alp,
    const __nv_bfloat16* Bhp, const __nv_bfloat16* Blp,
    int K, int m0, int n0, char* smem, float acc[2][8][4])
{
    u32 sbase = (u32)__cvta_generic_to_shared(smem);
    int tid = threadIdx.x;
    int lane = tid & 31, wid = tid >> 5;
    int wm = wid & 3, wn = wid >> 2;

    int r0c = tid >> 2, c0c = tid & 3;
    int r1c = (tid + 256) >> 2, c1c = (tid + 256) & 3;
    int NIT = K / 32;

    for (int pre = 0; pre < 2 && pre < NIT; pre++) {
        int k0 = pre * 32;
        u32 st = sbase + (u32)(pre & 1) * STAGEB;
        cpa16(st + OFF_AH + r0c*ROWB + c0c*16, Ahp + (size_t)(m0 + r0c)*K + k0 + c0c*8);
        cpa16(st + OFF_AH + r1c*ROWB + c1c*16, Ahp + (size_t)(m0 + r1c)*K + k0 + c1c*8);
        cpa16(st + OFF_AL + r0c*ROWB + c0c*16, Alp + (size_t)(m0 + r0c)*K + k0 + c0c*8);
        cpa16(st + OFF_AL + r1c*ROWB + c1c*16, Alp + (size_t)(m0 + r1c)*K + k0 + c1c*8);
        cpa16(st + OFF_BH + r0c*ROWB + c0c*16, Bhp + (size_t)(n0 + r0c)*K + k0 + c0c*8);
        cpa16(st + OFF_BH + r1c*ROWB + c1c*16, Bhp + (size_t)(n0 + r1c)*K + k0 + c1c*8);
        cpa16(st + OFF_BL + r0c*ROWB + c0c*16, Blp + (size_t)(n0 + r0c)*K + k0 + c0c*8);
        cpa16(st + OFF_BL + r1c*ROWB + c1c*16, Blp + (size_t)(n0 + r1c)*K + k0 + c1c*8);
        cp_commit();
    }

    for (int it = 0; it < NIT; it++) {
        cp_wait1();
        __syncthreads();

        u32 st = sbase + (u32)(it & 1) * STAGEB;
        #pragma unroll
        for (int ks = 0; ks < 2; ks++) {
            u32 fah0[4], fah1[4], fal0[4], fal1[4];
            {
                u32 adr0 = st + OFF_AH + (u32)((wm*32 + (lane & 15))*ROWB
                         + ks*32 + (lane >> 4)*16);
                u32 adr1 = adr0 + 16*ROWB;
                ldsm4(fah0[0], fah0[1], fah0[2], fah0[3], adr0);
                ldsm4(fal0[0], fal0[1], fal0[2], fal0[3], adr0 + (OFF_AL - OFF_AH));
                ldsm4(fah1[0], fah1[1], fah1[2], fah1[3], adr1);
                ldsm4(fal1[0], fal1[1], fal1[2], fal1[3], adr1 + (OFF_AL - OFF_AH));
            }
            #pragma unroll
            for (int j = 0; j < 4; j++) {
                u32 fbh[4], fbl[4];
                u32 bdr = st + OFF_BH + (u32)((wn*64 + j*16 + (lane & 15))*ROWB
                        + ks*32 + (lane >> 4)*16);
                ldsm4(fbh[0], fbh[1], fbh[2], fbh[3], bdr);
                ldsm4(fbl[0], fbl[1], fbl[2], fbl[3], bdr + (OFF_BL - OFF_BH));

                mma16816(acc[0][2*j][0], acc[0][2*j][1], acc[0][2*j][2], acc[0][2*j][3],
                         fah0[0], fah0[1], fah0[2], fah0[3], fbh[0], fbh[2]);
                mma16816(acc[0][2*j][0], acc[0][2*j][1], acc[0][2*j][2], acc[0][2*j][3],
                         fah0[0], fah0[1], fah0[2], fah0[3], fbl[0], fbl[2]);
                mma16816(acc[0][2*j][0], acc[0][2*j][1], acc[0][2*j][2], acc[0][2*j][3],
                         fal0[0], fal0[1], fal0[2], fal0[3], fbh[0], fbh[2]);
                mma16816(acc[0][2*j+1][0], acc[0][2*j+1][1], acc[0][2*j+1][2], acc[0][2*j+1][3],
                         fah0[0], fah0[1], fah0[2], fah0[3], fbh[1], fbh[3]);
                mma16816(acc[0][2*j+1][0], acc[0][2*j+1][1], acc[0][2*j+1][2], acc[0][2*j+1][3],
                         fah0[0], fah0[1], fah0[2], fah0[3], fbl[1], fbl[3]);
                mma16816(acc[0][2*j+1][0], acc[0][2*j+1][1], acc[0][2*j+1][2], acc[0][2*j+1][3],
                         fal0[0], fal0[1], fal0[2], fal0[3], fbh[1], fbh[3]);

                mma16816(acc[1][2*j][0], acc[1][2*j][1], acc[1][2*j][2], acc[1][2*j][3],
                         fah1[0], fah1[1], fah1[2], fah1[3], fbh[0], fbh[2]);
                mma16816(acc[1][2*j][0], acc[1][2*j][1], acc[1][2*j][2], acc[1][2*j][3],
                         fah1[0], fah1[1], fah1[2], fah1[3], fbl[0], fbl[2]);
                mma16816(acc[1][2*j][0], acc[1][2*j][1], acc[1][2*j][2], acc[1][2*j][3],
                         fal1[0], fal1[1], fal1[2], fal1[3], fbh[0], fbh[2]);
                mma16816(acc[1][2*j+1][0], acc[1][2*j+1][1], acc[1][2*j+1][2], acc[1][2*j+1][3],
                         fah1[0], fah1[1], fah1[2], fah1[3], fbh[1], fbh[3]);
                mma16816(acc[1][2*j+1][0], acc[1][2*j+1][1], acc[1][2*j+1][2], acc[1][2*j+1][3],
                         fah1[0], fah1[1], fah1[2], fah1[3], fbl[1], fbl[3]);
                mma16816(acc[1][2*j+1][0], acc[1][2*j+1][1], acc[1][2*j+1][2], acc[1][2*j+1][3],
                         fal1[0], fal1[1], fal1[2], fal1[3], fbh[1], fbh[3]);
            }
        }
        __syncthreads();
        if (it + 2 < NIT) {
            int k0 = (it + 2) * 32;
            u32 st2 = sbase + (u32)((it + 2) & 1) * STAGEB;
            cpa16(st2 + OFF_AH + r0c*ROWB + c0c*16, Ahp + (size_t)(m0 + r0c)*K + k0 + c0c*8);
            cpa16(st2 + OFF_AH + r1c*ROWB + c1c*16, Ahp + (size_t)(m0 + r1c)*K + k0 + c1c*8);
            cpa16(st2 + OFF_AL + r0c*ROWB + c0c*16, Alp + (size_t)(m0 + r0c)*K + k0 + c0c*8);
            cpa16(st2 + OFF_AL + r1c*ROWB + c1c*16, Alp + (size_t)(m0 + r1c)*K + k0 + c1c*8);
            cpa16(st2 + OFF_BH + r0c*ROWB + c0c*16, Bhp + (size_t)(n0 + r0c)*K + k0 + c0c*8);
            cpa16(st2 + OFF_BH + r1c*ROWB + c1c*16, Bhp + (size_t)(n0 + r1c)*K + k0 + c1c*8);
            cpa16(st2 + OFF_BL + r0c*ROWB + c0c*16, Blp + (size_t)(n0 + r0c)*K + k0 + c0c*8);
            cpa16(st2 + OFF_BL + r1c*ROWB + c1c*16, Blp + (size_t)(n0 + r1c)*K + k0 + c1c*8);
        }
        cp_commit();
    }
}

// plain fp32 store (z-batched)
__global__ void __launch_bounds__(256)
gemm_tc_store(const __nv_bfloat16* __restrict__ Ahp, const __nv_bfloat16* __restrict__ Alp,
              const __nv_bfloat16* __restrict__ Bhp, const __nv_bfloat16* __restrict__ Blp,
              float* __restrict__ C, int K, int N, int ldc, size_t aZ, size_t cZ)
{
    extern __shared__ char smem[];
    float acc[2][8][4];
    #pragma unroll
    for (int i = 0; i < 2; i++)
        #pragma unroll
        for (int j = 0; j < 8; j++)
            #pragma unroll
            for (int q = 0; q < 4; q++) acc[i][j][q] = 0.f;

    int m0 = blockIdx.y*128, n0 = blockIdx.x*128;
    tc_mainloop(Ahp + (size_t)blockIdx.z*aZ, Alp + (size_t)blockIdx.z*aZ,
                Bhp, Blp, K, m0, n0, smem, acc);
    C += (size_t)blockIdx.z * cZ;

    int lane = threadIdx.x & 31, wid = threadIdx.x >> 5;
    int wm = wid & 3, wn = wid >> 2;
    int gp = lane >> 2, tg = lane & 3;
    #pragma unroll
    for (int mi = 0; mi < 2; mi++) {
        int row = m0 + wm*32 + mi*16 + gp;
        #pragma unroll
        for (int ni = 0; ni < 8; ni++) {
            int col = n0 + wn*64 + ni*8 + tg*2;
            if (col < N) {
                float2 v0; v0.x = acc[mi][ni][0]; v0.y = acc[mi][ni][1];
                float2 v1; v1.x = acc[mi][ni][2]; v1.y = acc[mi][ni][3];
                *(float2*)&C[(size_t)row*ldc + col]       = v0;
                *(float2*)&C[(size_t)(row + 8)*ldc + col] = v1;
            }
        }
    }
}

// transposed store to d_out laid out (B, C, L)
__global__ void __launch_bounds__(256)
gemm_tc_out(const __nv_bfloat16* __restrict__ Ahp, const __nv_bfloat16* __restrict__ Alp,
            const __nv_bfloat16* __restrict__ Bhp, const __nv_bfloat16* __restrict__ Blp,
            int K, int N, float* __restrict__ dout)
{
    extern __shared__ char smem[];
    float acc[2][8][4];
    #pragma unroll
    for (int i = 0; i < 2; i++)
        #pragma unroll
        for (int j = 0; j < 8; j++)
            #pragma unroll
            for (int q = 0; q < 4; q++) acc[i][j][q] = 0.f;

    int m0 = blockIdx.y*128, n0 = blockIdx.x*128;
    tc_mainloop(Ahp, Alp, Bhp, Blp, K, m0, n0, smem, acc);

    cp_wait0();
    __syncthreads();
    float* so = (float*)smem;   // [128][132]
    int lane = threadIdx.x & 31, wid = threadIdx.x >> 5;
    int wm = wid & 3, wn = wid >> 2;
    int gp = lane >> 2, tg = lane & 3;
    #pragma unroll
    for (int mi = 0; mi < 2; mi++) {
        int ml = wm*32 + mi*16 + gp;
        #pragma unroll
        for (int ni = 0; ni < 8; ni++) {
            int nl = wn*64 + ni*8 + tg*2;
            so[(size_t)nl*132 + ml]         = acc[mi][ni][0];
            so[(size_t)(nl+1)*132 + ml]     = acc[mi][ni][1];
            so[(size_t)nl*132 + ml + 8]     = acc[mi][ni][2];
            so[(size_t)(nl+1)*132 + ml + 8] = acc[mi][ni][3];
        }
    }
    __syncthreads();
    int b = m0 >> 12, p0 = m0 & (LL - 1);
    for (int e = threadIdx.x; e < 128*128; e += 256) {
        int nl = e >> 7, mlp = e & 127;
        int n = n0 + nl;
        if (n < N)
            dout[((size_t)(b*CC + n))*LL + p0 + mlp] = so[(size_t)nl*132 + mlp];
    }
}

// ---------------- depthwise causal conv (both directions) + silu -> bf16 hi/lo ----
__global__ void conv_silu_kernel(const float* __restrict__ cw, const float* __restrict__ cb)
{
    __shared__ float s[16 + 6][DI];
    int b = blockIdx.y, t0 = blockIdx.x * 16, d = threadIdx.x;

    #pragma unroll
    for (int j = 0; j < 22; j++) {
        int t = t0 - 3 + j;
        float v = 0.f;
        if (t >= 0 && t < LL) v = g_xz[((size_t)(b*LL + t))*768 + d];
        s[j][d] = v;
    }
    __syncthreads();
    float w0 = cw[d*4+0], w1 = cw[d*4+1], w2 = cw[d*4+2], w3 = cw[d*4+3];
    float bias = cb[d];
    #pragma unroll
    for (int tt = 0; tt < 16; tt++) {
        float of = w0*s[tt][d] + w1*s[tt+1][d] + w2*s[tt+2][d] + w3*s[tt+3][d] + bias;
        float ob = w3*s[tt+3][d] + w2*s[tt+4][d] + w1*s[tt+5][d] + w0*s[tt+6][d] + bias;
        size_t m = (size_t)(b*LL + t0 + tt);
        float vf = silu_f(of), vb = silu_f(ob);
        __nv_bfloat16 h, l;
        split_bf16(vf, h, l); g_xsh[0][m*DI + d] = h; g_xsl[0][m*DI + d] = l;
        split_bf16(vb, h, l); g_xsh[1][m*DI + d] = h; g_xsl[1][m*DI + d] = l;
    }
}

// ---------------- chunked selective scan (dt_proj fused, f32x2-packed state) ----
// P3=false: pass1 -> h_end / P_end.
// P3=true : pass3 -> fused gate: writes t_r = silu(z)*(y_r + u_r*D) as bf16 hi/lo
//           into g_Gh/g_Gl[m*KO + r*DI + d]. No y roundtrip, no combine kernel.
// grid(DI/128, NC, 2*BB), block 128, both directions concurrent.
#define SROW 48   // smem row stride in floats (44 padded to 48)

template<bool P3>
__global__ void __launch_bounds__(128)
scan_kernel(const float* __restrict__ A_log,
            const float* __restrict__ dtw,
            const float* __restrict__ dtbv,
            const float* __restrict__ Dv)
{
    __shared__ __align__(16) float sdbl[2][SW][SROW];

    int d  = blockIdx.x * 128 + threadIdx.x;
    int c  = blockIdx.y;
    int rb = blockIdx.z;
    int r  = rb >> 2, b = rb & 3;
    int tid = threadIdx.x;

    const int NSEG = P3 ? 11 : 7;          // 16B chunks per row staged
    const float* dblp = g_dbl[r];
    u32 sb = (u32)__cvta_generic_to_shared(&sdbl[0][0][0]);

    auto issue_win = [&](int w) {
        int nch = SW * NSEG;
        u32 dst0 = sb + (u32)(w & 1) * (SW*SROW*4);
        for (int q = tid; q < nch; q += 128) {
            int j = q / NSEG, seg = q % NSEG;
            int tau = c*LC + w*SW + j;
            int pos = r ? (LL - 1 - tau) : tau;
            size_t m = (size_t)b*LL + pos;
            cpa16(dst0 + (u32)(j*SROW + seg*4)*4, dblp + m*NDBL + seg*4);
        }
        cp_commit();
    };

    float A2[DS], wdt[DTR];
    bool structured = true;
    #pragma unroll
    for (int sIdx = 0; sIdx < DS; sIdx++)
        A2[sIdx] = -__expf(A_log[d*DS + sIdx]) * LOG2E;
    #pragma unroll
    for (int sIdx = 1; sIdx < DS; sIdx++)
        structured &= fabsf(A2[sIdx] - (sIdx+1)*A2[0]) <= 1e-4f*fabsf(A2[sIdx]);
    #pragma unroll
    for (int j = 0; j < DTR; j++) wdt[j] = dtw[d*DTR + j];
    float dtb = dtbv[d];
    float Dval = P3 ? Dv[d] : 0.f;

    // packed dt weights
    u64 wdt2[6];
    #pragma unroll
    for (int k = 0; k < 6; k++) wdt2[k] = pk2(wdt[2*k], wdt[2*k+1]);

    size_t base = (((size_t)rb*NC + c)*DI + d)*DS;
    u64 hp[DS/2];
    #pragma unroll
    for (int k = 0; k < DS/2; k++) {
        if (P3) {
            float2 hv = *(const float2*)&g_hstart[base + 2*k];
            hp[k] = pk2(hv.x, hv.y);
        } else {
            hp[k] = 0ull;
        }
    }

    const __nv_bfloat16* xshp = g_xsh[r];
    const __nv_bfloat16* xslp = g_xsl[r];
    float S = 0.f;

    issue_win(0);
    if (NW > 1) issue_win(1);

    for (int w = 0; w < NW; w++) {
        if (w + 1 < NW) cp_wait1(); else cp_wait0();
        __syncthreads();
        const float (*row)[SROW] = sdbl[w & 1];

        #pragma unroll 4
        for (int j = 0; j < SW; j++) {
            int tau = c*LC + w*SW + j;
            int pos = r ? (LL - 1 - tau) : tau;
            size_t m = (size_t)b*LL + pos;

            // dt dot (packed: 6 fma2 + horizontal add)
            u64 acc2 = 0ull;
            #pragma unroll
            for (int k = 0; k < 6; k++) {
                u64 iv = *(const u64*)&row[j][2*k];
                acc2 = fma2_(iv, wdt2[k], acc2);
            }
            float alo, ahi; upk2(alo, ahi, acc2);
            float dt = sp_f(dtb + alo + ahi);

            float u  = b2f(xshp[m*DI + d]) + b2f(xslp[m*DI + d]);
            float dtx = dt * u;
            u64 dtx2 = pk2(dtx, dtx);

            float y = 0.f;
            if (structured) {
                float e1 = ex2(dt * A2[0]);
                float ee = e1 * e1;
                u64 eep = pk2(ee, ee);
                u64 ap  = pk2(e1, ee);
                u64 y2  = 0ull;
                #pragma unroll
                for (int k = 0; k < DS/2; k++) {
                    u64 Bp = *(const u64*)&row[j][DTR + 2*k];
                    hp[k] = fma2_(ap, hp[k], mul2_(dtx2, Bp));
                    if (P3) {
                        u64 Cp = *(const u64*)&row[j][DTR + DS + 2*k];
                        y2 = fma2_(hp[k], Cp, y2);
                    }
                    if (k < DS/2 - 1) ap = mul2_(ap, eep);
                }
                if (P3) { float yl, yh; upk2(yl, yh, y2); y = yl + yh; }
            } else {
                #pragma unroll
                for (int k = 0; k < DS/2; k++) {
                    float h0, h1; upk2(h0, h1, hp[k]);
                    float a0 = ex2(dt * A2[2*k]);
                    float a1 = ex2(dt * A2[2*k+1]);
                    float B0 = row[j][DTR + 2*k], B1 = row[j][DTR + 2*k+1];
                    h0 = fmaf(a0, h0, dtx * B0);
                    h1 = fmaf(a1, h1, dtx * B1);
                    if (P3) {
                        y = fmaf(h0, row[j][DTR + DS + 2*k], y);
                        y = fmaf(h1, row[j][DTR + DS + 2*k+1], y);
                    }
                    hp[k] = pk2(h0, h1);
                }
            }
            if (P3) {
                float z  = g_xz[m*768 + DI + d];
                float tv = silu_f(z) * (y + u * Dval);
                __nv_bfloat16 th, tl; split_bf16(tv, th, tl);
                size_t gi = m*KO + (size_t)r*DI + d;
                g_Gh[gi] = th; g_Gl[gi] = tl;
            } else {
                S += dt;
            }
        }
        __syncthreads();
        if (w + 2 < NW) issue_win(w + 2);
    }

    if (!P3) {
        #pragma unroll
        for (int k = 0; k < DS/2; k++) {
            float h0, h1; upk2(h0, h1, hp[k]);
            float2 hv; hv.x = h0; hv.y = h1;
            *(float2*)&g_hend[base + 2*k] = hv;
            float2 pv;
            pv.x = ex2(A2[2*k]   * S);
            pv.y = ex2(A2[2*k+1] * S);
            *(float2*)&g_pend[base + 2*k] = pv;
        }
    }
}

__global__ void scan_combine()
{
    int g = blockIdx.x * 256 + threadIdx.x;
    if (g >= 2*BB*DI*DS) return;
    int sd = g % (DI*DS);
    int rb = g / (DI*DS);
    float carry = 0.f;
    for (int c = 0; c < NC; c++) {
        size_t idx = ((size_t)rb*NC + c)*(DI*DS) + sd;
        g_hstart[idx] = carry;
        carry = g_pend[idx]*carry + g_hend[idx];
    }
}

// ---------------- launch ----------------
static void* sym_addr(const void* sym) {
    void* p = nullptr;
    cudaGetSymbolAddress(&p, sym);
    return p;
}

extern "C" void kernel_launch(void* const* d_in, const int* in_sizes, int n_in,
                              void* d_out, int out_size)
{
    const float* x          = (const float*)d_in[0];
    const float* ln_w       = (const float*)d_in[1];
    const float* ln_b       = (const float*)d_in[2];
    const float* in_proj_w  = (const float*)d_in[3];
    const float* conv_w     = (const float*)d_in[4];
    const float* conv_b     = (const float*)d_in[5];
    const float* x_proj_w   = (const float*)d_in[6];
    const float* dt_proj_w  = (const float*)d_in[7];
    const float* dt_proj_b  = (const float*)d_in[8];
    const float* A_log      = (const float*)d_in[9];
    const float* D_vec      = (const float*)d_in[10];
    const float* out_proj_w = (const float*)d_in[11];
    float* out = (float*)d_out;

    float* p_xz  = (float*)sym_addr(g_xz);
    float* p_dbl = (float*)sym_addr(g_dbl);
    __nv_bfloat16* p_xnh = (__nv_bfloat16*)sym_addr(g_xnh);
    __nv_bfloat16* p_xnl = (__nv_bfloat16*)sym_addr(g_xnl);
    __nv_bfloat16* p_xsh = (__nv_bfloat16*)sym_addr(g_xsh);
    __nv_bfloat16* p_xsl = (__nv_bfloat16*)sym_addr(g_xsl);
    __nv_bfloat16* p_Gh  = (__nv_bfloat16*)sym_addr(g_Gh);
    __nv_bfloat16* p_Gl  = (__nv_bfloat16*)sym_addr(g_Gl);
    __nv_bfloat16* p_wih = (__nv_bfloat16*)sym_addr(g_wih);
    __nv_bfloat16* p_wil = (__nv_bfloat16*)sym_addr(g_wil);
    __nv_bfloat16* p_wxh = (__nv_bfloat16*)sym_addr(g_wxh);
    __nv_bfloat16* p_wxl = (__nv_bfloat16*)sym_addr(g_wxl);
    __nv_bfloat16* p_woh = (__nv_bfloat16*)sym_addr(g_woh);
    __nv_bfloat16* p_wol = (__nv_bfloat16*)sym_addr(g_wol);

    cudaFuncSetAttribute((const void*)gemm_tc_store,
                         cudaFuncAttributeMaxDynamicSharedMemorySize, SMEM_TC);
    cudaFuncSetAttribute((const void*)gemm_tc_out,
                         cudaFuncAttributeMaxDynamicSharedMemorySize, SMEM_TC);

    // 1) LayerNorm -> bf16 hi/lo
    ln_kernel<<<dim3(LL/32, BB), dim3(32, 8)>>>(x, ln_w, ln_b);

    // 1b) weight conversion (out_proj weight duplicated across both K-halves)
    cvt_weights<<<256, 256>>>(in_proj_w, x_proj_w, out_proj_w);

    // 2) in_proj: xz[M,768] = xn @ Wi^T  (tensor cores)
    gemm_tc_store<<<dim3(768/128, MM/128, 1), 256, SMEM_TC>>>(
        p_xnh, p_xnl, p_wih, p_wil, p_xz, CC, 768, 768, 0, 0);

    // 3) conv + silu (both directions) -> bf16 hi/lo
    conv_silu_kernel<<<dim3(LL/16, BB), DI>>>(conv_w, conv_b);

    // 4) x_proj both dirs: dbl[M,44] = xs @ Wx^T  (tensor cores)
    gemm_tc_store<<<dim3(1, MM/128, 2), 256, SMEM_TC>>>(
        p_xsh, p_xsl, p_wxh, p_wxl, p_dbl, DI, NDBL, NDBL,
        (size_t)MM*DI, (size_t)MM*NDBL);

    // 5-8) chunked selective scan; pass3 emits per-direction gate halves
    scan_kernel<false><<<dim3(DI/128, NC, 2*BB), 128>>>(A_log, dt_proj_w, dt_proj_b, D_vec);
    scan_combine<<<dim3((2*BB*DI*DS + 255)/256), 256>>>();
    scan_kernel<true><<<dim3(DI/128, NC, 2*BB), 128>>>(A_log, dt_proj_w, dt_proj_b, D_vec);

    // 9) out_proj over extended K=768 ([t0, t1] @ [Wo; Wo]^T), transposed store
    gemm_tc_out<<<dim3(2, MM/128, 1), 256, SMEM_TC>>>(
        p_Gh, p_Gl, p_woh, p_wol, KO, CC, out);
}

// round 11
// speedup vs baseline: 1.0955x; 1.0955x over previous
#include <cuda_runtime.h>
#include <cuda_bf16.h>
#include <cstdint>
#include <math.h>

typedef unsigned int u32;
typedef unsigned long long u64;
struct __align__(16) u64x2 { u64 a, b; };

// ---------------- problem constants ----------------
#define BB   4
#define CC   192
#define HH   64
#define WW   64
#define LL   (HH*WW)          // 4096
#define MM   (BB*LL)          // 16384
#define DI   384
#define DS   16
#define DTR  12
#define NDBL 44               // DTR + 2*DS
#define NC   32               // scan chunks
#define LC   (LL/NC)          // 128
#define SW   16               // scan smem window (timesteps)
#define NW   (LC/SW)          // 8 windows
#define LOG2E 1.4426950408889634f
#define LN2   0.6931471805599453f

// ---------------- scratch (device globals: allocation-free) ----------------
__device__ __align__(128) float g_xz [(size_t)MM*768];
__device__ __align__(128) float g_dbl[2][(size_t)MM*NDBL];
__device__ __align__(128) float g_y  [2][(size_t)MM*DI];
__device__ float g_hend  [2*BB*NC*DI*DS];
__device__ float g_pend  [2*BB*NC*DI*DS];
__device__ float g_hstart[2*BB*NC*DI*DS];

// bf16 hi/lo pairs for tensor-core GEMMs (k-contiguous natural layouts)
__device__ __align__(128) __nv_bfloat16 g_xnh[(size_t)MM*CC];
__device__ __align__(128) __nv_bfloat16 g_xnl[(size_t)MM*CC];
__device__ __align__(128) __nv_bfloat16 g_xsh[2][(size_t)MM*DI];
__device__ __align__(128) __nv_bfloat16 g_xsl[2][(size_t)MM*DI];
__device__ __align__(128) __nv_bfloat16 g_Gh [(size_t)MM*DI];
__device__ __align__(128) __nv_bfloat16 g_Gl [(size_t)MM*DI];
__device__ __align__(128) __nv_bfloat16 g_wih[768*CC];
__device__ __align__(128) __nv_bfloat16 g_wil[768*CC];
__device__ __align__(128) __nv_bfloat16 g_wxh[128*DI];   // x_proj W padded 44->128 rows
__device__ __align__(128) __nv_bfloat16 g_wxl[128*DI];
__device__ __align__(128) __nv_bfloat16 g_woh[256*DI];   // out_proj W padded 192->256 rows
__device__ __align__(128) __nv_bfloat16 g_wol[256*DI];

__device__ __forceinline__ float ex2(float x){
    float r; asm("ex2.approx.ftz.f32 %0, %1;" : "=f"(r) : "f"(x)); return r;
}
__device__ __forceinline__ float silu_f(float x){
    return x / (1.f + __expf(-x));
}
__device__ __forceinline__ float sp_f(float v){   // softplus
    if (v > 15.f) return v;
    float e = ex2(v * LOG2E);
    return __log2f(1.f + e) * LN2;
}
__device__ __forceinline__ void split_bf16(float v, __nv_bfloat16& h, __nv_bfloat16& l){
    h = __float2bfloat16(v);
    l = __float2bfloat16(v - __bfloat162float(h));
}
__device__ __forceinline__ float b2f(__nv_bfloat16 v){ return __bfloat162float(v); }
__device__ __forceinline__ __nv_bfloat162 mk2(__nv_bfloat16 x, __nv_bfloat16 y){
    __nv_bfloat162 t; t.x = x; t.y = y; return t;
}

// ---------------- packed f32x2 helpers (sm_103a FFMA2 via PTX) ----------------
__device__ __forceinline__ u64 pk2(float lo, float hi){
    u64 d; asm("mov.b64 %0, {%1,%2};" : "=l"(d) : "f"(lo), "f"(hi)); return d;
}
__device__ __forceinline__ void upk2(float& lo, float& hi, u64 v){
    asm("mov.b64 {%0,%1}, %2;" : "=f"(lo), "=f"(hi) : "l"(v));
}
__device__ __forceinline__ u64 fma2_(u64 a, u64 b, u64 c){
    u64 d; asm("fma.rn.f32x2 %0, %1, %2, %3;" : "=l"(d) : "l"(a), "l"(b), "l"(c)); return d;
}
__device__ __forceinline__ u64 mul2_(u64 a, u64 b){
    u64 d; asm("mul.rn.f32x2 %0, %1, %2;" : "=l"(d) : "l"(a), "l"(b)); return d;
}

// ---------------- PTX helpers ----------------
__device__ __forceinline__ void cpa16(u32 dst, const void* src){
    asm volatile("cp.async.ca.shared.global [%0], [%1], 16;" :: "r"(dst), "l"(src));
}
__device__ __forceinline__ void cp_commit(){
    asm volatile("cp.async.commit_group;");
}
__device__ __forceinline__ void cp_wait1(){
    asm volatile("cp.async.wait_group 1;");
}
__device__ __forceinline__ void cp_wait0(){
    asm volatile("cp.async.wait_group 0;");
}
__device__ __forceinline__ void ldsm4(u32& x0, u32& x1, u32& x2, u32& x3, u32 addr){
    asm volatile("ldmatrix.sync.aligned.m8n8.x4.shared.b16 {%0,%1,%2,%3}, [%4];"
                 : "=r"(x0), "=r"(x1), "=r"(x2), "=r"(x3) : "r"(addr));
}
__device__ __forceinline__ void mma16816(float& d0, float& d1, float& d2, float& d3,
                                         u32 a0, u32 a1, u32 a2, u32 a3,
                                         u32 v0, u32 v1){
    asm volatile("mma.sync.aligned.m16n8k16.row.col.f32.bf16.bf16.f32 "
                 "{%0,%1,%2,%3},{%4,%5,%6,%7},{%8,%9},{%0,%1,%2,%3};"
                 : "+f"(d0), "+f"(d1), "+f"(d2), "+f"(d3)
                 : "r"(a0), "r"(a1), "r"(a2), "r"(a3), "r"(v0), "r"(v1));
}

// ---------------- 1) LayerNorm over channels -> bf16 hi/lo (paired stores) ------
__global__ void ln_kernel(const float* __restrict__ x,
                          const float* __restrict__ w,
                          const float* __restrict__ bsh)
{
    int b = blockIdx.y, p0 = blockIdx.x * 32;
    int tx = threadIdx.x, ty = threadIdx.y;
    __shared__ float sx[CC][33];
    __shared__ float red[2][8][32];
    __shared__ float smu[32], srs[32];

    float s1 = 0.f, s2 = 0.f;
    for (int c = ty; c < CC; c += 8) {
        float v = x[((size_t)(b*CC + c))*LL + p0 + tx];
        sx[c][tx] = v; s1 += v; s2 += v*v;
    }
    red[0][ty][tx] = s1; red[1][ty][tx] = s2;
    __syncthreads();
    if (ty == 0) {
        float a = 0.f, q = 0.f;
        #pragma unroll
        for (int j = 0; j < 8; j++){ a += red[0][j][tx]; q += red[1][j][tx]; }
        float mu = a / CC;
        float var = q / CC - mu*mu;
        smu[tx] = mu; srs[tx] = rsqrtf(var + 1e-5f);
    }
    __syncthreads();
    int tid = ty*32 + tx;
    for (int e = tid; e < 32*(CC/2); e += 256) {
        int pp = e / (CC/2), cc2 = e % (CC/2);
        int cc = 2*cc2;
        float mu = smu[pp], rs = srs[pp];
        float v0 = (sx[cc][pp]   - mu) * rs * w[cc]   + bsh[cc];
        float v1 = (sx[cc+1][pp] - mu) * rs * w[cc+1] + bsh[cc+1];
        size_t idx = ((size_t)(b*LL + p0 + pp))*CC + cc;
        __nv_bfloat16 h0, l0, h1, l1;
        split_bf16(v0, h0, l0); split_bf16(v1, h1, l1);
        *(__nv_bfloat162*)&g_xnh[idx] = mk2(h0, h1);
        *(__nv_bfloat162*)&g_xnl[idx] = mk2(l0, l1);
    }
}

// ---------------- weight conversion (hi/lo split + zero padding) ----------------
__global__ void cvt_weights(const float* __restrict__ wi,
                            const float* __restrict__ wx,
                            const float* __restrict__ wo)
{
    int stride = gridDim.x * blockDim.x;
    int t = blockIdx.x * blockDim.x + threadIdx.x;
    for (int e = t; e < 768*CC; e += stride) {
        __nv_bfloat16 h, l; split_bf16(wi[e], h, l);
        g_wih[e] = h; g_wil[e] = l;
    }
    for (int e = t; e < 128*DI; e += stride) {
        int n = e / DI, k = e % DI;
        float v = (n < NDBL) ? wx[n*DI + k] : 0.f;
        __nv_bfloat16 h, l; split_bf16(v, h, l);
        g_wxh[e] = h; g_wxl[e] = l;
    }
    for (int e = t; e < 256*DI; e += stride) {
        int n = e / DI, k = e % DI;
        float v = (n < CC) ? wo[n*DI + k] : 0.f;
        __nv_bfloat16 h, l; split_bf16(v, h, l);
        g_woh[e] = h; g_wol[e] = l;
    }
}

// ---------------- tensor-core GEMM mainloop (shared by both kernels) ----------
#define ROWB   80
#define OFF_AH 0
#define OFF_AL (128*ROWB)
#define OFF_BH (2*128*ROWB)
#define OFF_BL (3*128*ROWB)
#define STAGEB (4*128*ROWB)
#define SMEM_TC (2*STAGEB)

__device__ __forceinline__ void tc_mainloop(
    const __nv_bfloat16* Ahp, const __nv_bfloat16* Alp,
    const __nv_bfloat16* Bhp, const __nv_bfloat16* Blp,
    int K, int m0, int n0, char* smem, float acc[2][8][4])
{
    u32 sbase = (u32)__cvta_generic_to_shared(smem);
    int tid = threadIdx.x;
    int lane = tid & 31, wid = tid >> 5;
    int wm = wid & 3, wn = wid >> 2;

    int r0c = tid >> 2, c0c = tid & 3;
    int r1c = (tid + 256) >> 2, c1c = (tid + 256) & 3;
    int NIT = K / 32;

    for (int pre = 0; pre < 2 && pre < NIT; pre++) {
        int k0 = pre * 32;
        u32 st = sbase + (u32)(pre & 1) * STAGEB;
        cpa16(st + OFF_AH + r0c*ROWB + c0c*16, Ahp + (size_t)(m0 + r0c)*K + k0 + c0c*8);
        cpa16(st + OFF_AH + r1c*ROWB + c1c*16, Ahp + (size_t)(m0 + r1c)*K + k0 + c1c*8);
        cpa16(st + OFF_AL + r0c*ROWB + c0c*16, Alp + (size_t)(m0 + r0c)*K + k0 + c0c*8);
        cpa16(st + OFF_AL + r1c*ROWB + c1c*16, Alp + (size_t)(m0 + r1c)*K + k0 + c1c*8);
        cpa16(st + OFF_BH + r0c*ROWB + c0c*16, Bhp + (size_t)(n0 + r0c)*K + k0 + c0c*8);
        cpa16(st + OFF_BH + r1c*ROWB + c1c*16, Bhp + (size_t)(n0 + r1c)*K + k0 + c1c*8);
        cpa16(st + OFF_BL + r0c*ROWB + c0c*16, Blp + (size_t)(n0 + r0c)*K + k0 + c0c*8);
        cpa16(st + OFF_BL + r1c*ROWB + c1c*16, Blp + (size_t)(n0 + r1c)*K + k0 + c1c*8);
        cp_commit();
    }

    for (int it = 0; it < NIT; it++) {
        cp_wait1();
        __syncthreads();

        u32 st = sbase + (u32)(it & 1) * STAGEB;
        #pragma unroll
        for (int ks = 0; ks < 2; ks++) {
            u32 fah0[4], fah1[4], fal0[4], fal1[4];
            {
                u32 adr0 = st + OFF_AH + (u32)((wm*32 + (lane & 15))*ROWB
                         + ks*32 + (lane >> 4)*16);
                u32 adr1 = adr0 + 16*ROWB;
                ldsm4(fah0[0], fah0[1], fah0[2], fah0[3], adr0);
                ldsm4(fal0[0], fal0[1], fal0[2], fal0[3], adr0 + (OFF_AL - OFF_AH));
                ldsm4(fah1[0], fah1[1], fah1[2], fah1[3], adr1);
                ldsm4(fal1[0], fal1[1], fal1[2], fal1[3], adr1 + (OFF_AL - OFF_AH));
            }
            #pragma unroll
            for (int j = 0; j < 4; j++) {
                u32 fbh[4], fbl[4];
                u32 bdr = st + OFF_BH + (u32)((wn*64 + j*16 + (lane & 15))*ROWB
                        + ks*32 + (lane >> 4)*16);
                ldsm4(fbh[0], fbh[1], fbh[2], fbh[3], bdr);
                ldsm4(fbl[0], fbl[1], fbl[2], fbl[3], bdr + (OFF_BL - OFF_BH));

                mma16816(acc[0][2*j][0], acc[0][2*j][1], acc[0][2*j][2], acc[0][2*j][3],
                         fah0[0], fah0[1], fah0[2], fah0[3], fbh[0], fbh[2]);
                mma16816(acc[0][2*j][0], acc[0][2*j][1], acc[0][2*j][2], acc[0][2*j][3],
                         fah0[0], fah0[1], fah0[2], fah0[3], fbl[0], fbl[2]);
                mma16816(acc[0][2*j][0], acc[0][2*j][1], acc[0][2*j][2], acc[0][2*j][3],
                         fal0[0], fal0[1], fal0[2], fal0[3], fbh[0], fbh[2]);
                mma16816(acc[0][2*j+1][0], acc[0][2*j+1][1], acc[0][2*j+1][2], acc[0][2*j+1][3],
                         fah0[0], fah0[1], fah0[2], fah0[3], fbh[1], fbh[3]);
                mma16816(acc[0][2*j+1][0], acc[0][2*j+1][1], acc[0][2*j+1][2], acc[0][2*j+1][3],
                         fah0[0], fah0[1], fah0[2], fah0[3], fbl[1], fbl[3]);
                mma16816(acc[0][2*j+1][0], acc[0][2*j+1][1], acc[0][2*j+1][2], acc[0][2*j+1][3],
                         fal0[0], fal0[1], fal0[2], fal0[3], fbh[1], fbh[3]);

                mma16816(acc[1][2*j][0], acc[1][2*j][1], acc[1][2*j][2], acc[1][2*j][3],
                         fah1[0], fah1[1], fah1[2], fah1[3], fbh[0], fbh[2]);
                mma16816(acc[1][2*j][0], acc[1][2*j][1], acc[1][2*j][2], acc[1][2*j][3],
                         fah1[0], fah1[1], fah1[2], fah1[3], fbl[0], fbl[2]);
                mma16816(acc[1][2*j][0], acc[1][2*j][1], acc[1][2*j][2], acc[1][2*j][3],
                         fal1[0], fal1[1], fal1[2], fal1[3], fbh[0], fbh[2]);
                mma16816(acc[1][2*j+1][0], acc[1][2*j+1][1], acc[1][2*j+1][2], acc[1][2*j+1][3],
                         fah1[0], fah1[1], fah1[2], fah1[3], fbh[1], fbh[3]);
                mma16816(acc[1][2*j+1][0], acc[1][2*j+1][1], acc[1][2*j+1][2], acc[1][2*j+1][3],
                         fah1[0], fah1[1], fah1[2], fah1[3], fbl[1], fbl[3]);
                mma16816(acc[1][2*j+1][0], acc[1][2*j+1][1], acc[1][2*j+1][2], acc[1][2*j+1][3],
                         fal1[0], fal1[1], fal1[2], fal1[3], fbh[1], fbh[3]);
            }
        }
        __syncthreads();
        if (it + 2 < NIT) {
            int k0 = (it + 2) * 32;
            u32 st2 = sbase + (u32)((it + 2) & 1) * STAGEB;
            cpa16(st2 + OFF_AH + r0c*ROWB + c0c*16, Ahp + (size_t)(m0 + r0c)*K + k0 + c0c*8);
            cpa16(st2 + OFF_AH + r1c*ROWB + c1c*16, Ahp + (size_t)(m0 + r1c)*K + k0 + c1c*8);
            cpa16(st2 + OFF_AL + r0c*ROWB + c0c*16, Alp + (size_t)(m0 + r0c)*K + k0 + c0c*8);
            cpa16(st2 + OFF_AL + r1c*ROWB + c1c*16, Alp + (size_t)(m0 + r1c)*K + k0 + c1c*8);
            cpa16(st2 + OFF_BH + r0c*ROWB + c0c*16, Bhp + (size_t)(n0 + r0c)*K + k0 + c0c*8);
            cpa16(st2 + OFF_BH + r1c*ROWB + c1c*16, Bhp + (size_t)(n0 + r1c)*K + k0 + c1c*8);
            cpa16(st2 + OFF_BL + r0c*ROWB + c0c*16, Blp + (size_t)(n0 + r0c)*K + k0 + c0c*8);
            cpa16(st2 + OFF_BL + r1c*ROWB + c1c*16, Blp + (size_t)(n0 + r1c)*K + k0 + c1c*8);
        }
        cp_commit();
    }
}

// plain fp32 store (z-batched)
__global__ void __launch_bounds__(256)
gemm_tc_store(const __nv_bfloat16* __restrict__ Ahp, const __nv_bfloat16* __restrict__ Alp,
              const __nv_bfloat16* __restrict__ Bhp, const __nv_bfloat16* __restrict__ Blp,
              float* __restrict__ C, int K, int N, int ldc, size_t aZ, size_t cZ)
{
    extern __shared__ char smem[];
    float acc[2][8][4];
    #pragma unroll
    for (int i = 0; i < 2; i++)
        #pragma unroll
        for (int j = 0; j < 8; j++)
            #pragma unroll
            for (int q = 0; q < 4; q++) acc[i][j][q] = 0.f;

    int m0 = blockIdx.y*128, n0 = blockIdx.x*128;
    tc_mainloop(Ahp + (size_t)blockIdx.z*aZ, Alp + (size_t)blockIdx.z*aZ,
                Bhp, Blp, K, m0, n0, smem, acc);
    C += (size_t)blockIdx.z * cZ;

    int lane = threadIdx.x & 31, wid = threadIdx.x >> 5;
    int wm = wid & 3, wn = wid >> 2;
    int gp = lane >> 2, tg = lane & 3;
    #pragma unroll
    for (int mi = 0; mi < 2; mi++) {
        int row = m0 + wm*32 + mi*16 + gp;
        #pragma unroll
        for (int ni = 0; ni < 8; ni++) {
            int col = n0 + wn*64 + ni*8 + tg*2;
            if (col < N) {
                float2 v0; v0.x = acc[mi][ni][0]; v0.y = acc[mi][ni][1];
                float2 v1; v1.x = acc[mi][ni][2]; v1.y = acc[mi][ni][3];
                *(float2*)&C[(size_t)row*ldc + col]       = v0;
                *(float2*)&C[(size_t)(row + 8)*ldc + col] = v1;
            }
        }
    }
}

// transposed store to d_out laid out (B, C, L)
__global__ void __launch_bounds__(256)
gemm_tc_out(const __nv_bfloat16* __restrict__ Ahp, const __nv_bfloat16* __restrict__ Alp,
            const __nv_bfloat16* __restrict__ Bhp, const __nv_bfloat16* __restrict__ Blp,
            int K, int N, float* __restrict__ dout)
{
    extern __shared__ char smem[];
    float acc[2][8][4];
    #pragma unroll
    for (int i = 0; i < 2; i++)
        #pragma unroll
        for (int j = 0; j < 8; j++)
            #pragma unroll
            for (int q = 0; q < 4; q++) acc[i][j][q] = 0.f;

    int m0 = blockIdx.y*128, n0 = blockIdx.x*128;
    tc_mainloop(Ahp, Alp, Bhp, Blp, K, m0, n0, smem, acc);

    cp_wait0();
    __syncthreads();
    float* so = (float*)smem;   // [128][132]
    int lane = threadIdx.x & 31, wid = threadIdx.x >> 5;
    int wm = wid & 3, wn = wid >> 2;
    int gp = lane >> 2, tg = lane & 3;
    #pragma unroll
    for (int mi = 0; mi < 2; mi++) {
        int ml = wm*32 + mi*16 + gp;
        #pragma unroll
        for (int ni = 0; ni < 8; ni++) {
            int nl = wn*64 + ni*8 + tg*2;
            so[(size_t)nl*132 + ml]         = acc[mi][ni][0];
            so[(size_t)(nl+1)*132 + ml]     = acc[mi][ni][1];
            so[(size_t)nl*132 + ml + 8]     = acc[mi][ni][2];
            so[(size_t)(nl+1)*132 + ml + 8] = acc[mi][ni][3];
        }
    }
    __syncthreads();
    int b = m0 >> 12, p0 = m0 & (LL - 1);
    for (int e = threadIdx.x; e < 128*128; e += 256) {
        int nl = e >> 7, mlp = e & 127;
        int n = n0 + nl;
        if (n < N)
            dout[((size_t)(b*CC + n))*LL + p0 + mlp] = so[(size_t)nl*132 + mlp];
    }
}

// ---------------- depthwise causal conv + silu (2 channels/thread) -------------
__global__ void conv_silu_kernel(const float* __restrict__ cw, const float* __restrict__ cb)
{
    __shared__ float2 s[16 + 6][DI/2];
    int b = blockIdx.y, t0 = blockIdx.x * 16, d2 = threadIdx.x;   // 192 threads
    int d = 2*d2;

    #pragma unroll
    for (int j = 0; j < 22; j++) {
        int t = t0 - 3 + j;
        float2 v; v.x = 0.f; v.y = 0.f;
        if (t >= 0 && t < LL) v = *(const float2*)&g_xz[((size_t)(b*LL + t))*768 + d];
        s[j][d2] = v;
    }
    __syncthreads();
    float4 wa = *(const float4*)&cw[d*4];
    float4 wb = *(const float4*)&cw[(d+1)*4];
    float2 bias = *(const float2*)&cb[d];

    #pragma unroll
    for (int tt = 0; tt < 16; tt++) {
        float2 a0 = s[tt][d2],   a1 = s[tt+1][d2], a2 = s[tt+2][d2];
        float2 a3 = s[tt+3][d2], a4 = s[tt+4][d2], a5 = s[tt+5][d2], a6 = s[tt+6][d2];
        float of0 = wa.x*a0.x + wa.y*a1.x + wa.z*a2.x + wa.w*a3.x + bias.x;
        float of1 = wb.x*a0.y + wb.y*a1.y + wb.z*a2.y + wb.w*a3.y + bias.y;
        float ob0 = wa.w*a3.x + wa.z*a4.x + wa.y*a5.x + wa.x*a6.x + bias.x;
        float ob1 = wb.w*a3.y + wb.z*a4.y + wb.y*a5.y + wb.x*a6.y + bias.y;
        size_t m = (size_t)(b*LL + t0 + tt);
        float vf0 = silu_f(of0), vf1 = silu_f(of1);
        float vb0 = silu_f(ob0), vb1 = silu_f(ob1);
        __nv_bfloat16 h0, l0, h1, l1;
        split_bf16(vf0, h0, l0); split_bf16(vf1, h1, l1);
        *(__nv_bfloat162*)&g_xsh[0][m*DI + d] = mk2(h0, h1);
        *(__nv_bfloat162*)&g_xsl[0][m*DI + d] = mk2(l0, l1);
        split_bf16(vb0, h0, l0); split_bf16(vb1, h1, l1);
        *(__nv_bfloat162*)&g_xsh[1][m*DI + d] = mk2(h0, h1);
        *(__nv_bfloat162*)&g_xsl[1][m*DI + d] = mk2(l0, l1);
    }
}

// ---------------- chunked selective scan (dt_proj fused, f32x2 + LDS.128) -------
#define SROW 48   // smem row stride in floats (44 padded to 48)

template<bool P3>
__global__ void __launch_bounds__(128)
scan_kernel(const float* __restrict__ A_log,
            const float* __restrict__ dtw,
            const float* __restrict__ dtbv)
{
    __shared__ __align__(16) float sdbl[2][SW][SROW];

    int d  = blockIdx.x * 128 + threadIdx.x;
    int c  = blockIdx.y;
    int rb = blockIdx.z;
    int r  = rb >> 2, b = rb & 3;
    int tid = threadIdx.x;

    const int NSEG = P3 ? 11 : 7;          // 16B chunks per row staged
    const float* dblp = g_dbl[r];
    u32 sb = (u32)__cvta_generic_to_shared(&sdbl[0][0][0]);

    auto issue_win = [&](int w) {
        int nch = SW * NSEG;
        u32 dst0 = sb + (u32)(w & 1) * (SW*SROW*4);
        for (int q = tid; q < nch; q += 128) {
            int j = q / NSEG, seg = q % NSEG;
            int tau = c*LC + w*SW + j;
            int pos = r ? (LL - 1 - tau) : tau;
            size_t m = (size_t)b*LL + pos;
            cpa16(dst0 + (u32)(j*SROW + seg*4)*4, dblp + m*NDBL + seg*4);
        }
        cp_commit();
    };

    float A2[DS], wdt[DTR];
    bool structured = true;
    #pragma unroll
    for (int sIdx = 0; sIdx < DS; sIdx++)
        A2[sIdx] = -__expf(A_log[d*DS + sIdx]) * LOG2E;
    #pragma unroll
    for (int sIdx = 1; sIdx < DS; sIdx++)
        structured &= fabsf(A2[sIdx] - (sIdx+1)*A2[0]) <= 1e-4f*fabsf(A2[sIdx]);
    #pragma unroll
    for (int j = 0; j < DTR; j++) wdt[j] = dtw[d*DTR + j];
    float dtb = dtbv[d];

    u64 wdt2[6];
    #pragma unroll
    for (int k = 0; k < 6; k++) wdt2[k] = pk2(wdt[2*k], wdt[2*k+1]);

    size_t base = (((size_t)rb*NC + c)*DI + d)*DS;
    u64 hp[DS/2];
    #pragma unroll
    for (int k = 0; k < DS/2; k++) {
        if (P3) {
            float2 hv = *(const float2*)&g_hstart[base + 2*k];
            hp[k] = pk2(hv.x, hv.y);
        } else {
            hp[k] = 0ull;
        }
    }

    const __nv_bfloat16* xshp = g_xsh[r];
    const __nv_bfloat16* xslp = g_xsl[r];
    float* yp = g_y[r];
    float S = 0.f;

    issue_win(0);
    if (NW > 1) issue_win(1);

    for (int w = 0; w < NW; w++) {
        if (w + 1 < NW) cp_wait1(); else cp_wait0();
        __syncthreads();
        const float (*row)[SROW] = sdbl[w & 1];

        #pragma unroll 4
        for (int j = 0; j < SW; j++) {
            int tau = c*LC + w*SW + j;
            int pos = r ? (LL - 1 - tau) : tau;
            size_t m = (size_t)b*LL + pos;

            // 128-bit smem reads: dt inputs (3), B (4), C (4)
            u64x2 I0 = *(const u64x2*)&row[j][0];
            u64x2 I1 = *(const u64x2*)&row[j][4];
            u64x2 I2 = *(const u64x2*)&row[j][8];
            u64x2 Bq0 = *(const u64x2*)&row[j][DTR];
            u64x2 Bq1 = *(const u64x2*)&row[j][DTR+4];
            u64x2 Bq2 = *(const u64x2*)&row[j][DTR+8];
            u64x2 Bq3 = *(const u64x2*)&row[j][DTR+12];
            u64 Bp[8] = {Bq0.a,Bq0.b, Bq1.a,Bq1.b, Bq2.a,Bq2.b, Bq3.a,Bq3.b};
            u64 Cp[8];
            if (P3) {
                u64x2 Cq0 = *(const u64x2*)&row[j][DTR+DS];
                u64x2 Cq1 = *(const u64x2*)&row[j][DTR+DS+4];
                u64x2 Cq2 = *(const u64x2*)&row[j][DTR+DS+8];
                u64x2 Cq3 = *(const u64x2*)&row[j][DTR+DS+12];
                Cp[0]=Cq0.a; Cp[1]=Cq0.b; Cp[2]=Cq1.a; Cp[3]=Cq1.b;
                Cp[4]=Cq2.a; Cp[5]=Cq2.b; Cp[6]=Cq3.a; Cp[7]=Cq3.b;
            }

            u64 acc2 = fma2_(I0.a, wdt2[0], 0ull);
            acc2 = fma2_(I0.b, wdt2[1], acc2);
            acc2 = fma2_(I1.a, wdt2[2], acc2);
            acc2 = fma2_(I1.b, wdt2[3], acc2);
            acc2 = fma2_(I2.a, wdt2[4], acc2);
            acc2 = fma2_(I2.b, wdt2[5], acc2);
            float alo, ahi; upk2(alo, ahi, acc2);
            float dt = sp_f(dtb + alo + ahi);

            float u  = b2f(xshp[m*DI + d]) + b2f(xslp[m*DI + d]);
            float dtx = dt * u;
            u64 dtx2 = pk2(dtx, dtx);

            float y = 0.f;
            if (structured) {
                float e1 = ex2(dt * A2[0]);
                float ee = e1 * e1;
                u64 eep = pk2(ee, ee);
                u64 ap  = pk2(e1, ee);
                u64 y2  = 0ull;
                #pragma unroll
                for (int k = 0; k < DS/2; k++) {
                    hp[k] = fma2_(ap, hp[k], mul2_(dtx2, Bp[k]));
                    if (P3) y2 = fma2_(hp[k], Cp[k], y2);
                    if (k < DS/2 - 1) ap = mul2_(ap, eep);
                }
                if (P3) { float yl, yh; upk2(yl, yh, y2); y = yl + yh; }
            } else {
                #pragma unroll
                for (int k = 0; k < DS/2; k++) {
                    float h0, h1; upk2(h0, h1, hp[k]);
                    float B0, B1; upk2(B0, B1, Bp[k]);
                    float a0 = ex2(dt * A2[2*k]);
                    float a1 = ex2(dt * A2[2*k+1]);
                    h0 = fmaf(a0, h0, dtx * B0);
                    h1 = fmaf(a1, h1, dtx * B1);
                    if (P3) {
                        float C0, C1; upk2(C0, C1, Cp[k]);
                        y = fmaf(h0, C0, y);
                        y = fmaf(h1, C1, y);
                    }
                    hp[k] = pk2(h0, h1);
                }
            }
            if (P3) yp[m*DI + d] = y;
            else    S += dt;
        }
        __syncthreads();
        if (w + 2 < NW) issue_win(w + 2);
    }

    if (!P3) {
        #pragma unroll
        for (int k = 0; k < DS/2; k++) {
            float h0, h1; upk2(h0, h1, hp[k]);
            float2 hv; hv.x = h0; hv.y = h1;
            *(float2*)&g_hend[base + 2*k] = hv;
            float2 pv;
            pv.x = ex2(A2[2*k]   * S);
            pv.y = ex2(A2[2*k+1] * S);
            *(float2*)&g_pend[base + 2*k] = pv;
        }
    }
}

__global__ void scan_combine()
{
    int g = blockIdx.x * 256 + threadIdx.x;
    if (g >= 2*BB*DI*DS) return;
    int sd = g % (DI*DS);
    int rb = g / (DI*DS);
    float carry = 0.f;
    for (int c = 0; c < NC; c++) {
        size_t idx = ((size_t)rb*NC + c)*(DI*DS) + sd;
        g_hstart[idx] = carry;
        carry = g_pend[idx]*carry + g_hend[idx];
    }
}

// ---------------- fused gate -> bf16 hi/lo (2 elements/thread) ----------------
__global__ void combine_G(const float* __restrict__ Dv)
{
    size_t g2 = (size_t)blockIdx.x * 256 + threadIdx.x;
    if (g2 >= (size_t)MM*DI/2) return;
    int d2 = (int)(g2 % (DI/2));
    size_t m = g2 / (DI/2);
    int d = 2*d2;
    size_t gi = m*DI + d;

    float2 z  = *(const float2*)&g_xz[m*768 + DI + d];
    __nv_bfloat162 x0h = *(const __nv_bfloat162*)&g_xsh[0][gi];
    __nv_bfloat162 x0l = *(const __nv_bfloat162*)&g_xsl[0][gi];
    __nv_bfloat162 x1h = *(const __nv_bfloat162*)&g_xsh[1][gi];
    __nv_bfloat162 x1l = *(const __nv_bfloat162*)&g_xsl[1][gi];
    float2 y0 = *(const float2*)&g_y[0][gi];
    float2 y1 = *(const float2*)&g_y[1][gi];
    float2 Dq = *(const float2*)&Dv[d];

    float xs0 = b2f(x0h.x) + b2f(x0l.x) + b2f(x1h.x) + b2f(x1l.x);
    float xs1 = b2f(x0h.y) + b2f(x0l.y) + b2f(x1h.y) + b2f(x1l.y);
    float v0 = silu_f(z.x) * (y0.x + y1.x + xs0 * Dq.x);
    float v1 = silu_f(z.y) * (y0.y + y1.y + xs1 * Dq.y);
    __nv_bfloat16 h0, l0, h1, l1;
    split_bf16(v0, h0, l0); split_bf16(v1, h1, l1);
    *(__nv_bfloat162*)&g_Gh[gi] = mk2(h0, h1);
    *(__nv_bfloat162*)&g_Gl[gi] = mk2(l0, l1);
}

// ---------------- launch ----------------
static void* sym_addr(const void* sym) {
    void* p = nullptr;
    cudaGetSymbolAddress(&p, sym);
    return p;
}

extern "C" void kernel_launch(void* const* d_in, const int* in_sizes, int n_in,
                              void* d_out, int out_size)
{
    const float* x          = (const float*)d_in[0];
    const float* ln_w       = (const float*)d_in[1];
    const float* ln_b       = (const float*)d_in[2];
    const float* in_proj_w  = (const float*)d_in[3];
    const float* conv_w     = (const float*)d_in[4];
    const float* conv_b     = (const float*)d_in[5];
    const float* x_proj_w   = (const float*)d_in[6];
    const float* dt_proj_w  = (const float*)d_in[7];
    const float* dt_proj_b  = (const float*)d_in[8];
    const float* A_log      = (const float*)d_in[9];
    const float* D_vec      = (const float*)d_in[10];
    const float* out_proj_w = (const float*)d_in[11];
    float* out = (float*)d_out;

    float* p_xz  = (float*)sym_addr(g_xz);
    float* p_dbl = (float*)sym_addr(g_dbl);
    __nv_bfloat16* p_xnh = (__nv_bfloat16*)sym_addr(g_xnh);
    __nv_bfloat16* p_xnl = (__nv_bfloat16*)sym_addr(g_xnl);
    __nv_bfloat16* p_xsh = (__nv_bfloat16*)sym_addr(g_xsh);
    __nv_bfloat16* p_xsl = (__nv_bfloat16*)sym_addr(g_xsl);
    __nv_bfloat16* p_Gh  = (__nv_bfloat16*)sym_addr(g_Gh);
    __nv_bfloat16* p_Gl  = (__nv_bfloat16*)sym_addr(g_Gl);
    __nv_bfloat16* p_wih = (__nv_bfloat16*)sym_addr(g_wih);
    __nv_bfloat16* p_wil = (__nv_bfloat16*)sym_addr(g_wil);
    __nv_bfloat16* p_wxh = (__nv_bfloat16*)sym_addr(g_wxh);
    __nv_bfloat16* p_wxl = (__nv_bfloat16*)sym_addr(g_wxl);
    __nv_bfloat16* p_woh = (__nv_bfloat16*)sym_addr(g_woh);
    __nv_bfloat16* p_wol = (__nv_bfloat16*)sym_addr(g_wol);

    cudaFuncSetAttribute((const void*)gemm_tc_store,
                         cudaFuncAttributeMaxDynamicSharedMemorySize, SMEM_TC);
    cudaFuncSetAttribute((const void*)gemm_tc_out,
                         cudaFuncAttributeMaxDynamicSharedMemorySize, SMEM_TC);

    // 1) LayerNorm -> bf16 hi/lo
    ln_kernel<<<dim3(LL/32, BB), dim3(32, 8)>>>(x, ln_w, ln_b);

    // 1b) weight conversion
    cvt_weights<<<256, 256>>>(in_proj_w, x_proj_w, out_proj_w);

    // 2) in_proj: xz[M,768] = xn @ Wi^T  (tensor cores)
    gemm_tc_store<<<dim3(768/128, MM/128, 1), 256, SMEM_TC>>>(
        p_xnh, p_xnl, p_wih, p_wil, p_xz, CC, 768, 768, 0, 0);

    // 3) conv + silu (both directions) -> bf16 hi/lo
    conv_silu_kernel<<<dim3(LL/16, BB), DI/2>>>(conv_w, conv_b);

    // 4) x_proj both dirs: dbl[M,44] = xs @ Wx^T  (tensor cores)
    gemm_tc_store<<<dim3(1, MM/128, 2), 256, SMEM_TC>>>(
        p_xsh, p_xsl, p_wxh, p_wxl, p_dbl, DI, NDBL, NDBL,
        (size_t)MM*DI, (size_t)MM*NDBL);

    // 5-8) chunked selective scan: fused dt_proj, f32x2-packed, LDS.128 reads
    scan_kernel<false><<<dim3(DI/128, NC, 2*BB), 128>>>(A_log, dt_proj_w, dt_proj_b);
    scan_combine<<<dim3((2*BB*DI*DS + 255)/256), 256>>>();
    scan_kernel<true><<<dim3(DI/128, NC, 2*BB), 128>>>(A_log, dt_proj_w, dt_proj_b);

    // 9) fused gate -> bf16 hi/lo (vectorized)
    combine_G<<<dim3((MM*DI/2 + 255)/256), 256>>>(D_vec);

    // 10) out_proj (tensor cores) with transposed store to (B,C,H,W)
    gemm_tc_out<<<dim3(2, MM/128, 1), 256, SMEM_TC>>>(
        p_Gh, p_Gl, p_woh, p_wol, DI, CC, out);
}

// round 12
// speedup vs baseline: 1.0984x; 1.0027x over previous
#include <cuda_runtime.h>
#include <cuda_bf16.h>
#include <cstdint>
#include <math.h>

typedef unsigned int u32;
typedef unsigned long long u64;

// ---------------- problem constants ----------------
#define BB   4
#define CC   192
#define HH   64
#define WW   64
#define LL   (HH*WW)          // 4096
#define MM   (BB*LL)          // 16384
#define DI   384
#define DS   16
#define DTR  12
#define NDBL 44               // DTR + 2*DS
#define NC   64               // scan chunks (2x TLP for latency hiding)
#define LC   (LL/NC)          // 64
#define SW   16               // scan smem window (timesteps)
#define NW   (LC/SW)          // 4 windows
#define LOG2E 1.4426950408889634f
#define LN2   0.6931471805599453f

// ---------------- scratch (device globals: allocation-free) ----------------
__device__ __align__(128) float g_xz [(size_t)MM*768];
__device__ __align__(128) float g_dbl[2][(size_t)MM*NDBL];
__device__ __align__(128) float g_y  [2][(size_t)MM*DI];
__device__ float g_hend  [2*BB*NC*DI*DS];
__device__ float g_pend  [2*BB*NC*DI*DS];
__device__ float g_hstart[2*BB*NC*DI*DS];

// bf16 hi/lo pairs for tensor-core GEMMs (k-contiguous natural layouts)
__device__ __align__(128) __nv_bfloat16 g_xnh[(size_t)MM*CC];
__device__ __align__(128) __nv_bfloat16 g_xnl[(size_t)MM*CC];
__device__ __align__(128) __nv_bfloat16 g_xsh[2][(size_t)MM*DI];
__device__ __align__(128) __nv_bfloat16 g_xsl[2][(size_t)MM*DI];
__device__ __align__(128) __nv_bfloat16 g_Gh [(size_t)MM*DI];
__device__ __align__(128) __nv_bfloat16 g_Gl [(size_t)MM*DI];
__device__ __align__(128) __nv_bfloat16 g_wih[768*CC];
__device__ __align__(128) __nv_bfloat16 g_wil[768*CC];
__device__ __align__(128) __nv_bfloat16 g_wxh[128*DI];   // x_proj W padded 44->128 rows
__device__ __align__(128) __nv_bfloat16 g_wxl[128*DI];
__device__ __align__(128) __nv_bfloat16 g_woh[256*DI];   // out_proj W padded 192->256 rows
__device__ __align__(128) __nv_bfloat16 g_wol[256*DI];

__device__ __forceinline__ float ex2(float x){
    float r; asm("ex2.approx.ftz.f32 %0, %1;" : "=f"(r) : "f"(x)); return r;
}
__device__ __forceinline__ float silu_f(float x){
    return x / (1.f + __expf(-x));
}
__device__ __forceinline__ float sp_f(float v){   // softplus
    if (v > 15.f) return v;
    float e = ex2(v * LOG2E);
    return __log2f(1.f + e) * LN2;
}
__device__ __forceinline__ void split_bf16(float v, __nv_bfloat16& h, __nv_bfloat16& l){
    h = __float2bfloat16(v);
    l = __float2bfloat16(v - __bfloat162float(h));
}
__device__ __forceinline__ float b2f(__nv_bfloat16 v){ return __bfloat162float(v); }

// ---------------- packed f32x2 helpers (sm_103a FFMA2 via PTX) ----------------
__device__ __forceinline__ u64 pk2(float lo, float hi){
    u64 d; asm("mov.b64 %0, {%1,%2};" : "=l"(d) : "f"(lo), "f"(hi)); return d;
}
__device__ __forceinline__ void upk2(float& lo, float& hi, u64 v){
    asm("mov.b64 {%0,%1}, %2;" : "=f"(lo), "=f"(hi) : "l"(v));
}
__device__ __forceinline__ u64 fma2_(u64 a, u64 b, u64 c){
    u64 d; asm("fma.rn.f32x2 %0, %1, %2, %3;" : "=l"(d) : "l"(a), "l"(b), "l"(c)); return d;
}
__device__ __forceinline__ u64 mul2_(u64 a, u64 b){
    u64 d; asm("mul.rn.f32x2 %0, %1, %2;" : "=l"(d) : "l"(a), "l"(b)); return d;
}

// ---------------- PTX helpers ----------------
__device__ __forceinline__ void cpa16(u32 dst, const void* src){
    asm volatile("cp.async.ca.shared.global [%0], [%1], 16;" :: "r"(dst), "l"(src));
}
__device__ __forceinline__ void cp_commit(){
    asm volatile("cp.async.commit_group;");
}
__device__ __forceinline__ void cp_wait1(){
    asm volatile("cp.async.wait_group 1;");
}
__device__ __forceinline__ void cp_wait0(){
    asm volatile("cp.async.wait_group 0;");
}
__device__ __forceinline__ void ldsm4(u32& x0, u32& x1, u32& x2, u32& x3, u32 addr){
    asm volatile("ldmatrix.sync.aligned.m8n8.x4.shared.b16 {%0,%1,%2,%3}, [%4];"
                 : "=r"(x0), "=r"(x1), "=r"(x2), "=r"(x3) : "r"(addr));
}
__device__ __forceinline__ void mma16816(float& d0, float& d1, float& d2, float& d3,
                                         u32 a0, u32 a1, u32 a2, u32 a3,
                                         u32 v0, u32 v1){
    asm volatile("mma.sync.aligned.m16n8k16.row.col.f32.bf16.bf16.f32 "
                 "{%0,%1,%2,%3},{%4,%5,%6,%7},{%8,%9},{%0,%1,%2,%3};"
                 : "+f"(d0), "+f"(d1), "+f"(d2), "+f"(d3)
                 : "r"(a0), "r"(a1), "r"(a2), "r"(a3), "r"(v0), "r"(v1));
}

// ---------------- 1) LayerNorm over channels -> bf16 hi/lo ----------------
__global__ void ln_kernel(const float* __restrict__ x,
                          const float* __restrict__ w,
                          const float* __restrict__ bsh)
{
    int b = blockIdx.y, p0 = blockIdx.x * 32;
    int tx = threadIdx.x, ty = threadIdx.y;
    __shared__ float sx[CC][33];
    __shared__ float red[2][8][32];
    __shared__ float smu[32], srs[32];

    float s1 = 0.f, s2 = 0.f;
    for (int c = ty; c < CC; c += 8) {
        float v = x[((size_t)(b*CC + c))*LL + p0 + tx];
        sx[c][tx] = v; s1 += v; s2 += v*v;
    }
    red[0][ty][tx] = s1; red[1][ty][tx] = s2;
    __syncthreads();
    if (ty == 0) {
        float a = 0.f, q = 0.f;
        #pragma unroll
        for (int j = 0; j < 8; j++){ a += red[0][j][tx]; q += red[1][j][tx]; }
        float mu = a / CC;
        float var = q / CC - mu*mu;
        smu[tx] = mu; srs[tx] = rsqrtf(var + 1e-5f);
    }
    __syncthreads();
    int tid = ty*32 + tx;
    for (int e = tid; e < 32*CC; e += 256) {
        int pp = e / CC, cc = e % CC;
        float v = (sx[cc][pp] - smu[pp]) * srs[pp] * w[cc] + bsh[cc];
        size_t idx = ((size_t)(b*LL + p0 + pp))*CC + cc;
        __nv_bfloat16 h, l; split_bf16(v, h, l);
        g_xnh[idx] = h; g_xnl[idx] = l;
    }
}

// ---------------- weight conversion (hi/lo split + zero padding) ----------------
__global__ void cvt_weights(const float* __restrict__ wi,
                            const float* __restrict__ wx,
                            const float* __restrict__ wo)
{
    int stride = gridDim.x * blockDim.x;
    int t = blockIdx.x * blockDim.x + threadIdx.x;
    for (int e = t; e < 768*CC; e += stride) {
        __nv_bfloat16 h, l; split_bf16(wi[e], h, l);
        g_wih[e] = h; g_wil[e] = l;
    }
    for (int e = t; e < 128*DI; e += stride) {
        int n = e / DI, k = e % DI;
        float v = (n < NDBL) ? wx[n*DI + k] : 0.f;
        __nv_bfloat16 h, l; split_bf16(v, h, l);
        g_wxh[e] = h; g_wxl[e] = l;
    }
    for (int e = t; e < 256*DI; e += stride) {
        int n = e / DI, k = e % DI;
        float v = (n < CC) ? wo[n*DI + k] : 0.f;
        __nv_bfloat16 h, l; split_bf16(v, h, l);
        g_woh[e] = h; g_wol[e] = l;
    }
}

// ---------------- tensor-core GEMM mainloop (shared by both kernels) ----------
#define ROWB   80
#define OFF_AH 0
#define OFF_AL (128*ROWB)
#define OFF_BH (2*128*ROWB)
#define OFF_BL (3*128*ROWB)
#define STAGEB (4*128*ROWB)
#define SMEM_TC (2*STAGEB)

__device__ __forceinline__ void tc_mainloop(
    const __nv_bfloat16* Ahp, const __nv_bfloat16* Alp,
    const __nv_bfloat16* Bhp, const __nv_bfloat16* Blp,
    int K, int m0, int n0, char* smem, float acc[2][8][4])
{
    u32 sbase = (u32)__cvta_generic_to_shared(smem);
    int tid = threadIdx.x;
    int lane = tid & 31, wid = tid >> 5;
    int wm = wid & 3, wn = wid >> 2;

    int r0c = tid >> 2, c0c = tid & 3;
    int r1c = (tid + 256) >> 2, c1c = (tid + 256) & 3;
    int NIT = K / 32;

    for (int pre = 0; pre < 2 && pre < NIT; pre++) {
        int k0 = pre * 32;
        u32 st = sbase + (u32)(pre & 1) * STAGEB;
        cpa16(st + OFF_AH + r0c*ROWB + c0c*16, Ahp + (size_t)(m0 + r0c)*K + k0 + c0c*8);
        cpa16(st + OFF_AH + r1c*ROWB + c1c*16, Ahp + (size_t)(m0 + r1c)*K + k0 + c1c*8);
        cpa16(st + OFF_AL + r0c*ROWB + c0c*16, Alp + (size_t)(m0 + r0c)*K + k0 + c0c*8);
        cpa16(st + OFF_AL + r1c*ROWB + c1c*16, Alp + (size_t)(m0 + r1c)*K + k0 + c1c*8);
        cpa16(st + OFF_BH + r0c*ROWB + c0c*16, Bhp + (size_t)(n0 + r0c)*K + k0 + c0c*8);
        cpa16(st + OFF_BH + r1c*ROWB + c1c*16, Bhp + (size_t)(n0 + r1c)*K + k0 + c1c*8);
        cpa16(st + OFF_BL + r0c*ROWB + c0c*16, Blp + (size_t)(n0 + r0c)*K + k0 + c0c*8);
        cpa16(st + OFF_BL + r1c*ROWB + c1c*16, Blp + (size_t)(n0 + r1c)*K + k0 + c1c*8);
        cp_commit();
    }

    for (int it = 0; it < NIT; it++) {
        cp_wait1();
        __syncthreads();

        u32 st = sbase + (u32)(it & 1) * STAGEB;
        #pragma unroll
        for (int ks = 0; ks < 2; ks++) {
            u32 fah0[4], fah1[4], fal0[4], fal1[4];
            {
                u32 adr0 = st + OFF_AH + (u32)((wm*32 + (lane & 15))*ROWB
                         + ks*32 + (lane >> 4)*16);
                u32 adr1 = adr0 + 16*ROWB;
                ldsm4(fah0[0], fah0[1], fah0[2], fah0[3], adr0);
                ldsm4(fal0[0], fal0[1], fal0[2], fal0[3], adr0 + (OFF_AL - OFF_AH));
                ldsm4(fah1[0], fah1[1], fah1[2], fah1[3], adr1);
                ldsm4(fal1[0], fal1[1], fal1[2], fal1[3], adr1 + (OFF_AL - OFF_AH));
            }
            #pragma unroll
            for (int j = 0; j < 4; j++) {
                u32 fbh[4], fbl[4];
                u32 bdr = st + OFF_BH + (u32)((wn*64 + j*16 + (lane & 15))*ROWB
                        + ks*32 + (lane >> 4)*16);
                ldsm4(fbh[0], fbh[1], fbh[2], fbh[3], bdr);
                ldsm4(fbl[0], fbl[1], fbl[2], fbl[3], bdr + (OFF_BL - OFF_BH));

                mma16816(acc[0][2*j][0], acc[0][2*j][1], acc[0][2*j][2], acc[0][2*j][3],
                         fah0[0], fah0[1], fah0[2], fah0[3], fbh[0], fbh[2]);
                mma16816(acc[0][2*j][0], acc[0][2*j][1], acc[0][2*j][2], acc[0][2*j][3],
                         fah0[0], fah0[1], fah0[2], fah0[3], fbl[0], fbl[2]);
                mma16816(acc[0][2*j][0], acc[0][2*j][1], acc[0][2*j][2], acc[0][2*j][3],
                         fal0[0], fal0[1], fal0[2], fal0[3], fbh[0], fbh[2]);
                mma16816(acc[0][2*j+1][0], acc[0][2*j+1][1], acc[0][2*j+1][2], acc[0][2*j+1][3],
                         fah0[0], fah0[1], fah0[2], fah0[3], fbh[1], fbh[3]);
                mma16816(acc[0][2*j+1][0], acc[0][2*j+1][1], acc[0][2*j+1][2], acc[0][2*j+1][3],
                         fah0[0], fah0[1], fah0[2], fah0[3], fbl[1], fbl[3]);
                mma16816(acc[0][2*j+1][0], acc[0][2*j+1][1], acc[0][2*j+1][2], acc[0][2*j+1][3],
                         fal0[0], fal0[1], fal0[2], fal0[3], fbh[1], fbh[3]);

                mma16816(acc[1][2*j][0], acc[1][2*j][1], acc[1][2*j][2], acc[1][2*j][3],
                         fah1[0], fah1[1], fah1[2], fah1[3], fbh[0], fbh[2]);
                mma16816(acc[1][2*j][0], acc[1][2*j][1], acc[1][2*j][2], acc[1][2*j][3],
                         fah1[0], fah1[1], fah1[2], fah1[3], fbl[0], fbl[2]);
                mma16816(acc[1][2*j][0], acc[1][2*j][1], acc[1][2*j][2], acc[1][2*j][3],
                         fal1[0], fal1[1], fal1[2], fal1[3], fbh[0], fbh[2]);
                mma16816(acc[1][2*j+1][0], acc[1][2*j+1][1], acc[1][2*j+1][2], acc[1][2*j+1][3],
                         fah1[0], fah1[1], fah1[2], fah1[3], fbh[1], fbh[3]);
                mma16816(acc[1][2*j+1][0], acc[1][2*j+1][1], acc[1][2*j+1][2], acc[1][2*j+1][3],
                         fah1[0], fah1[1], fah1[2], fah1[3], fbl[1], fbl[3]);
                mma16816(acc[1][2*j+1][0], acc[1][2*j+1][1], acc[1][2*j+1][2], acc[1][2*j+1][3],
                         fal1[0], fal1[1], fal1[2], fal1[3], fbh[1], fbh[3]);
            }
        }
        __syncthreads();
        if (it + 2 < NIT) {
            int k0 = (it + 2) * 32;
            u32 st2 = sbase + (u32)((it + 2) & 1) * STAGEB;
            cpa16(st2 + OFF_AH + r0c*ROWB + c0c*16, Ahp + (size_t)(m0 + r0c)*K + k0 + c0c*8);
            cpa16(st2 + OFF_AH + r1c*ROWB + c1c*16, Ahp + (size_t)(m0 + r1c)*K + k0 + c1c*8);
            cpa16(st2 + OFF_AL + r0c*ROWB + c0c*16, Alp + (size_t)(m0 + r0c)*K + k0 + c0c*8);
            cpa16(st2 + OFF_AL + r1c*ROWB + c1c*16, Alp + (size_t)(m0 + r1c)*K + k0 + c1c*8);
            cpa16(st2 + OFF_BH + r0c*ROWB + c0c*16, Bhp + (size_t)(n0 + r0c)*K + k0 + c0c*8);
            cpa16(st2 + OFF_BH + r1c*ROWB + c1c*16, Bhp + (size_t)(n0 + r1c)*K + k0 + c1c*8);
            cpa16(st2 + OFF_BL + r0c*ROWB + c0c*16, Blp + (size_t)(n0 + r0c)*K + k0 + c0c*8);
            cpa16(st2 + OFF_BL + r1c*ROWB + c1c*16, Blp + (size_t)(n0 + r1c)*K + k0 + c1c*8);
        }
        cp_commit();
    }
}

// plain fp32 store (z-batched)
__global__ void __launch_bounds__(256)
gemm_tc_store(const __nv_bfloat16* __restrict__ Ahp, const __nv_bfloat16* __restrict__ Alp,
              const __nv_bfloat16* __restrict__ Bhp, const __nv_bfloat16* __restrict__ Blp,
              float* __restrict__ C, int K, int N, int ldc, size_t aZ, size_t cZ)
{
    extern __shared__ char smem[];
    float acc[2][8][4];
    #pragma unroll
    for (int i = 0; i < 2; i++)
        #pragma unroll
        for (int j = 0; j < 8; j++)
            #pragma unroll
            for (int q = 0; q < 4; q++) acc[i][j][q] = 0.f;

    int m0 = blockIdx.y*128, n0 = blockIdx.x*128;
    tc_mainloop(Ahp + (size_t)blockIdx.z*aZ, Alp + (size_t)blockIdx.z*aZ,
                Bhp, Blp, K, m0, n0, smem, acc);
    C += (size_t)blockIdx.z * cZ;

    int lane = threadIdx.x & 31, wid = threadIdx.x >> 5;
    int wm = wid & 3, wn = wid >> 2;
    int gp = lane >> 2, tg = lane & 3;
    #pragma unroll
    for (int mi = 0; mi < 2; mi++) {
        int row = m0 + wm*32 + mi*16 + gp;
        #pragma unroll
        for (int ni = 0; ni < 8; ni++) {
            int col = n0 + wn*64 + ni*8 + tg*2;
            if (col < N) {
                float2 v0; v0.x = acc[mi][ni][0]; v0.y = acc[mi][ni][1];
                float2 v1; v1.x = acc[mi][ni][2]; v1.y = acc[mi][ni][3];
                *(float2*)&C[(size_t)row*ldc + col]       = v0;
                *(float2*)&C[(size_t)(row + 8)*ldc + col] = v1;
            }
        }
    }
}

// transposed store to d_out laid out (B, C, L)
__global__ void __launch_bounds__(256)
gemm_tc_out(const __nv_bfloat16* __restrict__ Ahp, const __nv_bfloat16* __restrict__ Alp,
            const __nv_bfloat16* __restrict__ Bhp, const __nv_bfloat16* __restrict__ Blp,
            int K, int N, float* __restrict__ dout)
{
    extern __shared__ char smem[];
    float acc[2][8][4];
    #pragma unroll
    for (int i = 0; i < 2; i++)
        #pragma unroll
        for (int j = 0; j < 8; j++)
            #pragma unroll
            for (int q = 0; q < 4; q++) acc[i][j][q] = 0.f;

    int m0 = blockIdx.y*128, n0 = blockIdx.x*128;
    tc_mainloop(Ahp, Alp, Bhp, Blp, K, m0, n0, smem, acc);

    cp_wait0();
    __syncthreads();
    float* so = (float*)smem;   // [128][132]
    int lane = threadIdx.x & 31, wid = threadIdx.x >> 5;
    int wm = wid & 3, wn = wid >> 2;
    int gp = lane >> 2, tg = lane & 3;
    #pragma unroll
    for (int mi = 0; mi < 2; mi++) {
        int ml = wm*32 + mi*16 + gp;
        #pragma unroll
        for (int ni = 0; ni < 8; ni++) {
            int nl = wn*64 + ni*8 + tg*2;
            so[(size_t)nl*132 + ml]         = acc[mi][ni][0];
            so[(size_t)(nl+1)*132 + ml]     = acc[mi][ni][1];
            so[(size_t)nl*132 + ml + 8]     = acc[mi][ni][2];
            so[(size_t)(nl+1)*132 + ml + 8] = acc[mi][ni][3];
        }
    }
    __syncthreads();
    int b = m0 >> 12, p0 = m0 & (LL - 1);
    for (int e = threadIdx.x; e < 128*128; e += 256) {
        int nl = e >> 7, mlp = e & 127;
        int n = n0 + nl;
        if (n < N)
            dout[((size_t)(b*CC + n))*LL + p0 + mlp] = so[(size_t)nl*132 + mlp];
    }
}

// ---------------- depthwise causal conv (both directions) + silu -> bf16 hi/lo ----
__global__ void conv_silu_kernel(const float* __restrict__ cw, const float* __restrict__ cb)
{
    __shared__ float s[16 + 6][DI];
    int b = blockIdx.y, t0 = blockIdx.x * 16, d = threadIdx.x;

    #pragma unroll
    for (int j = 0; j < 22; j++) {
        int t = t0 - 3 + j;
        float v = 0.f;
        if (t >= 0 && t < LL) v = g_xz[((size_t)(b*LL + t))*768 + d];
        s[j][d] = v;
    }
    __syncthreads();
    float w0 = cw[d*4+0], w1 = cw[d*4+1], w2 = cw[d*4+2], w3 = cw[d*4+3];
    float bias = cb[d];
    #pragma unroll
    for (int tt = 0; tt < 16; tt++) {
        float of = w0*s[tt][d] + w1*s[tt+1][d] + w2*s[tt+2][d] + w3*s[tt+3][d] + bias;
        float ob = w3*s[tt+3][d] + w2*s[tt+4][d] + w1*s[tt+5][d] + w0*s[tt+6][d] + bias;
        size_t m = (size_t)(b*LL + t0 + tt);
        float vf = silu_f(of), vb = silu_f(ob);
        __nv_bfloat16 h, l;
        split_bf16(vf, h, l); g_xsh[0][m*DI + d] = h; g_xsl[0][m*DI + d] = l;
        split_bf16(vb, h, l); g_xsh[1][m*DI + d] = h; g_xsl[1][m*DI + d] = l;
    }
}

// ---------------- chunked selective scan (dt_proj fused, f32x2-packed state) ----
#define SROW 48   // smem row stride in floats (44 padded to 48)

template<bool P3>
__global__ void __launch_bounds__(128)
scan_kernel(const float* __restrict__ A_log,
            const float* __restrict__ dtw,
            const float* __restrict__ dtbv)
{
    __shared__ __align__(16) float sdbl[2][SW][SROW];

    int d  = blockIdx.x * 128 + threadIdx.x;
    int c  = blockIdx.y;
    int rb = blockIdx.z;
    int r  = rb >> 2, b = rb & 3;
    int tid = threadIdx.x;

    const int NSEG = P3 ? 11 : 7;          // 16B chunks per row staged
    const float* dblp = g_dbl[r];
    u32 sb = (u32)__cvta_generic_to_shared(&sdbl[0][0][0]);

    auto issue_win = [&](int w) {
        int nch = SW * NSEG;
        u32 dst0 = sb + (u32)(w & 1) * (SW*SROW*4);
        for (int q = tid; q < nch; q += 128) {
            int j = q / NSEG, seg = q % NSEG;
            int tau = c*LC + w*SW + j;
            int pos = r ? (LL - 1 - tau) : tau;
            size_t m = (size_t)b*LL + pos;
            cpa16(dst0 + (u32)(j*SROW + seg*4)*4, dblp + m*NDBL + seg*4);
        }
        cp_commit();
    };

    float A2[DS], wdt[DTR];
    bool structured = true;
    #pragma unroll
    for (int sIdx = 0; sIdx < DS; sIdx++)
        A2[sIdx] = -__expf(A_log[d*DS + sIdx]) * LOG2E;
    #pragma unroll
    for (int sIdx = 1; sIdx < DS; sIdx++)
        structured &= fabsf(A2[sIdx] - (sIdx+1)*A2[0]) <= 1e-4f*fabsf(A2[sIdx]);
    #pragma unroll
    for (int j = 0; j < DTR; j++) wdt[j] = dtw[d*DTR + j];
    float dtb = dtbv[d];

    u64 wdt2[6];
    #pragma unroll
    for (int k = 0; k < 6; k++) wdt2[k] = pk2(wdt[2*k], wdt[2*k+1]);

    size_t base = (((size_t)rb*NC + c)*DI + d)*DS;
    u64 hp[DS/2];
    #pragma unroll
    for (int k = 0; k < DS/2; k++) {
        if (P3) {
            float2 hv = *(const float2*)&g_hstart[base + 2*k];
            hp[k] = pk2(hv.x, hv.y);
        } else {
            hp[k] = 0ull;
        }
    }

    const __nv_bfloat16* xshp = g_xsh[r];
    const __nv_bfloat16* xslp = g_xsl[r];
    float* yp = g_y[r];
    float S = 0.f;

    issue_win(0);
    if (NW > 1) issue_win(1);

    for (int w = 0; w < NW; w++) {
        if (w + 1 < NW) cp_wait1(); else cp_wait0();
        __syncthreads();
        const float (*row)[SROW] = sdbl[w & 1];

        #pragma unroll 4
        for (int j = 0; j < SW; j++) {
            int tau = c*LC + w*SW + j;
            int pos = r ? (LL - 1 - tau) : tau;
            size_t m = (size_t)b*LL + pos;

            // dt dot (packed: 6 fma2 + horizontal add)
            u64 acc2 = 0ull;
            #pragma unroll
            for (int k = 0; k < 6; k++) {
                u64 iv = *(const u64*)&row[j][2*k];
                acc2 = fma2_(iv, wdt2[k], acc2);
            }
            float alo, ahi; upk2(alo, ahi, acc2);
            float dt = sp_f(dtb + alo + ahi);

            float u  = b2f(xshp[m*DI + d]) + b2f(xslp[m*DI + d]);
            float dtx = dt * u;
            u64 dtx2 = pk2(dtx, dtx);

            float y = 0.f;
            if (structured) {
                float e1 = ex2(dt * A2[0]);
                float ee = e1 * e1;
                u64 eep = pk2(ee, ee);
                u64 ap  = pk2(e1, ee);
                u64 y2  = 0ull;
                #pragma unroll
                for (int k = 0; k < DS/2; k++) {
                    u64 Bp = *(const u64*)&row[j][DTR + 2*k];
                    hp[k] = fma2_(ap, hp[k], mul2_(dtx2, Bp));
                    if (P3) {
                        u64 Cp = *(const u64*)&row[j][DTR + DS + 2*k];
                        y2 = fma2_(hp[k], Cp, y2);
                    }
                    if (k < DS/2 - 1) ap = mul2_(ap, eep);
                }
                if (P3) { float yl, yh; upk2(yl, yh, y2); y = yl + yh; }
            } else {
                #pragma unroll
                for (int k = 0; k < DS/2; k++) {
                    float h0, h1; upk2(h0, h1, hp[k]);
                    float a0 = ex2(dt * A2[2*k]);
                    float a1 = ex2(dt * A2[2*k+1]);
                    float B0 = row[j][DTR + 2*k], B1 = row[j][DTR + 2*k+1];
                    h0 = fmaf(a0, h0, dtx * B0);
                    h1 = fmaf(a1, h1, dtx * B1);
                    if (P3) {
                        y = fmaf(h0, row[j][DTR + DS + 2*k], y);
                        y = fmaf(h1, row[j][DTR + DS + 2*k+1], y);
                    }
                    hp[k] = pk2(h0, h1);
                }
            }
            if (P3) yp[m*DI + d] = y;
            else    S += dt;
        }
        __syncthreads();
        if (w + 2 < NW) issue_win(w + 2);
    }

    if (!P3) {
        #pragma unroll
        for (int k = 0; k < DS/2; k++) {
            float h0, h1; upk2(h0, h1, hp[k]);
            float2 hv; hv.x = h0; hv.y = h1;
            *(float2*)&g_hend[base + 2*k] = hv;
            float2 pv;
            pv.x = ex2(A2[2*k]   * S);
            pv.y = ex2(A2[2*k+1] * S);
            *(float2*)&g_pend[base + 2*k] = pv;
        }
    }
}

__global__ void scan_combine()
{
    int g = blockIdx.x * 256 + threadIdx.x;
    if (g >= 2*BB*DI*DS) return;
    int sd = g % (DI*DS);
    int rb = g / (DI*DS);
    float carry = 0.f;
    for (int c = 0; c < NC; c++) {
        size_t idx = ((size_t)rb*NC + c)*(DI*DS) + sd;
        g_hstart[idx] = carry;
        carry = g_pend[idx]*carry + g_hend[idx];
    }
}

// ---------------- fused gate -> bf16 hi/lo ----------------
__global__ void combine_G(const float* __restrict__ Dv)
{
    size_t g = (size_t)blockIdx.x * 256 + threadIdx.x;
    if (g >= (size_t)MM*DI) return;
    int d = (int)(g % DI);
    size_t m = g / DI;
    float z  = g_xz[m*768 + DI + d];
    float sz = silu_f(z);
    float xsum = b2f(g_xsh[0][g]) + b2f(g_xsl[0][g])
               + b2f(g_xsh[1][g]) + b2f(g_xsl[1][g]);
    float ysum = g_y[0][g] + g_y[1][g];
    float v = sz * (ysum + xsum * Dv[d]);
    __nv_bfloat16 h, l; split_bf16(v, h, l);
    g_Gh[g] = h; g_Gl[g] = l;
}

// ---------------- launch ----------------
static void* sym_addr(const void* sym) {
    void* p = nullptr;
    cudaGetSymbolAddress(&p, sym);
    return p;
}

extern "C" void kernel_launch(void* const* d_in, const int* in_sizes, int n_in,
                              void* d_out, int out_size)
{
    const float* x          = (const float*)d_in[0];
    const float* ln_w       = (const float*)d_in[1];
    const float* ln_b       = (const float*)d_in[2];
    const float* in_proj_w  = (const float*)d_in[3];
    const float* conv_w     = (const float*)d_in[4];
    const float* conv_b     = (const float*)d_in[5];
    const float* x_proj_w   = (const float*)d_in[6];
    const float* dt_proj_w  = (const float*)d_in[7];
    const float* dt_proj_b  = (const float*)d_in[8];
    const float* A_log      = (const float*)d_in[9];
    const float* D_vec      = (const float*)d_in[10];
    const float* out_proj_w = (const float*)d_in[11];
    float* out = (float*)d_out;

    float* p_xz  = (float*)sym_addr(g_xz);
    float* p_dbl = (float*)sym_addr(g_dbl);
    __nv_bfloat16* p_xnh = (__nv_bfloat16*)sym_addr(g_xnh);
    __nv_bfloat16* p_xnl = (__nv_bfloat16*)sym_addr(g_xnl);
    __nv_bfloat16* p_xsh = (__nv_bfloat16*)sym_addr(g_xsh);
    __nv_bfloat16* p_xsl = (__nv_bfloat16*)sym_addr(g_xsl);
    __nv_bfloat16* p_Gh  = (__nv_bfloat16*)sym_addr(g_Gh);
    __nv_bfloat16* p_Gl  = (__nv_bfloat16*)sym_addr(g_Gl);
    __nv_bfloat16* p_wih = (__nv_bfloat16*)sym_addr(g_wih);
    __nv_bfloat16* p_wil = (__nv_bfloat16*)sym_addr(g_wil);
    __nv_bfloat16* p_wxh = (__nv_bfloat16*)sym_addr(g_wxh);
    __nv_bfloat16* p_wxl = (__nv_bfloat16*)sym_addr(g_wxl);
    __nv_bfloat16* p_woh = (__nv_bfloat16*)sym_addr(g_woh);
    __nv_bfloat16* p_wol = (__nv_bfloat16*)sym_addr(g_wol);

    cudaFuncSetAttribute((const void*)gemm_tc_store,
                         cudaFuncAttributeMaxDynamicSharedMemorySize, SMEM_TC);
    cudaFuncSetAttribute((const void*)gemm_tc_out,
                         cudaFuncAttributeMaxDynamicSharedMemorySize, SMEM_TC);

    // 1) LayerNorm -> bf16 hi/lo
    ln_kernel<<<dim3(LL/32, BB), dim3(32, 8)>>>(x, ln_w, ln_b);

    // 1b) weight conversion
    cvt_weights<<<256, 256>>>(in_proj_w, x_proj_w, out_proj_w);

    // 2) in_proj: xz[M,768] = xn @ Wi^T  (tensor cores)
    gemm_tc_store<<<dim3(768/128, MM/128, 1), 256, SMEM_TC>>>(
        p_xnh, p_xnl, p_wih, p_wil, p_xz, CC, 768, 768, 0, 0);

    // 3) conv + silu (both directions) -> bf16 hi/lo
    conv_silu_kernel<<<dim3(LL/16, BB), DI>>>(conv_w, conv_b);

    // 4) x_proj both dirs: dbl[M,44] = xs @ Wx^T  (tensor cores)
    gemm_tc_store<<<dim3(1, MM/128, 2), 256, SMEM_TC>>>(
        p_xsh, p_xsl, p_wxh, p_wxl, p_dbl, DI, NDBL, NDBL,
        (size_t)MM*DI, (size_t)MM*NDBL);

    // 5-8) chunked selective scan: fused dt_proj, f32x2, NC=64 for 2x TLP
    scan_kernel<false><<<dim3(DI/128, NC, 2*BB), 128>>>(A_log, dt_proj_w, dt_proj_b);
    scan_combine<<<dim3((2*BB*DI*DS + 255)/256), 256>>>();
    scan_kernel<true><<<dim3(DI/128, NC, 2*BB), 128>>>(A_log, dt_proj_w, dt_proj_b);

    // 9) fused gate -> bf16 hi/lo
    combine_G<<<dim3((MM*DI + 255)/256), 256>>>(D_vec);

    // 10) out_proj (tensor cores) with transposed store to (B,C,H,W)
    gemm_tc_out<<<dim3(2, MM/128, 1), 256, SMEM_TC>>>(
        p_Gh, p_Gl, p_woh, p_wol, DI, CC, out);
}

// round 13
// speedup vs baseline: 1.2036x; 1.0957x over previous
#include <cuda_runtime.h>
#include <cuda_bf16.h>
#include <cstdint>
#include <math.h>

typedef unsigned int u32;
typedef unsigned long long u64;

// ---------------- problem constants ----------------
#define BB   4
#define CC   192
#define HH   64
#define WW   64
#define LL   (HH*WW)          // 4096
#define MM   (BB*LL)          // 16384
#define DI   384
#define DS   16
#define DTR  12
#define NDBL 44               // DTR + 2*DS
#define NC   32               // scan chunks
#define LC   (LL/NC)          // 128
#define SW   16               // scan smem window (timesteps)
#define NW   (LC/SW)          // 8 windows
#define LOG2E 1.4426950408889634f
#define LN2   0.6931471805599453f

// ---------------- scratch (device globals: allocation-free) ----------------
__device__ __align__(128) float g_xz [(size_t)MM*768];
__device__ __align__(128) float g_dbl[2][(size_t)MM*NDBL];
__device__ __align__(128) float g_y  [2][(size_t)MM*DI];
__device__ float g_hend  [2*BB*NC*DI*DS];
__device__ float g_pend  [2*BB*NC*DI*DS];
__device__ float g_hstart[2*BB*NC*DI*DS];

// bf16 hi/lo pairs for tensor-core GEMMs (k-contiguous natural layouts)
__device__ __align__(128) __nv_bfloat16 g_xnh[(size_t)MM*CC];
__device__ __align__(128) __nv_bfloat16 g_xnl[(size_t)MM*CC];
__device__ __align__(128) __nv_bfloat16 g_xsh[2][(size_t)MM*DI];
__device__ __align__(128) __nv_bfloat16 g_xsl[2][(size_t)MM*DI];
__device__ __align__(128) __nv_bfloat16 g_Gh [(size_t)MM*DI];
__device__ __align__(128) __nv_bfloat16 g_Gl [(size_t)MM*DI];
__device__ __align__(128) __nv_bfloat16 g_wih[768*CC];
__device__ __align__(128) __nv_bfloat16 g_wil[768*CC];
__device__ __align__(128) __nv_bfloat16 g_wxh[128*DI];   // x_proj W padded 44->128 rows
__device__ __align__(128) __nv_bfloat16 g_wxl[128*DI];
__device__ __align__(128) __nv_bfloat16 g_woh[256*DI];   // out_proj W padded 192->256 rows
__device__ __align__(128) __nv_bfloat16 g_wol[256*DI];

__device__ __forceinline__ float ex2(float x){
    float r; asm("ex2.approx.ftz.f32 %0, %1;" : "=f"(r) : "f"(x)); return r;
}
__device__ __forceinline__ float silu_f(float x){
    return x / (1.f + __expf(-x));
}
__device__ __forceinline__ float sp_f(float v){   // softplus
    if (v > 15.f) return v;
    float e = ex2(v * LOG2E);
    return __log2f(1.f + e) * LN2;
}
__device__ __forceinline__ void split_bf16(float v, __nv_bfloat16& h, __nv_bfloat16& l){
    h = __float2bfloat16(v);
    l = __float2bfloat16(v - __bfloat162float(h));
}
__device__ __forceinline__ float b2f(__nv_bfloat16 v){ return __bfloat162float(v); }
__device__ __forceinline__ __nv_bfloat162 mk2(__nv_bfloat16 x, __nv_bfloat16 y){
    __nv_bfloat162 t; t.x = x; t.y = y; return t;
}

// ---------------- packed f32x2 helpers (sm_103a FFMA2 via PTX) ----------------
__device__ __forceinline__ u64 pk2(float lo, float hi){
    u64 d; asm("mov.b64 %0, {%1,%2};" : "=l"(d) : "f"(lo), "f"(hi)); return d;
}
__device__ __forceinline__ void upk2(float& lo, float& hi, u64 v){
    asm("mov.b64 {%0,%1}, %2;" : "=f"(lo), "=f"(hi) : "l"(v));
}
__device__ __forceinline__ u64 fma2_(u64 a, u64 b, u64 c){
    u64 d; asm("fma.rn.f32x2 %0, %1, %2, %3;" : "=l"(d) : "l"(a), "l"(b), "l"(c)); return d;
}
__device__ __forceinline__ u64 mul2_(u64 a, u64 b){
    u64 d; asm("mul.rn.f32x2 %0, %1, %2;" : "=l"(d) : "l"(a), "l"(b)); return d;
}

// ---------------- PTX helpers ----------------
__device__ __forceinline__ void cpa16(u32 dst, const void* src){
    asm volatile("cp.async.ca.shared.global [%0], [%1], 16;" :: "r"(dst), "l"(src));
}
__device__ __forceinline__ void cp_commit(){
    asm volatile("cp.async.commit_group;");
}
__device__ __forceinline__ void cp_wait1(){
    asm volatile("cp.async.wait_group 1;");
}
__device__ __forceinline__ void cp_wait0(){
    asm volatile("cp.async.wait_group 0;");
}
__device__ __forceinline__ void ldsm4(u32& x0, u32& x1, u32& x2, u32& x3, u32 addr){
    asm volatile("ldmatrix.sync.aligned.m8n8.x4.shared.b16 {%0,%1,%2,%3}, [%4];"
                 : "=r"(x0), "=r"(x1), "=r"(x2), "=r"(x3) : "r"(addr));
}
__device__ __forceinline__ void mma16816(float& d0, float& d1, float& d2, float& d3,
                                         u32 a0, u32 a1, u32 a2, u32 a3,
                                         u32 v0, u32 v1){
    asm volatile("mma.sync.aligned.m16n8k16.row.col.f32.bf16.bf16.f32 "
                 "{%0,%1,%2,%3},{%4,%5,%6,%7},{%8,%9},{%0,%1,%2,%3};"
                 : "+f"(d0), "+f"(d1), "+f"(d2), "+f"(d3)
                 : "r"(a0), "r"(a1), "r"(a2), "r"(a3), "r"(v0), "r"(v1));
}

// ---------------- 1) LayerNorm over channels -> bf16 hi/lo ----------------
__global__ void ln_kernel(const float* __restrict__ x,
                          const float* __restrict__ w,
                          const float* __restrict__ bsh)
{
    int b = blockIdx.y, p0 = blockIdx.x * 32;
    int tx = threadIdx.x, ty = threadIdx.y;
    __shared__ float sx[CC][33];
    __shared__ float red[2][8][32];
    __shared__ float smu[32], srs[32];

    float s1 = 0.f, s2 = 0.f;
    for (int c = ty; c < CC; c += 8) {
        float v = x[((size_t)(b*CC + c))*LL + p0 + tx];
        sx[c][tx] = v; s1 += v; s2 += v*v;
    }
    red[0][ty][tx] = s1; red[1][ty][tx] = s2;
    __syncthreads();
    if (ty == 0) {
        float a = 0.f, q = 0.f;
        #pragma unroll
        for (int j = 0; j < 8; j++){ a += red[0][j][tx]; q += red[1][j][tx]; }
        float mu = a / CC;
        float var = q / CC - mu*mu;
        smu[tx] = mu; srs[tx] = rsqrtf(var + 1e-5f);
    }
    __syncthreads();
    int tid = ty*32 + tx;
    for (int e = tid; e < 32*CC; e += 256) {
        int pp = e / CC, cc = e % CC;
        float v = (sx[cc][pp] - smu[pp]) * srs[pp] * w[cc] + bsh[cc];
        size_t idx = ((size_t)(b*LL + p0 + pp))*CC + cc;
        __nv_bfloat16 h, l; split_bf16(v, h, l);
        g_xnh[idx] = h; g_xnl[idx] = l;
    }
}

// ---------------- weight conversion (hi/lo split + zero padding) ----------------
__global__ void cvt_weights(const float* __restrict__ wi,
                            const float* __restrict__ wx,
                            const float* __restrict__ wo)
{
    int stride = gridDim.x * blockDim.x;
    int t = blockIdx.x * blockDim.x + threadIdx.x;
    for (int e = t; e < 768*CC; e += stride) {
        __nv_bfloat16 h, l; split_bf16(wi[e], h, l);
        g_wih[e] = h; g_wil[e] = l;
    }
    for (int e = t; e < 128*DI; e += stride) {
        int n = e / DI, k = e % DI;
        float v = (n < NDBL) ? wx[n*DI + k] : 0.f;
        __nv_bfloat16 h, l; split_bf16(v, h, l);
        g_wxh[e] = h; g_wxl[e] = l;
    }
    for (int e = t; e < 256*DI; e += stride) {
        int n = e / DI, k = e % DI;
        float v = (n < CC) ? wo[n*DI + k] : 0.f;
        __nv_bfloat16 h, l; split_bf16(v, h, l);
        g_woh[e] = h; g_wol[e] = l;
    }
}

// ---------------- tensor-core GEMM mainloop (shared by both kernels) ----------
#define ROWB   80
#define OFF_AH 0
#define OFF_AL (128*ROWB)
#define OFF_BH (2*128*ROWB)
#define OFF_BL (3*128*ROWB)
#define STAGEB (4*128*ROWB)
#define SMEM_TC (2*STAGEB)

__device__ __forceinline__ void tc_mainloop(
    const __nv_bfloat16* Ahp, const __nv_bfloat16* Alp,
    const __nv_bfloat16* Bhp, const __nv_bfloat16* Blp,
    int K, int m0, int n0, char* smem, float acc[2][8][4])
{
    u32 sbase = (u32)__cvta_generic_to_shared(smem);
    int tid = threadIdx.x;
    int lane = tid & 31, wid = tid >> 5;
    int wm = wid & 3, wn = wid >> 2;

    int r0c = tid >> 2, c0c = tid & 3;
    int r1c = (tid + 256) >> 2, c1c = (tid + 256) & 3;
    int NIT = K / 32;

    for (int pre = 0; pre < 2 && pre < NIT; pre++) {
        int k0 = pre * 32;
        u32 st = sbase + (u32)(pre & 1) * STAGEB;
        cpa16(st + OFF_AH + r0c*ROWB + c0c*16, Ahp + (size_t)(m0 + r0c)*K + k0 + c0c*8);
        cpa16(st + OFF_AH + r1c*ROWB + c1c*16, Ahp + (size_t)(m0 + r1c)*K + k0 + c1c*8);
        cpa16(st + OFF_AL + r0c*ROWB + c0c*16, Alp + (size_t)(m0 + r0c)*K + k0 + c0c*8);
        cpa16(st + OFF_AL + r1c*ROWB + c1c*16, Alp + (size_t)(m0 + r1c)*K + k0 + c1c*8);
        cpa16(st + OFF_BH + r0c*ROWB + c0c*16, Bhp + (size_t)(n0 + r0c)*K + k0 + c0c*8);
        cpa16(st + OFF_BH + r1c*ROWB + c1c*16, Bhp + (size_t)(n0 + r1c)*K + k0 + c1c*8);
        cpa16(st + OFF_BL + r0c*ROWB + c0c*16, Blp + (size_t)(n0 + r0c)*K + k0 + c0c*8);
        cpa16(st + OFF_BL + r1c*ROWB + c1c*16, Blp + (size_t)(n0 + r1c)*K + k0 + c1c*8);
        cp_commit();
    }

    for (int it = 0; it < NIT; it++) {
        cp_wait1();
        __syncthreads();

        u32 st = sbase + (u32)(it & 1) * STAGEB;
        #pragma unroll
        for (int ks = 0; ks < 2; ks++) {
            u32 fah0[4], fah1[4], fal0[4], fal1[4];
            {
                u32 adr0 = st + OFF_AH + (u32)((wm*32 + (lane & 15))*ROWB
                         + ks*32 + (lane >> 4)*16);
                u32 adr1 = adr0 + 16*ROWB;
                ldsm4(fah0[0], fah0[1], fah0[2], fah0[3], adr0);
                ldsm4(fal0[0], fal0[1], fal0[2], fal0[3], adr0 + (OFF_AL - OFF_AH));
                ldsm4(fah1[0], fah1[1], fah1[2], fah1[3], adr1);
                ldsm4(fal1[0], fal1[1], fal1[2], fal1[3], adr1 + (OFF_AL - OFF_AH));
            }
            #pragma unroll
            for (int j = 0; j < 4; j++) {
                u32 fbh[4], fbl[4];
                u32 bdr = st + OFF_BH + (u32)((wn*64 + j*16 + (lane & 15))*ROWB
                        + ks*32 + (lane >> 4)*16);
                ldsm4(fbh[0], fbh[1], fbh[2], fbh[3], bdr);
                ldsm4(fbl[0], fbl[1], fbl[2], fbl[3], bdr + (OFF_BL - OFF_BH));

                mma16816(acc[0][2*j][0], acc[0][2*j][1], acc[0][2*j][2], acc[0][2*j][3],
                         fah0[0], fah0[1], fah0[2], fah0[3], fbh[0], fbh[2]);
                mma16816(acc[0][2*j][0], acc[0][2*j][1], acc[0][2*j][2], acc[0][2*j][3],
                         fah0[0], fah0[1], fah0[2], fah0[3], fbl[0], fbl[2]);
                mma16816(acc[0][2*j][0], acc[0][2*j][1], acc[0][2*j][2], acc[0][2*j][3],
                         fal0[0], fal0[1], fal0[2], fal0[3], fbh[0], fbh[2]);
                mma16816(acc[0][2*j+1][0], acc[0][2*j+1][1], acc[0][2*j+1][2], acc[0][2*j+1][3],
                         fah0[0], fah0[1], fah0[2], fah0[3], fbh[1], fbh[3]);
                mma16816(acc[0][2*j+1][0], acc[0][2*j+1][1], acc[0][2*j+1][2], acc[0][2*j+1][3],
                         fah0[0], fah0[1], fah0[2], fah0[3], fbl[1], fbl[3]);
                mma16816(acc[0][2*j+1][0], acc[0][2*j+1][1], acc[0][2*j+1][2], acc[0][2*j+1][3],
                         fal0[0], fal0[1], fal0[2], fal0[3], fbh[1], fbh[3]);

                mma16816(acc[1][2*j][0], acc[1][2*j][1], acc[1][2*j][2], acc[1][2*j][3],
                         fah1[0], fah1[1], fah1[2], fah1[3], fbh[0], fbh[2]);
                mma16816(acc[1][2*j][0], acc[1][2*j][1], acc[1][2*j][2], acc[1][2*j][3],
                         fah1[0], fah1[1], fah1[2], fah1[3], fbl[0], fbl[2]);
                mma16816(acc[1][2*j][0], acc[1][2*j][1], acc[1][2*j][2], acc[1][2*j][3],
                         fal1[0], fal1[1], fal1[2], fal1[3], fbh[0], fbh[2]);
                mma16816(acc[1][2*j+1][0], acc[1][2*j+1][1], acc[1][2*j+1][2], acc[1][2*j+1][3],
                         fah1[0], fah1[1], fah1[2], fah1[3], fbh[1], fbh[3]);
                mma16816(acc[1][2*j+1][0], acc[1][2*j+1][1], acc[1][2*j+1][2], acc[1][2*j+1][3],
                         fah1[0], fah1[1], fah1[2], fah1[3], fbl[1], fbl[3]);
                mma16816(acc[1][2*j+1][0], acc[1][2*j+1][1], acc[1][2*j+1][2], acc[1][2*j+1][3],
                         fal1[0], fal1[1], fal1[2], fal1[3], fbh[1], fbh[3]);
            }
        }
        __syncthreads();
        if (it + 2 < NIT) {
            int k0 = (it + 2) * 32;
            u32 st2 = sbase + (u32)((it + 2) & 1) * STAGEB;
            cpa16(st2 + OFF_AH + r0c*ROWB + c0c*16, Ahp + (size_t)(m0 + r0c)*K + k0 + c0c*8);
            cpa16(st2 + OFF_AH + r1c*ROWB + c1c*16, Ahp + (size_t)(m0 + r1c)*K + k0 + c1c*8);
            cpa16(st2 + OFF_AL + r0c*ROWB + c0c*16, Alp + (size_t)(m0 + r0c)*K + k0 + c0c*8);
            cpa16(st2 + OFF_AL + r1c*ROWB + c1c*16, Alp + (size_t)(m0 + r1c)*K + k0 + c1c*8);
            cpa16(st2 + OFF_BH + r0c*ROWB + c0c*16, Bhp + (size_t)(n0 + r0c)*K + k0 + c0c*8);
            cpa16(st2 + OFF_BH + r1c*ROWB + c1c*16, Bhp + (size_t)(n0 + r1c)*K + k0 + c1c*8);
            cpa16(st2 + OFF_BL + r0c*ROWB + c0c*16, Blp + (size_t)(n0 + r0c)*K + k0 + c0c*8);
            cpa16(st2 + OFF_BL + r1c*ROWB + c1c*16, Blp + (size_t)(n0 + r1c)*K + k0 + c1c*8);
        }
        cp_commit();
    }
}

// plain fp32 store (z-batched)
__global__ void __launch_bounds__(256)
gemm_tc_store(const __nv_bfloat16* __restrict__ Ahp, const __nv_bfloat16* __restrict__ Alp,
              const __nv_bfloat16* __restrict__ Bhp, const __nv_bfloat16* __restrict__ Blp,
              float* __restrict__ C, int K, int N, int ldc, size_t aZ, size_t cZ)
{
    extern __shared__ char smem[];
    float acc[2][8][4];
    #pragma unroll
    for (int i = 0; i < 2; i++)
        #pragma unroll
        for (int j = 0; j < 8; j++)
            #pragma unroll
            for (int q = 0; q < 4; q++) acc[i][j][q] = 0.f;

    int m0 = blockIdx.y*128, n0 = blockIdx.x*128;
    tc_mainloop(Ahp + (size_t)blockIdx.z*aZ, Alp + (size_t)blockIdx.z*aZ,
                Bhp, Blp, K, m0, n0, smem, acc);
    C += (size_t)blockIdx.z * cZ;

    int lane = threadIdx.x & 31, wid = threadIdx.x >> 5;
    int wm = wid & 3, wn = wid >> 2;
    int gp = lane >> 2, tg = lane & 3;
    #pragma unroll
    for (int mi = 0; mi < 2; mi++) {
        int row = m0 + wm*32 + mi*16 + gp;
        #pragma unroll
        for (int ni = 0; ni < 8; ni++) {
            int col = n0 + wn*64 + ni*8 + tg*2;
            if (col < N) {
                float2 v0; v0.x = acc[mi][ni][0]; v0.y = acc[mi][ni][1];
                float2 v1; v1.x = acc[mi][ni][2]; v1.y = acc[mi][ni][3];
                *(float2*)&C[(size_t)row*ldc + col]       = v0;
                *(float2*)&C[(size_t)(row + 8)*ldc + col] = v1;
            }
        }
    }
}

// transposed store to d_out laid out (B, C, L)
__global__ void __launch_bounds__(256)
gemm_tc_out(const __nv_bfloat16* __restrict__ Ahp, const __nv_bfloat16* __restrict__ Alp,
            const __nv_bfloat16* __restrict__ Bhp, const __nv_bfloat16* __restrict__ Blp,
            int K, int N, float* __restrict__ dout)
{
    extern __shared__ char smem[];
    float acc[2][8][4];
    #pragma unroll
    for (int i = 0; i < 2; i++)
        #pragma unroll
        for (int j = 0; j < 8; j++)
            #pragma unroll
            for (int q = 0; q < 4; q++) acc[i][j][q] = 0.f;

    int m0 = blockIdx.y*128, n0 = blockIdx.x*128;
    tc_mainloop(Ahp, Alp, Bhp, Blp, K, m0, n0, smem, acc);

    cp_wait0();
    __syncthreads();
    float* so = (float*)smem;   // [128][132]
    int lane = threadIdx.x & 31, wid = threadIdx.x >> 5;
    int wm = wid & 3, wn = wid >> 2;
    int gp = lane >> 2, tg = lane & 3;
    #pragma unroll
    for (int mi = 0; mi < 2; mi++) {
        int ml = wm*32 + mi*16 + gp;
        #pragma unroll
        for (int ni = 0; ni < 8; ni++) {
            int nl = wn*64 + ni*8 + tg*2;
            so[(size_t)nl*132 + ml]         = acc[mi][ni][0];
            so[(size_t)(nl+1)*132 + ml]     = acc[mi][ni][1];
            so[(size_t)nl*132 + ml + 8]     = acc[mi][ni][2];
            so[(size_t)(nl+1)*132 + ml + 8] = acc[mi][ni][3];
        }
    }
    __syncthreads();
    int b = m0 >> 12, p0 = m0 & (LL - 1);
    for (int e = threadIdx.x; e < 128*128; e += 256) {
        int nl = e >> 7, mlp = e & 127;
        int n = n0 + nl;
        if (n < N)
            dout[((size_t)(b*CC + n))*LL + p0 + mlp] = so[(size_t)nl*132 + mlp];
    }
}

// ---------------- depthwise causal conv (both directions) + silu -> bf16 hi/lo ----
__global__ void conv_silu_kernel(const float* __restrict__ cw, const float* __restrict__ cb)
{
    __shared__ float s[16 + 6][DI];
    int b = blockIdx.y, t0 = blockIdx.x * 16, d = threadIdx.x;

    #pragma unroll
    for (int j = 0; j < 22; j++) {
        int t = t0 - 3 + j;
        float v = 0.f;
        if (t >= 0 && t < LL) v = g_xz[((size_t)(b*LL + t))*768 + d];
        s[j][d] = v;
    }
    __syncthreads();
    float w0 = cw[d*4+0], w1 = cw[d*4+1], w2 = cw[d*4+2], w3 = cw[d*4+3];
    float bias = cb[d];
    #pragma unroll
    for (int tt = 0; tt < 16; tt++) {
        float of = w0*s[tt][d] + w1*s[tt+1][d] + w2*s[tt+2][d] + w3*s[tt+3][d] + bias;
        float ob = w3*s[tt+3][d] + w2*s[tt+4][d] + w1*s[tt+5][d] + w0*s[tt+6][d] + bias;
        size_t m = (size_t)(b*LL + t0 + tt);
        float vf = silu_f(of), vb = silu_f(ob);
        __nv_bfloat16 h, l;
        split_bf16(vf, h, l); g_xsh[0][m*DI + d] = h; g_xsl[0][m*DI + d] = l;
        split_bf16(vb, h, l); g_xsh[1][m*DI + d] = h; g_xsl[1][m*DI + d] = l;
    }
}

// ---------------- chunked selective scan (dt_proj fused, f32x2-packed state) ----
// P3=false: pass1 -> h_end / P_end.
// P3=true : pass3 -> y' = y + D*u  (D-term folded; combine_G needs no xs)
#define SROW 48   // smem row stride in floats (44 padded to 48)

template<bool P3>
__global__ void __launch_bounds__(128)
scan_kernel(const float* __restrict__ A_log,
            const float* __restrict__ dtw,
            const float* __restrict__ dtbv,
            const float* __restrict__ Dv)
{
    __shared__ __align__(16) float sdbl[2][SW][SROW];

    int d  = blockIdx.x * 128 + threadIdx.x;
    int c  = blockIdx.y;
    int rb = blockIdx.z;
    int r  = rb >> 2, b = rb & 3;
    int tid = threadIdx.x;

    const int NSEG = P3 ? 11 : 7;          // 16B chunks per row staged
    const float* dblp = g_dbl[r];
    u32 sb = (u32)__cvta_generic_to_shared(&sdbl[0][0][0]);

    auto issue_win = [&](int w) {
        int nch = SW * NSEG;
        u32 dst0 = sb + (u32)(w & 1) * (SW*SROW*4);
        for (int q = tid; q < nch; q += 128) {
            int j = q / NSEG, seg = q % NSEG;
            int tau = c*LC + w*SW + j;
            int pos = r ? (LL - 1 - tau) : tau;
            size_t m = (size_t)b*LL + pos;
            cpa16(dst0 + (u32)(j*SROW + seg*4)*4, dblp + m*NDBL + seg*4);
        }
        cp_commit();
    };

    float A2[DS], wdt[DTR];
    bool structured = true;
    #pragma unroll
    for (int sIdx = 0; sIdx < DS; sIdx++)
        A2[sIdx] = -__expf(A_log[d*DS + sIdx]) * LOG2E;
    #pragma unroll
    for (int sIdx = 1; sIdx < DS; sIdx++)
        structured &= fabsf(A2[sIdx] - (sIdx+1)*A2[0]) <= 1e-4f*fabsf(A2[sIdx]);
    #pragma unroll
    for (int j = 0; j < DTR; j++) wdt[j] = dtw[d*DTR + j];
    float dtb = dtbv[d];
    float Dval = P3 ? Dv[d] : 0.f;

    u64 wdt2[6];
    #pragma unroll
    for (int k = 0; k < 6; k++) wdt2[k] = pk2(wdt[2*k], wdt[2*k+1]);

    size_t base = (((size_t)rb*NC + c)*DI + d)*DS;
    u64 hp[DS/2];
    #pragma unroll
    for (int k = 0; k < DS/2; k++) {
        if (P3) {
            float2 hv = *(const float2*)&g_hstart[base + 2*k];
            hp[k] = pk2(hv.x, hv.y);
        } else {
            hp[k] = 0ull;
        }
    }

    const __nv_bfloat16* xshp = g_xsh[r];
    const __nv_bfloat16* xslp = g_xsl[r];
    float* yp = g_y[r];
    float S = 0.f;

    issue_win(0);
    if (NW > 1) issue_win(1);

    for (int w = 0; w < NW; w++) {
        if (w + 1 < NW) cp_wait1(); else cp_wait0();
        __syncthreads();
        const float (*row)[SROW] = sdbl[w & 1];

        #pragma unroll 4
        for (int j = 0; j < SW; j++) {
            int tau = c*LC + w*SW + j;
            int pos = r ? (LL - 1 - tau) : tau;
            size_t m = (size_t)b*LL + pos;

            // dt dot (packed: 6 fma2 + horizontal add)
            u64 acc2 = 0ull;
            #pragma unroll
            for (int k = 0; k < 6; k++) {
                u64 iv = *(const u64*)&row[j][2*k];
                acc2 = fma2_(iv, wdt2[k], acc2);
            }
            float alo, ahi; upk2(alo, ahi, acc2);
            float dt = sp_f(dtb + alo + ahi);

            float u  = b2f(xshp[m*DI + d]) + b2f(xslp[m*DI + d]);
            float dtx = dt * u;
            u64 dtx2 = pk2(dtx, dtx);

            float y = 0.f;
            if (structured) {
                float e1 = ex2(dt * A2[0]);
                float ee = e1 * e1;
                u64 eep = pk2(ee, ee);
                u64 ap  = pk2(e1, ee);
                u64 y2  = 0ull;
                #pragma unroll
                for (int k = 0; k < DS/2; k++) {
                    u64 Bp = *(const u64*)&row[j][DTR + 2*k];
                    hp[k] = fma2_(ap, hp[k], mul2_(dtx2, Bp));
                    if (P3) {
                        u64 Cp = *(const u64*)&row[j][DTR + DS + 2*k];
                        y2 = fma2_(hp[k], Cp, y2);
                    }
                    if (k < DS/2 - 1) ap = mul2_(ap, eep);
                }
                if (P3) { float yl, yh; upk2(yl, yh, y2); y = yl + yh; }
            } else {
                #pragma unroll
                for (int k = 0; k < DS/2; k++) {
                    float h0, h1; upk2(h0, h1, hp[k]);
                    float a0 = ex2(dt * A2[2*k]);
                    float a1 = ex2(dt * A2[2*k+1]);
                    float B0 = row[j][DTR + 2*k], B1 = row[j][DTR + 2*k+1];
                    h0 = fmaf(a0, h0, dtx * B0);
                    h1 = fmaf(a1, h1, dtx * B1);
                    if (P3) {
                        y = fmaf(h0, row[j][DTR + DS + 2*k], y);
                        y = fmaf(h1, row[j][DTR + DS + 2*k+1], y);
                    }
                    hp[k] = pk2(h0, h1);
                }
            }
            if (P3) {
                y = fmaf(u, Dval, y);       // fold D*u here; combine_G skips xs
                yp[m*DI + d] = y;
            } else {
                S += dt;
            }
        }
        __syncthreads();
        if (w + 2 < NW) issue_win(w + 2);
    }

    if (!P3) {
        #pragma unroll
        for (int k = 0; k < DS/2; k++) {
            float h0, h1; upk2(h0, h1, hp[k]);
            float2 hv; hv.x = h0; hv.y = h1;
            *(float2*)&g_hend[base + 2*k] = hv;
            float2 pv;
            pv.x = ex2(A2[2*k]   * S);
            pv.y = ex2(A2[2*k+1] * S);
            *(float2*)&g_pend[base + 2*k] = pv;
        }
    }
}

__global__ void scan_combine()
{
    int g = blockIdx.x * 256 + threadIdx.x;
    if (g >= 2*BB*DI*DS) return;
    int sd = g % (DI*DS);
    int rb = g / (DI*DS);
    float carry = 0.f;
    for (int c = 0; c < NC; c++) {
        size_t idx = ((size_t)rb*NC + c)*(DI*DS) + sd;
        g_hstart[idx] = carry;
        carry = g_pend[idx]*carry + g_hend[idx];
    }
}

// ---------------- fused gate -> bf16 hi/lo (no xs needed; 2 elems/thread) -------
__global__ void combine_G(const float* __restrict__ Dv)
{
    size_t g2 = (size_t)blockIdx.x * 256 + threadIdx.x;
    if (g2 >= (size_t)MM*DI/2) return;
    int d2 = (int)(g2 % (DI/2));
    size_t m = g2 / (DI/2);
    int d = 2*d2;
    size_t gi = m*DI + d;

    float2 z  = *(const float2*)&g_xz[m*768 + DI + d];
    float2 y0 = *(const float2*)&g_y[0][gi];
    float2 y1 = *(const float2*)&g_y[1][gi];

    float v0 = silu_f(z.x) * (y0.x + y1.x);
    float v1 = silu_f(z.y) * (y0.y + y1.y);
    __nv_bfloat16 h0, l0, h1, l1;
    split_bf16(v0, h0, l0); split_bf16(v1, h1, l1);
    *(__nv_bfloat162*)&g_Gh[gi] = mk2(h0, h1);
    *(__nv_bfloat162*)&g_Gl[gi] = mk2(l0, l1);
}

// ---------------- launch ----------------
static void* sym_addr(const void* sym) {
    void* p = nullptr;
    cudaGetSymbolAddress(&p, sym);
    return p;
}

extern "C" void kernel_launch(void* const* d_in, const int* in_sizes, int n_in,
                              void* d_out, int out_size)
{
    const float* x          = (const float*)d_in[0];
    const float* ln_w       = (const float*)d_in[1];
    const float* ln_b       = (const float*)d_in[2];
    const float* in_proj_w  = (const float*)d_in[3];
    const float* conv_w     = (const float*)d_in[4];
    const float* conv_b     = (const float*)d_in[5];
    const float* x_proj_w   = (const float*)d_in[6];
    const float* dt_proj_w  = (const float*)d_in[7];
    const float* dt_proj_b  = (const float*)d_in[8];
    const float* A_log      = (const float*)d_in[9];
    const float* D_vec      = (const float*)d_in[10];
    const float* out_proj_w = (const float*)d_in[11];
    float* out = (float*)d_out;

    float* p_xz  = (float*)sym_addr(g_xz);
    float* p_dbl = (float*)sym_addr(g_dbl);
    __nv_bfloat16* p_xnh = (__nv_bfloat16*)sym_addr(g_xnh);
    __nv_bfloat16* p_xnl = (__nv_bfloat16*)sym_addr(g_xnl);
    __nv_bfloat16* p_xsh = (__nv_bfloat16*)sym_addr(g_xsh);
    __nv_bfloat16* p_xsl = (__nv_bfloat16*)sym_addr(g_xsl);
    __nv_bfloat16* p_Gh  = (__nv_bfloat16*)sym_addr(g_Gh);
    __nv_bfloat16* p_Gl  = (__nv_bfloat16*)sym_addr(g_Gl);
    __nv_bfloat16* p_wih = (__nv_bfloat16*)sym_addr(g_wih);
    __nv_bfloat16* p_wil = (__nv_bfloat16*)sym_addr(g_wil);
    __nv_bfloat16* p_wxh = (__nv_bfloat16*)sym_addr(g_wxh);
    __nv_bfloat16* p_wxl = (__nv_bfloat16*)sym_addr(g_wxl);
    __nv_bfloat16* p_woh = (__nv_bfloat16*)sym_addr(g_woh);
    __nv_bfloat16* p_wol = (__nv_bfloat16*)sym_addr(g_wol);

    cudaFuncSetAttribute((const void*)gemm_tc_store,
                         cudaFuncAttributeMaxDynamicSharedMemorySize, SMEM_TC);
    cudaFuncSetAttribute((const void*)gemm_tc_out,
                         cudaFuncAttributeMaxDynamicSharedMemorySize, SMEM_TC);

    // 1) LayerNorm -> bf16 hi/lo
    ln_kernel<<<dim3(LL/32, BB), dim3(32, 8)>>>(x, ln_w, ln_b);

    // 1b) weight conversion
    cvt_weights<<<256, 256>>>(in_proj_w, x_proj_w, out_proj_w);

    // 2) in_proj: xz[M,768] = xn @ Wi^T  (tensor cores)
    gemm_tc_store<<<dim3(768/128, MM/128, 1), 256, SMEM_TC>>>(
        p_xnh, p_xnl, p_wih, p_wil, p_xz, CC, 768, 768, 0, 0);

    // 3) conv + silu (both directions) -> bf16 hi/lo
    conv_silu_kernel<<<dim3(LL/16, BB), DI>>>(conv_w, conv_b);

    // 4) x_proj both dirs: dbl[M,44] = xs @ Wx^T  (tensor cores)
    gemm_tc_store<<<dim3(1, MM/128, 2), 256, SMEM_TC>>>(
        p_xsh, p_xsl, p_wxh, p_wxl, p_dbl, DI, NDBL, NDBL,
        (size_t)MM*DI, (size_t)MM*NDBL);

    // 5-8) chunked selective scan (r9 config, D*u folded into pass3 y)
    scan_kernel<false><<<dim3(DI/128, NC, 2*BB), 128>>>(A_log, dt_proj_w, dt_proj_b, D_vec);
    scan_combine<<<dim3((2*BB*DI*DS + 255)/256), 256>>>();
    scan_kernel<true><<<dim3(DI/128, NC, 2*BB), 128>>>(A_log, dt_proj_w, dt_proj_b, D_vec);

    // 9) fused gate -> bf16 hi/lo (xs-free, vectorized)
    combine_G<<<dim3((MM*DI/2 + 255)/256), 256>>>(D_vec);

    // 10) out_proj (tensor cores) with transposed store to (B,C,H,W)
    gemm_tc_out<<<dim3(2, MM/128, 1), 256, SMEM_TC>>>(
        p_Gh, p_Gl, p_woh, p_wol, DI, CC, out);
}

// round 14
// speedup vs baseline: 1.3510x; 1.1225x over previous
#include <cuda_runtime.h>
#include <cuda_bf16.h>
#include <cstdint>
#include <math.h>

typedef unsigned int u32;
typedef unsigned long long u64;

// ---------------- problem constants ----------------
#define BB   4
#define CC   192
#define HH   64
#define WW   64
#define LL   (HH*WW)          // 4096
#define MM   (BB*LL)          // 16384
#define DI   384
#define DS   16
#define DTR  12
#define NDBL 44               // DTR + 2*DS
#define NC   32               // scan chunks
#define LC   (LL/NC)          // 128
#define SW   16               // scan smem window (timesteps)
#define NW   (LC/SW)          // 8 windows
#define LOG2E 1.4426950408889634f
#define LN2   0.6931471805599453f

// ---------------- scratch (device globals: allocation-free) ----------------
__device__ __align__(128) float g_xz [(size_t)MM*768];
__device__ __align__(128) float g_dbl[2][(size_t)MM*NDBL];
__device__ __align__(128) float g_y  [2][(size_t)MM*DI];
__device__ float g_hend  [2*BB*NC*DI*DS];
__device__ float g_pend  [2*BB*NC*DI*DS];
__device__ float g_hstart[2*BB*NC*DI*DS];

// bf16 hi/lo pairs for tensor-core GEMMs (k-contiguous natural layouts)
__device__ __align__(128) __nv_bfloat16 g_xnh[(size_t)MM*CC];
__device__ __align__(128) __nv_bfloat16 g_xnl[(size_t)MM*CC];
__device__ __align__(128) __nv_bfloat16 g_xsh[2][(size_t)MM*DI];
__device__ __align__(128) __nv_bfloat16 g_xsl[2][(size_t)MM*DI];
__device__ __align__(128) __nv_bfloat16 g_Gh [(size_t)MM*DI];
__device__ __align__(128) __nv_bfloat16 g_Gl [(size_t)MM*DI];
__device__ __align__(128) __nv_bfloat16 g_wih[768*CC];
__device__ __align__(128) __nv_bfloat16 g_wil[768*CC];
__device__ __align__(128) __nv_bfloat16 g_wxh[128*DI];   // x_proj W padded 44->128 rows
__device__ __align__(128) __nv_bfloat16 g_wxl[128*DI];
__device__ __align__(128) __nv_bfloat16 g_woh[256*DI];   // out_proj W padded 192->256 rows
__device__ __align__(128) __nv_bfloat16 g_wol[256*DI];

__device__ __forceinline__ float ex2(float x){
    float r; asm("ex2.approx.ftz.f32 %0, %1;" : "=f"(r) : "f"(x)); return r;
}
__device__ __forceinline__ float silu_f(float x){
    return x / (1.f + __expf(-x));
}
__device__ __forceinline__ float sp_f(float v){   // softplus
    if (v > 15.f) return v;
    float e = ex2(v * LOG2E);
    return __log2f(1.f + e) * LN2;
}
__device__ __forceinline__ void split_bf16(float v, __nv_bfloat16& h, __nv_bfloat16& l){
    h = __float2bfloat16(v);
    l = __float2bfloat16(v - __bfloat162float(h));
}
__device__ __forceinline__ float b2f(__nv_bfloat16 v){ return __bfloat162float(v); }
__device__ __forceinline__ __nv_bfloat162 mk2(__nv_bfloat16 x, __nv_bfloat16 y){
    __nv_bfloat162 t; t.x = x; t.y = y; return t;
}

// ---------------- packed f32x2 helpers (sm_103a FFMA2 via PTX) ----------------
__device__ __forceinline__ u64 pk2(float lo, float hi){
    u64 d; asm("mov.b64 %0, {%1,%2};" : "=l"(d) : "f"(lo), "f"(hi)); return d;
}
__device__ __forceinline__ void upk2(float& lo, float& hi, u64 v){
    asm("mov.b64 {%0,%1}, %2;" : "=f"(lo), "=f"(hi) : "l"(v));
}
__device__ __forceinline__ u64 fma2_(u64 a, u64 b, u64 c){
    u64 d; asm("fma.rn.f32x2 %0, %1, %2, %3;" : "=l"(d) : "l"(a), "l"(b), "l"(c)); return d;
}
__device__ __forceinline__ u64 mul2_(u64 a, u64 b){
    u64 d; asm("mul.rn.f32x2 %0, %1, %2;" : "=l"(d) : "l"(a), "l"(b)); return d;
}

// ---------------- PTX helpers ----------------
__device__ __forceinline__ void cpa16(u32 dst, const void* src){
    asm volatile("cp.async.ca.shared.global [%0], [%1], 16;" :: "r"(dst), "l"(src));
}
__device__ __forceinline__ void cp_commit(){
    asm volatile("cp.async.commit_group;");
}
__device__ __forceinline__ void cp_wait1(){
    asm volatile("cp.async.wait_group 1;");
}
__device__ __forceinline__ void cp_wait0(){
    asm volatile("cp.async.wait_group 0;");
}
__device__ __forceinline__ void ldsm4(u32& x0, u32& x1, u32& x2, u32& x3, u32 addr){
    asm volatile("ldmatrix.sync.aligned.m8n8.x4.shared.b16 {%0,%1,%2,%3}, [%4];"
                 : "=r"(x0), "=r"(x1), "=r"(x2), "=r"(x3) : "r"(addr));
}
__device__ __forceinline__ void mma16816(float& d0, float& d1, float& d2, float& d3,
                                         u32 a0, u32 a1, u32 a2, u32 a3,
                                         u32 v0, u32 v1){
    asm volatile("mma.sync.aligned.m16n8k16.row.col.f32.bf16.bf16.f32 "
                 "{%0,%1,%2,%3},{%4,%5,%6,%7},{%8,%9},{%0,%1,%2,%3};"
                 : "+f"(d0), "+f"(d1), "+f"(d2), "+f"(d3)
                 : "r"(a0), "r"(a1), "r"(a2), "r"(a3), "r"(v0), "r"(v1));
}

// ---------------- 1) LayerNorm over channels -> bf16 hi/lo ----------------
__global__ void ln_kernel(const float* __restrict__ x,
                          const float* __restrict__ w,
                          const float* __restrict__ bsh)
{
    int b = blockIdx.y, p0 = blockIdx.x * 32;
    int tx = threadIdx.x, ty = threadIdx.y;
    __shared__ float sx[CC][33];
    __shared__ float red[2][8][32];
    __shared__ float smu[32], srs[32];

    float s1 = 0.f, s2 = 0.f;
    for (int c = ty; c < CC; c += 8) {
        float v = x[((size_t)(b*CC + c))*LL + p0 + tx];
        sx[c][tx] = v; s1 += v; s2 += v*v;
    }
    red[0][ty][tx] = s1; red[1][ty][tx] = s2;
    __syncthreads();
    if (ty == 0) {
        float a = 0.f, q = 0.f;
        #pragma unroll
        for (int j = 0; j < 8; j++){ a += red[0][j][tx]; q += red[1][j][tx]; }
        float mu = a / CC;
        float var = q / CC - mu*mu;
        smu[tx] = mu; srs[tx] = rsqrtf(var + 1e-5f);
    }
    __syncthreads();
    int tid = ty*32 + tx;
    for (int e = tid; e < 32*CC; e += 256) {
        int pp = e / CC, cc = e % CC;
        float v = (sx[cc][pp] - smu[pp]) * srs[pp] * w[cc] + bsh[cc];
        size_t idx = ((size_t)(b*LL + p0 + pp))*CC + cc;
        __nv_bfloat16 h, l; split_bf16(v, h, l);
        g_xnh[idx] = h; g_xnl[idx] = l;
    }
}

// ---------------- weight conversion (hi/lo split + zero padding) ----------------
__global__ void cvt_weights(const float* __restrict__ wi,
                            const float* __restrict__ wx,
                            const float* __restrict__ wo)
{
    int stride = gridDim.x * blockDim.x;
    int t = blockIdx.x * blockDim.x + threadIdx.x;
    for (int e = t; e < 768*CC; e += stride) {
        __nv_bfloat16 h, l; split_bf16(wi[e], h, l);
        g_wih[e] = h; g_wil[e] = l;
    }
    for (int e = t; e < 128*DI; e += stride) {
        int n = e / DI, k = e % DI;
        float v = (n < NDBL) ? wx[n*DI + k] : 0.f;
        __nv_bfloat16 h, l; split_bf16(v, h, l);
        g_wxh[e] = h; g_wxl[e] = l;
    }
    for (int e = t; e < 256*DI; e += stride) {
        int n = e / DI, k = e % DI;
        float v = (n < CC) ? wo[n*DI + k] : 0.f;
        __nv_bfloat16 h, l; split_bf16(v, h, l);
        g_woh[e] = h; g_wol[e] = l;
    }
}

// ---------------- tensor-core GEMM mainloop (shared by both kernels) ----------
#define ROWB   80
#define OFF_AH 0
#define OFF_AL (128*ROWB)
#define OFF_BH (2*128*ROWB)
#define OFF_BL (3*128*ROWB)
#define STAGEB (4*128*ROWB)
#define SMEM_TC (2*STAGEB)

__device__ __forceinline__ void tc_mainloop(
    const __nv_bfloat16* Ahp, const __nv_bfloat16* Alp,
    const __nv_bfloat16* Bhp, const __nv_bfloat16* Blp,
    int K, int m0, int n0, char* smem, float acc[2][8][4])
{
    u32 sbase = (u32)__cvta_generic_to_shared(smem);
    int tid = threadIdx.x;
    int lane = tid & 31, wid = tid >> 5;
    int wm = wid & 3, wn = wid >> 2;

    int r0c = tid >> 2, c0c = tid & 3;
    int r1c = (tid + 256) >> 2, c1c = (tid + 256) & 3;
    int NIT = K / 32;

    for (int pre = 0; pre < 2 && pre < NIT; pre++) {
        int k0 = pre * 32;
        u32 st = sbase + (u32)(pre & 1) * STAGEB;
        cpa16(st + OFF_AH + r0c*ROWB + c0c*16, Ahp + (size_t)(m0 + r0c)*K + k0 + c0c*8);
        cpa16(st + OFF_AH + r1c*ROWB + c1c*16, Ahp + (size_t)(m0 + r1c)*K + k0 + c1c*8);
        cpa16(st + OFF_AL + r0c*ROWB + c0c*16, Alp + (size_t)(m0 + r0c)*K + k0 + c0c*8);
        cpa16(st + OFF_AL + r1c*ROWB + c1c*16, Alp + (size_t)(m0 + r1c)*K + k0 + c1c*8);
        cpa16(st + OFF_BH + r0c*ROWB + c0c*16, Bhp + (size_t)(n0 + r0c)*K + k0 + c0c*8);
        cpa16(st + OFF_BH + r1c*ROWB + c1c*16, Bhp + (size_t)(n0 + r1c)*K + k0 + c1c*8);
        cpa16(st + OFF_BL + r0c*ROWB + c0c*16, Blp + (size_t)(n0 + r0c)*K + k0 + c0c*8);
        cpa16(st + OFF_BL + r1c*ROWB + c1c*16, Blp + (size_t)(n0 + r1c)*K + k0 + c1c*8);
        cp_commit();
    }

    for (int it = 0; it < NIT; it++) {
        cp_wait1();
        __syncthreads();

        u32 st = sbase + (u32)(it & 1) * STAGEB;
        #pragma unroll
        for (int ks = 0; ks < 2; ks++) {
            u32 fah0[4], fah1[4], fal0[4], fal1[4];
            {
                u32 adr0 = st + OFF_AH + (u32)((wm*32 + (lane & 15))*ROWB
                         + ks*32 + (lane >> 4)*16);
                u32 adr1 = adr0 + 16*ROWB;
                ldsm4(fah0[0], fah0[1], fah0[2], fah0[3], adr0);
                ldsm4(fal0[0], fal0[1], fal0[2], fal0[3], adr0 + (OFF_AL - OFF_AH));
                ldsm4(fah1[0], fah1[1], fah1[2], fah1[3], adr1);
                ldsm4(fal1[0], fal1[1], fal1[2], fal1[3], adr1 + (OFF_AL - OFF_AH));
            }
            #pragma unroll
            for (int j = 0; j < 4; j++) {
                u32 fbh[4], fbl[4];
                u32 bdr = st + OFF_BH + (u32)((wn*64 + j*16 + (lane & 15))*ROWB
                        + ks*32 + (lane >> 4)*16);
                ldsm4(fbh[0], fbh[1], fbh[2], fbh[3], bdr);
                ldsm4(fbl[0], fbl[1], fbl[2], fbl[3], bdr + (OFF_BL - OFF_BH));

                mma16816(acc[0][2*j][0], acc[0][2*j][1], acc[0][2*j][2], acc[0][2*j][3],
                         fah0[0], fah0[1], fah0[2], fah0[3], fbh[0], fbh[2]);
                mma16816(acc[0][2*j][0], acc[0][2*j][1], acc[0][2*j][2], acc[0][2*j][3],
                         fah0[0], fah0[1], fah0[2], fah0[3], fbl[0], fbl[2]);
                mma16816(acc[0][2*j][0], acc[0][2*j][1], acc[0][2*j][2], acc[0][2*j][3],
                         fal0[0], fal0[1], fal0[2], fal0[3], fbh[0], fbh[2]);
                mma16816(acc[0][2*j+1][0], acc[0][2*j+1][1], acc[0][2*j+1][2], acc[0][2*j+1][3],
                         fah0[0], fah0[1], fah0[2], fah0[3], fbh[1], fbh[3]);
                mma16816(acc[0][2*j+1][0], acc[0][2*j+1][1], acc[0][2*j+1][2], acc[0][2*j+1][3],
                         fah0[0], fah0[1], fah0[2], fah0[3], fbl[1], fbl[3]);
                mma16816(acc[0][2*j+1][0], acc[0][2*j+1][1], acc[0][2*j+1][2], acc[0][2*j+1][3],
                         fal0[0], fal0[1], fal0[2], fal0[3], fbh[1], fbh[3]);

                mma16816(acc[1][2*j][0], acc[1][2*j][1], acc[1][2*j][2], acc[1][2*j][3],
                         fah1[0], fah1[1], fah1[2], fah1[3], fbh[0], fbh[2]);
                mma16816(acc[1][2*j][0], acc[1][2*j][1], acc[1][2*j][2], acc[1][2*j][3],
                         fah1[0], fah1[1], fah1[2], fah1[3], fbl[0], fbl[2]);
                mma16816(acc[1][2*j][0], acc[1][2*j][1], acc[1][2*j][2], acc[1][2*j][3],
                         fal1[0], fal1[1], fal1[2], fal1[3], fbh[0], fbh[2]);
                mma16816(acc[1][2*j+1][0], acc[1][2*j+1][1], acc[1][2*j+1][2], acc[1][2*j+1][3],
                         fah1[0], fah1[1], fah1[2], fah1[3], fbh[1], fbh[3]);
                mma16816(acc[1][2*j+1][0], acc[1][2*j+1][1], acc[1][2*j+1][2], acc[1][2*j+1][3],
                         fah1[0], fah1[1], fah1[2], fah1[3], fbl[1], fbl[3]);
                mma16816(acc[1][2*j+1][0], acc[1][2*j+1][1], acc[1][2*j+1][2], acc[1][2*j+1][3],
                         fal1[0], fal1[1], fal1[2], fal1[3], fbh[1], fbh[3]);
            }
        }
        __syncthreads();
        if (it + 2 < NIT) {
            int k0 = (it + 2) * 32;
            u32 st2 = sbase + (u32)((it + 2) & 1) * STAGEB;
            cpa16(st2 + OFF_AH + r0c*ROWB + c0c*16, Ahp + (size_t)(m0 + r0c)*K + k0 + c0c*8);
            cpa16(st2 + OFF_AH + r1c*ROWB + c1c*16, Ahp + (size_t)(m0 + r1c)*K + k0 + c1c*8);
            cpa16(st2 + OFF_AL + r0c*ROWB + c0c*16, Alp + (size_t)(m0 + r0c)*K + k0 + c0c*8);
            cpa16(st2 + OFF_AL + r1c*ROWB + c1c*16, Alp + (size_t)(m0 + r1c)*K + k0 + c1c*8);
            cpa16(st2 + OFF_BH + r0c*ROWB + c0c*16, Bhp + (size_t)(n0 + r0c)*K + k0 + c0c*8);
            cpa16(st2 + OFF_BH + r1c*ROWB + c1c*16, Bhp + (size_t)(n0 + r1c)*K + k0 + c1c*8);
            cpa16(st2 + OFF_BL + r0c*ROWB + c0c*16, Blp + (size_t)(n0 + r0c)*K + k0 + c0c*8);
            cpa16(st2 + OFF_BL + r1c*ROWB + c1c*16, Blp + (size_t)(n0 + r1c)*K + k0 + c1c*8);
        }
        cp_commit();
    }
}

// plain fp32 store (z-batched)
__global__ void __launch_bounds__(256)
gemm_tc_store(const __nv_bfloat16* __restrict__ Ahp, const __nv_bfloat16* __restrict__ Alp,
              const __nv_bfloat16* __restrict__ Bhp, const __nv_bfloat16* __restrict__ Blp,
              float* __restrict__ C, int K, int N, int ldc, size_t aZ, size_t cZ)
{
    extern __shared__ char smem[];
    float acc[2][8][4];
    #pragma unroll
    for (int i = 0; i < 2; i++)
        #pragma unroll
        for (int j = 0; j < 8; j++)
            #pragma unroll
            for (int q = 0; q < 4; q++) acc[i][j][q] = 0.f;

    int m0 = blockIdx.y*128, n0 = blockIdx.x*128;
    tc_mainloop(Ahp + (size_t)blockIdx.z*aZ, Alp + (size_t)blockIdx.z*aZ,
                Bhp, Blp, K, m0, n0, smem, acc);
    C += (size_t)blockIdx.z * cZ;

    int lane = threadIdx.x & 31, wid = threadIdx.x >> 5;
    int wm = wid & 3, wn = wid >> 2;
    int gp = lane >> 2, tg = lane & 3;
    #pragma unroll
    for (int mi = 0; mi < 2; mi++) {
        int row = m0 + wm*32 + mi*16 + gp;
        #pragma unroll
        for (int ni = 0; ni < 8; ni++) {
            int col = n0 + wn*64 + ni*8 + tg*2;
            if (col < N) {
                float2 v0; v0.x = acc[mi][ni][0]; v0.y = acc[mi][ni][1];
                float2 v1; v1.x = acc[mi][ni][2]; v1.y = acc[mi][ni][3];
                *(float2*)&C[(size_t)row*ldc + col]       = v0;
                *(float2*)&C[(size_t)(row + 8)*ldc + col] = v1;
            }
        }
    }
}

// transposed store to d_out laid out (B, C, L)
__global__ void __launch_bounds__(256)
gemm_tc_out(const __nv_bfloat16* __restrict__ Ahp, const __nv_bfloat16* __restrict__ Alp,
            const __nv_bfloat16* __restrict__ Bhp, const __nv_bfloat16* __restrict__ Blp,
            int K, int N, float* __restrict__ dout)
{
    extern __shared__ char smem[];
    float acc[2][8][4];
    #pragma unroll
    for (int i = 0; i < 2; i++)
        #pragma unroll
        for (int j = 0; j < 8; j++)
            #pragma unroll
            for (int q = 0; q < 4; q++) acc[i][j][q] = 0.f;

    int m0 = blockIdx.y*128, n0 = blockIdx.x*128;
    tc_mainloop(Ahp, Alp, Bhp, Blp, K, m0, n0, smem, acc);

    cp_wait0();
    __syncthreads();
    float* so = (float*)smem;   // [128][132]
    int lane = threadIdx.x & 31, wid = threadIdx.x >> 5;
    int wm = wid & 3, wn = wid >> 2;
    int gp = lane >> 2, tg = lane & 3;
    #pragma unroll
    for (int mi = 0; mi < 2; mi++) {
        int ml = wm*32 + mi*16 + gp;
        #pragma unroll
        for (int ni = 0; ni < 8; ni++) {
            int nl = wn*64 + ni*8 + tg*2;
            so[(size_t)nl*132 + ml]         = acc[mi][ni][0];
            so[(size_t)(nl+1)*132 + ml]     = acc[mi][ni][1];
            so[(size_t)nl*132 + ml + 8]     = acc[mi][ni][2];
            so[(size_t)(nl+1)*132 + ml + 8] = acc[mi][ni][3];
        }
    }
    __syncthreads();
    int b = m0 >> 12, p0 = m0 & (LL - 1);
    for (int e = threadIdx.x; e < 128*128; e += 256) {
        int nl = e >> 7, mlp = e & 127;
        int n = n0 + nl;
        if (n < N)
            dout[((size_t)(b*CC + n))*LL + p0 + mlp] = so[(size_t)nl*132 + mlp];
    }
}

// ---------------- depthwise causal conv (both directions) + silu -> bf16 hi/lo ----
__global__ void conv_silu_kernel(const float* __restrict__ cw, const float* __restrict__ cb)
{
    __shared__ float s[16 + 6][DI];
    int b = blockIdx.y, t0 = blockIdx.x * 16, d = threadIdx.x;

    #pragma unroll
    for (int j = 0; j < 22; j++) {
        int t = t0 - 3 + j;
        float v = 0.f;
        if (t >= 0 && t < LL) v = g_xz[((size_t)(b*LL + t))*768 + d];
        s[j][d] = v;
    }
    __syncthreads();
    float w0 = cw[d*4+0], w1 = cw[d*4+1], w2 = cw[d*4+2], w3 = cw[d*4+3];
    float bias = cb[d];
    #pragma unroll
    for (int tt = 0; tt < 16; tt++) {
        float of = w0*s[tt][d] + w1*s[tt+1][d] + w2*s[tt+2][d] + w3*s[tt+3][d] + bias;
        float ob = w3*s[tt+3][d] + w2*s[tt+4][d] + w1*s[tt+5][d] + w0*s[tt+6][d] + bias;
        size_t m = (size_t)(b*LL + t0 + tt);
        float vf = silu_f(of), vb = silu_f(ob);
        __nv_bfloat16 h, l;
        split_bf16(vf, h, l); g_xsh[0][m*DI + d] = h; g_xsl[0][m*DI + d] = l;
        split_bf16(vb, h, l); g_xsh[1][m*DI + d] = h; g_xsl[1][m*DI + d] = l;
    }
}

// ---------------- chunked selective scan (dt_proj fused, f32x2, xs prefetched) --
// P3=false: pass1 -> h_end / P_end.
// P3=true : pass3 -> y' = y + D*u
#define SROW 48   // smem row stride in floats (44 padded to 48)

template<bool P3>
__global__ void __launch_bounds__(128)
scan_kernel(const float* __restrict__ A_log,
            const float* __restrict__ dtw,
            const float* __restrict__ dtbv,
            const float* __restrict__ Dv)
{
    __shared__ __align__(16) float sdbl[2][SW][SROW];
    __shared__ __align__(16) __nv_bfloat16 sxh[2][SW][128];
    __shared__ __align__(16) __nv_bfloat16 sxl[2][SW][128];

    int d  = blockIdx.x * 128 + threadIdx.x;
    int d0 = blockIdx.x * 128;
    int c  = blockIdx.y;
    int rb = blockIdx.z;
    int r  = rb >> 2, b = rb & 3;
    int tid = threadIdx.x;

    const int NSEG = P3 ? 11 : 7;          // dbl 16B chunks per row staged
    const float* dblp = g_dbl[r];
    const __nv_bfloat16* xshp = g_xsh[r];
    const __nv_bfloat16* xslp = g_xsl[r];
    u32 sb  = (u32)__cvta_generic_to_shared(&sdbl[0][0][0]);
    u32 sxh_b = (u32)__cvta_generic_to_shared(&sxh[0][0][0]);
    u32 sxl_b = (u32)__cvta_generic_to_shared(&sxl[0][0][0]);

    auto issue_win = [&](int w) {
        u32 buf = (u32)(w & 1);
        // dbl rows
        int nch = SW * NSEG;
        u32 dst0 = sb + buf * (SW*SROW*4);
        for (int q = tid; q < nch; q += 128) {
            int j = q / NSEG, seg = q % NSEG;
            int tau = c*LC + w*SW + j;
            int pos = r ? (LL - 1 - tau) : tau;
            size_t m = (size_t)b*LL + pos;
            cpa16(dst0 + (u32)(j*SROW + seg*4)*4, dblp + m*NDBL + seg*4);
        }
        // xs rows (hi+lo): 16 segs of 8 bf16 per row per array
        u32 xh0 = sxh_b + buf * (SW*128*2);
        u32 xl0 = sxl_b + buf * (SW*128*2);
        for (int q = tid; q < SW*16; q += 128) {
            int j = q >> 4, seg = q & 15;
            int tau = c*LC + w*SW + j;
            int pos = r ? (LL - 1 - tau) : tau;
            size_t m = (size_t)b*LL + pos;
            const __nv_bfloat16* srch = xshp + m*DI + d0 + seg*8;
            const __nv_bfloat16* srcl = xslp + m*DI + d0 + seg*8;
            cpa16(xh0 + (u32)(j*128 + seg*8)*2, srch);
            cpa16(xl0 + (u32)(j*128 + seg*8)*2, srcl);
        }
        cp_commit();
    };

    float A2[DS], wdt[DTR];
    bool structured = true;
    #pragma unroll
    for (int sIdx = 0; sIdx < DS; sIdx++)
        A2[sIdx] = -__expf(A_log[d*DS + sIdx]) * LOG2E;
    #pragma unroll
    for (int sIdx = 1; sIdx < DS; sIdx++)
        structured &= fabsf(A2[sIdx] - (sIdx+1)*A2[0]) <= 1e-4f*fabsf(A2[sIdx]);
    #pragma unroll
    for (int j = 0; j < DTR; j++) wdt[j] = dtw[d*DTR + j];
    float dtb = dtbv[d];
    float Dval = P3 ? Dv[d] : 0.f;

    u64 wdt2[6];
    #pragma unroll
    for (int k = 0; k < 6; k++) wdt2[k] = pk2(wdt[2*k], wdt[2*k+1]);

    size_t base = (((size_t)rb*NC + c)*DI + d)*DS;
    u64 hp[DS/2];
    #pragma unroll
    for (int k = 0; k < DS/2; k++) {
        if (P3) {
            float2 hv = *(const float2*)&g_hstart[base + 2*k];
            hp[k] = pk2(hv.x, hv.y);
        } else {
            hp[k] = 0ull;
        }
    }

    float* yp = g_y[r];
    float S = 0.f;

    issue_win(0);
    if (NW > 1) issue_win(1);

    for (int w = 0; w < NW; w++) {
        if (w + 1 < NW) cp_wait1(); else cp_wait0();
        __syncthreads();
        int buf = w & 1;
        const float (*row)[SROW] = sdbl[buf];

        #pragma unroll 4
        for (int j = 0; j < SW; j++) {
            int tau = c*LC + w*SW + j;
            int pos = r ? (LL - 1 - tau) : tau;
            size_t m = (size_t)b*LL + pos;

            // dt dot (packed: 6 fma2 + horizontal add)
            u64 acc2 = 0ull;
            #pragma unroll
            for (int k = 0; k < 6; k++) {
                u64 iv = *(const u64*)&row[j][2*k];
                acc2 = fma2_(iv, wdt2[k], acc2);
            }
            float alo, ahi; upk2(alo, ahi, acc2);
            float dt = sp_f(dtb + alo + ahi);

            float u  = b2f(sxh[buf][j][tid]) + b2f(sxl[buf][j][tid]);
            float dtx = dt * u;
            u64 dtx2 = pk2(dtx, dtx);

            float y = 0.f;
            if (structured) {
                float e1 = ex2(dt * A2[0]);
                float ee = e1 * e1;
                u64 eep = pk2(ee, ee);
                u64 ap  = pk2(e1, ee);
                u64 y2  = 0ull;
                #pragma unroll
                for (int k = 0; k < DS/2; k++) {
                    u64 Bp = *(const u64*)&row[j][DTR + 2*k];
                    hp[k] = fma2_(ap, hp[k], mul2_(dtx2, Bp));
                    if (P3) {
                        u64 Cp = *(const u64*)&row[j][DTR + DS + 2*k];
                        y2 = fma2_(hp[k], Cp, y2);
                    }
                    if (k < DS/2 - 1) ap = mul2_(ap, eep);
                }
                if (P3) { float yl, yh; upk2(yl, yh, y2); y = yl + yh; }
            } else {
                #pragma unroll
                for (int k = 0; k < DS/2; k++) {
                    float h0, h1; upk2(h0, h1, hp[k]);
                    float a0 = ex2(dt * A2[2*k]);
                    float a1 = ex2(dt * A2[2*k+1]);
                    float B0 = row[j][DTR + 2*k], B1 = row[j][DTR + 2*k+1];
                    h0 = fmaf(a0, h0, dtx * B0);
                    h1 = fmaf(a1, h1, dtx * B1);
                    if (P3) {
                        y = fmaf(h0, row[j][DTR + DS + 2*k], y);
                        y = fmaf(h1, row[j][DTR + DS + 2*k+1], y);
                    }
                    hp[k] = pk2(h0, h1);
                }
            }
            if (P3) {
                y = fmaf(u, Dval, y);
                yp[m*DI + d] = y;
            } else {
                S += dt;
            }
        }
        __syncthreads();
        if (w + 2 < NW) issue_win(w + 2);
    }

    if (!P3) {
        #pragma unroll
        for (int k = 0; k < DS/2; k++) {
            float h0, h1; upk2(h0, h1, hp[k]);
            float2 hv; hv.x = h0; hv.y = h1;
            *(float2*)&g_hend[base + 2*k] = hv;
            float2 pv;
            pv.x = ex2(A2[2*k]   * S);
            pv.y = ex2(A2[2*k+1] * S);
            *(float2*)&g_pend[base + 2*k] = pv;
        }
    }
}

__global__ void scan_combine()
{
    int g = blockIdx.x * 256 + threadIdx.x;
    if (g >= 2*BB*DI*DS) return;
    int sd = g % (DI*DS);
    int rb = g / (DI*DS);
    float carry = 0.f;
    for (int c = 0; c < NC; c++) {
        size_t idx = ((size_t)rb*NC + c)*(DI*DS) + sd;
        g_hstart[idx] = carry;
        carry = g_pend[idx]*carry + g_hend[idx];
    }
}

// ---------------- fused gate -> bf16 hi/lo (no xs needed; 2 elems/thread) -------
__global__ void combine_G(const float* __restrict__ Dv)
{
    size_t g2 = (size_t)blockIdx.x * 256 + threadIdx.x;
    if (g2 >= (size_t)MM*DI/2) return;
    int d2 = (int)(g2 % (DI/2));
    size_t m = g2 / (DI/2);
    int d = 2*d2;
    size_t gi = m*DI + d;

    float2 z  = *(const float2*)&g_xz[m*768 + DI + d];
    float2 y0 = *(const float2*)&g_y[0][gi];
    float2 y1 = *(const float2*)&g_y[1][gi];

    float v0 = silu_f(z.x) * (y0.x + y1.x);
    float v1 = silu_f(z.y) * (y0.y + y1.y);
    __nv_bfloat16 h0, l0, h1, l1;
    split_bf16(v0, h0, l0); split_bf16(v1, h1, l1);
    *(__nv_bfloat162*)&g_Gh[gi] = mk2(h0, h1);
    *(__nv_bfloat162*)&g_Gl[gi] = mk2(l0, l1);
}

// ---------------- launch ----------------
static void* sym_addr(const void* sym) {
    void* p = nullptr;
    cudaGetSymbolAddress(&p, sym);
    return p;
}

extern "C" void kernel_launch(void* const* d_in, const int* in_sizes, int n_in,
                              void* d_out, int out_size)
{
    const float* x          = (const float*)d_in[0];
    const float* ln_w       = (const float*)d_in[1];
    const float* ln_b       = (const float*)d_in[2];
    const float* in_proj_w  = (const float*)d_in[3];
    const float* conv_w     = (const float*)d_in[4];
    const float* conv_b     = (const float*)d_in[5];
    const float* x_proj_w   = (const float*)d_in[6];
    const float* dt_proj_w  = (const float*)d_in[7];
    const float* dt_proj_b  = (const float*)d_in[8];
    const float* A_log      = (const float*)d_in[9];
    const float* D_vec      = (const float*)d_in[10];
    const float* out_proj_w = (const float*)d_in[11];
    float* out = (float*)d_out;

    float* p_xz  = (float*)sym_addr(g_xz);
    float* p_dbl = (float*)sym_addr(g_dbl);
    __nv_bfloat16* p_xnh = (__nv_bfloat16*)sym_addr(g_xnh);
    __nv_bfloat16* p_xnl = (__nv_bfloat16*)sym_addr(g_xnl);
    __nv_bfloat16* p_xsh = (__nv_bfloat16*)sym_addr(g_xsh);
    __nv_bfloat16* p_xsl = (__nv_bfloat16*)sym_addr(g_xsl);
    __nv_bfloat16* p_Gh  = (__nv_bfloat16*)sym_addr(g_Gh);
    __nv_bfloat16* p_Gl  = (__nv_bfloat16*)sym_addr(g_Gl);
    __nv_bfloat16* p_wih = (__nv_bfloat16*)sym_addr(g_wih);
    __nv_bfloat16* p_wil = (__nv_bfloat16*)sym_addr(g_wil);
    __nv_bfloat16* p_wxh = (__nv_bfloat16*)sym_addr(g_wxh);
    __nv_bfloat16* p_wxl = (__nv_bfloat16*)sym_addr(g_wxl);
    __nv_bfloat16* p_woh = (__nv_bfloat16*)sym_addr(g_woh);
    __nv_bfloat16* p_wol = (__nv_bfloat16*)sym_addr(g_wol);

    cudaFuncSetAttribute((const void*)gemm_tc_store,
                         cudaFuncAttributeMaxDynamicSharedMemorySize, SMEM_TC);
    cudaFuncSetAttribute((const void*)gemm_tc_out,
                         cudaFuncAttributeMaxDynamicSharedMemorySize, SMEM_TC);

    // 1) LayerNorm -> bf16 hi/lo
    ln_kernel<<<dim3(LL/32, BB), dim3(32, 8)>>>(x, ln_w, ln_b);

    // 1b) weight conversion
    cvt_weights<<<256, 256>>>(in_proj_w, x_proj_w, out_proj_w);

    // 2) in_proj: xz[M,768] = xn @ Wi^T  (tensor cores)
    gemm_tc_store<<<dim3(768/128, MM/128, 1), 256, SMEM_TC>>>(
        p_xnh, p_xnl, p_wih, p_wil, p_xz, CC, 768, 768, 0, 0);

    // 3) conv + silu (both directions) -> bf16 hi/lo
    conv_silu_kernel<<<dim3(LL/16, BB), DI>>>(conv_w, conv_b);

    // 4) x_proj both dirs: dbl[M,44] = xs @ Wx^T  (tensor cores)
    gemm_tc_store<<<dim3(1, MM/128, 2), 256, SMEM_TC>>>(
        p_xsh, p_xsl, p_wxh, p_wxl, p_dbl, DI, NDBL, NDBL,
        (size_t)MM*DI, (size_t)MM*NDBL);

    // 5-8) chunked selective scan (xs prefetched via cp.async alongside dbl)
    scan_kernel<false><<<dim3(DI/128, NC, 2*BB), 128>>>(A_log, dt_proj_w, dt_proj_b, D_vec);
    scan_combine<<<dim3((2*BB*DI*DS + 255)/256), 256>>>();
    scan_kernel<true><<<dim3(DI/128, NC, 2*BB), 128>>>(A_log, dt_proj_w, dt_proj_b, D_vec);

    // 9) fused gate -> bf16 hi/lo (xs-free, vectorized)
    combine_G<<<dim3((MM*DI/2 + 255)/256), 256>>>(D_vec);

    // 10) out_proj (tensor cores) with transposed store to (B,C,H,W)
    gemm_tc_out<<<dim3(2, MM/128, 1), 256, SMEM_TC>>>(
        p_Gh, p_Gl, p_woh, p_wol, DI, CC, out);
}

// round 15
// speedup vs baseline: 1.3638x; 1.0095x over previous
#include <cuda_runtime.h>
#include <cuda_bf16.h>
#include <cstdint>
#include <math.h>

typedef unsigned int u32;
typedef unsigned long long u64;

// ---------------- problem constants ----------------
#define BB   4
#define CC   192
#define HH   64
#define WW   64
#define LL   (HH*WW)          // 4096
#define MM   (BB*LL)          // 16384
#define DI   384
#define DS   16
#define DTR  12
#define NDBL 44               // DTR + 2*DS
#define NC   32               // scan chunks
#define LC   (LL/NC)          // 128
#define SW   16               // scan smem window (timesteps)
#define NW   (LC/SW)          // 8 windows
#define LOG2E 1.4426950408889634f
#define LN2   0.6931471805599453f

// ---------------- scratch (device globals: allocation-free) ----------------
__device__ __align__(128) float g_xz [(size_t)MM*768];
__device__ __align__(128) float g_dbl[2][(size_t)MM*NDBL];
__device__ __align__(128) float g_y  [2][(size_t)MM*DI];
__device__ float g_hend  [2*BB*NC*DI*DS];
__device__ float g_pend  [2*BB*NC*DI*DS];
__device__ float g_hstart[2*BB*NC*DI*DS];

// bf16 hi/lo pairs for tensor-core GEMMs (k-contiguous natural layouts)
__device__ __align__(128) __nv_bfloat16 g_xnh[(size_t)MM*CC];
__device__ __align__(128) __nv_bfloat16 g_xnl[(size_t)MM*CC];
__device__ __align__(128) __nv_bfloat16 g_xsh[2][(size_t)MM*DI];
__device__ __align__(128) __nv_bfloat16 g_xsl[2][(size_t)MM*DI];
__device__ __align__(128) __nv_bfloat16 g_Gh [(size_t)MM*DI];
__device__ __align__(128) __nv_bfloat16 g_Gl [(size_t)MM*DI];
__device__ __align__(128) __nv_bfloat16 g_wih[768*CC];
__device__ __align__(128) __nv_bfloat16 g_wil[768*CC];
__device__ __align__(128) __nv_bfloat16 g_wxh[128*DI];   // x_proj W padded 44->128 rows
__device__ __align__(128) __nv_bfloat16 g_wxl[128*DI];
__device__ __align__(128) __nv_bfloat16 g_woh[256*DI];   // out_proj W padded 192->256 rows
__device__ __align__(128) __nv_bfloat16 g_wol[256*DI];

__device__ __forceinline__ float ex2(float x){
    float r; asm("ex2.approx.ftz.f32 %0, %1;" : "=f"(r) : "f"(x)); return r;
}
__device__ __forceinline__ float silu_f(float x){
    return x / (1.f + __expf(-x));
}
__device__ __forceinline__ float sp_f(float v){   // softplus
    if (v > 15.f) return v;
    float e = ex2(v * LOG2E);
    return __log2f(1.f + e) * LN2;
}
__device__ __forceinline__ void split_bf16(float v, __nv_bfloat16& h, __nv_bfloat16& l){
    h = __float2bfloat16(v);
    l = __float2bfloat16(v - __bfloat162float(h));
}
__device__ __forceinline__ float b2f(__nv_bfloat16 v){ return __bfloat162float(v); }
__device__ __forceinline__ __nv_bfloat162 mk2(__nv_bfloat16 x, __nv_bfloat16 y){
    __nv_bfloat162 t; t.x = x; t.y = y; return t;
}

// ---------------- packed f32x2 helpers (sm_103a FFMA2 via PTX) ----------------
__device__ __forceinline__ u64 pk2(float lo, float hi){
    u64 d; asm("mov.b64 %0, {%1,%2};" : "=l"(d) : "f"(lo), "f"(hi)); return d;
}
__device__ __forceinline__ void upk2(float& lo, float& hi, u64 v){
    asm("mov.b64 {%0,%1}, %2;" : "=f"(lo), "=f"(hi) : "l"(v));
}
__device__ __forceinline__ u64 fma2_(u64 a, u64 b, u64 c){
    u64 d; asm("fma.rn.f32x2 %0, %1, %2, %3;" : "=l"(d) : "l"(a), "l"(b), "l"(c)); return d;
}
__device__ __forceinline__ u64 mul2_(u64 a, u64 b){
    u64 d; asm("mul.rn.f32x2 %0, %1, %2;" : "=l"(d) : "l"(a), "l"(b)); return d;
}

// ---------------- PTX helpers ----------------
__device__ __forceinline__ void cpa16(u32 dst, const void* src){
    asm volatile("cp.async.ca.shared.global [%0], [%1], 16;" :: "r"(dst), "l"(src));
}
__device__ __forceinline__ void cp_commit(){
    asm volatile("cp.async.commit_group;");
}
__device__ __forceinline__ void cp_wait2(){
    asm volatile("cp.async.wait_group 2;");
}
__device__ __forceinline__ void cp_wait1(){
    asm volatile("cp.async.wait_group 1;");
}
__device__ __forceinline__ void cp_wait0(){
    asm volatile("cp.async.wait_group 0;");
}
__device__ __forceinline__ void ldsm4(u32& x0, u32& x1, u32& x2, u32& x3, u32 addr){
    asm volatile("ldmatrix.sync.aligned.m8n8.x4.shared.b16 {%0,%1,%2,%3}, [%4];"
                 : "=r"(x0), "=r"(x1), "=r"(x2), "=r"(x3) : "r"(addr));
}
__device__ __forceinline__ void mma16816(float& d0, float& d1, float& d2, float& d3,
                                         u32 a0, u32 a1, u32 a2, u32 a3,
                                         u32 v0, u32 v1){
    asm volatile("mma.sync.aligned.m16n8k16.row.col.f32.bf16.bf16.f32 "
                 "{%0,%1,%2,%3},{%4,%5,%6,%7},{%8,%9},{%0,%1,%2,%3};"
                 : "+f"(d0), "+f"(d1), "+f"(d2), "+f"(d3)
                 : "r"(a0), "r"(a1), "r"(a2), "r"(a3), "r"(v0), "r"(v1));
}

// ---------------- 1) LayerNorm over channels -> bf16 hi/lo (paired stores) ------
__global__ void ln_kernel(const float* __restrict__ x,
                          const float* __restrict__ w,
                          const float* __restrict__ bsh)
{
    int b = blockIdx.y, p0 = blockIdx.x * 32;
    int tx = threadIdx.x, ty = threadIdx.y;
    __shared__ float sx[CC][33];
    __shared__ float red[2][8][32];
    __shared__ float smu[32], srs[32];

    float s1 = 0.f, s2 = 0.f;
    for (int c = ty; c < CC; c += 8) {
        float v = x[((size_t)(b*CC + c))*LL + p0 + tx];
        sx[c][tx] = v; s1 += v; s2 += v*v;
    }
    red[0][ty][tx] = s1; red[1][ty][tx] = s2;
    __syncthreads();
    if (ty == 0) {
        float a = 0.f, q = 0.f;
        #pragma unroll
        for (int j = 0; j < 8; j++){ a += red[0][j][tx]; q += red[1][j][tx]; }
        float mu = a / CC;
        float var = q / CC - mu*mu;
        smu[tx] = mu; srs[tx] = rsqrtf(var + 1e-5f);
    }
    __syncthreads();
    int tid = ty*32 + tx;
    for (int e = tid; e < 32*(CC/2); e += 256) {
        int pp = e / (CC/2), cc2 = e % (CC/2);
        int cc = 2*cc2;
        float mu = smu[pp], rs = srs[pp];
        float v0 = (sx[cc][pp]   - mu) * rs * w[cc]   + bsh[cc];
        float v1 = (sx[cc+1][pp] - mu) * rs * w[cc+1] + bsh[cc+1];
        size_t idx = ((size_t)(b*LL + p0 + pp))*CC + cc;
        __nv_bfloat16 h0, l0, h1, l1;
        split_bf16(v0, h0, l0); split_bf16(v1, h1, l1);
        *(__nv_bfloat162*)&g_xnh[idx] = mk2(h0, h1);
        *(__nv_bfloat162*)&g_xnl[idx] = mk2(l0, l1);
    }
}

// ---------------- weight conversion (hi/lo split + zero padding) ----------------
__global__ void cvt_weights(const float* __restrict__ wi,
                            const float* __restrict__ wx,
                            const float* __restrict__ wo)
{
    int stride = gridDim.x * blockDim.x;
    int t = blockIdx.x * blockDim.x + threadIdx.x;
    for (int e = t; e < 768*CC; e += stride) {
        __nv_bfloat16 h, l; split_bf16(wi[e], h, l);
        g_wih[e] = h; g_wil[e] = l;
    }
    for (int e = t; e < 128*DI; e += stride) {
        int n = e / DI, k = e % DI;
        float v = (n < NDBL) ? wx[n*DI + k] : 0.f;
        __nv_bfloat16 h, l; split_bf16(v, h, l);
        g_wxh[e] = h; g_wxl[e] = l;
    }
    for (int e = t; e < 256*DI; e += stride) {
        int n = e / DI, k = e % DI;
        float v = (n < CC) ? wo[n*DI + k] : 0.f;
        __nv_bfloat16 h, l; split_bf16(v, h, l);
        g_woh[e] = h; g_wol[e] = l;
    }
}

// ---------------- tensor-core GEMM mainloop (shared by both kernels) ----------
#define ROWB   80
#define OFF_AH 0
#define OFF_AL (128*ROWB)
#define OFF_BH (2*128*ROWB)
#define OFF_BL (3*128*ROWB)
#define STAGEB (4*128*ROWB)
#define SMEM_TC (2*STAGEB)

__device__ __forceinline__ void tc_mainloop(
    const __nv_bfloat16* Ahp, const __nv_bfloat16* Alp,
    const __nv_bfloat16* Bhp, const __nv_bfloat16* Blp,
    int K, int m0, int n0, char* smem, float acc[2][8][4])
{
    u32 sbase = (u32)__cvta_generic_to_shared(smem);
    int tid = threadIdx.x;
    int lane = tid & 31, wid = tid >> 5;
    int wm = wid & 3, wn = wid >> 2;

    int r0c = tid >> 2, c0c = tid & 3;
    int r1c = (tid + 256) >> 2, c1c = (tid + 256) & 3;
    int NIT = K / 32;

    for (int pre = 0; pre < 2 && pre < NIT; pre++) {
        int k0 = pre * 32;
        u32 st = sbase + (u32)(pre & 1) * STAGEB;
        cpa16(st + OFF_AH + r0c*ROWB + c0c*16, Ahp + (size_t)(m0 + r0c)*K + k0 + c0c*8);
        cpa16(st + OFF_AH + r1c*ROWB + c1c*16, Ahp + (size_t)(m0 + r1c)*K + k0 + c1c*8);
        cpa16(st + OFF_AL + r0c*ROWB + c0c*16, Alp + (size_t)(m0 + r0c)*K + k0 + c0c*8);
        cpa16(st + OFF_AL + r1c*ROWB + c1c*16, Alp + (size_t)(m0 + r1c)*K + k0 + c1c*8);
        cpa16(st + OFF_BH + r0c*ROWB + c0c*16, Bhp + (size_t)(n0 + r0c)*K + k0 + c0c*8);
        cpa16(st + OFF_BH + r1c*ROWB + c1c*16, Bhp + (size_t)(n0 + r1c)*K + k0 + c1c*8);
        cpa16(st + OFF_BL + r0c*ROWB + c0c*16, Blp + (size_t)(n0 + r0c)*K + k0 + c0c*8);
        cpa16(st + OFF_BL + r1c*ROWB + c1c*16, Blp + (size_t)(n0 + r1c)*K + k0 + c1c*8);
        cp_commit();
    }

    for (int it = 0; it < NIT; it++) {
        cp_wait1();
        __syncthreads();

        u32 st = sbase + (u32)(it & 1) * STAGEB;
        #pragma unroll
        for (int ks = 0; ks < 2; ks++) {
            u32 fah0[4], fah1[4], fal0[4], fal1[4];
            {
                u32 adr0 = st + OFF_AH + (u32)((wm*32 + (lane & 15))*ROWB
                         + ks*32 + (lane >> 4)*16);
                u32 adr1 = adr0 + 16*ROWB;
                ldsm4(fah0[0], fah0[1], fah0[2], fah0[3], adr0);
                ldsm4(fal0[0], fal0[1], fal0[2], fal0[3], adr0 + (OFF_AL - OFF_AH));
                ldsm4(fah1[0], fah1[1], fah1[2], fah1[3], adr1);
                ldsm4(fal1[0], fal1[1], fal1[2], fal1[3], adr1 + (OFF_AL - OFF_AH));
            }
            #pragma unroll
            for (int j = 0; j < 4; j++) {
                u32 fbh[4], fbl[4];
                u32 bdr = st + OFF_BH + (u32)((wn*64 + j*16 + (lane & 15))*ROWB
                        + ks*32 + (lane >> 4)*16);
                ldsm4(fbh[0], fbh[1], fbh[2], fbh[3], bdr);
                ldsm4(fbl[0], fbl[1], fbl[2], fbl[3], bdr + (OFF_BL - OFF_BH));

                mma16816(acc[0][2*j][0], acc[0][2*j][1], acc[0][2*j][2], acc[0][2*j][3],
                         fah0[0], fah0[1], fah0[2], fah0[3], fbh[0], fbh[2]);
                mma16816(acc[0][2*j][0], acc[0][2*j][1], acc[0][2*j][2], acc[0][2*j][3],
                         fah0[0], fah0[1], fah0[2], fah0[3], fbl[0], fbl[2]);
                mma16816(acc[0][2*j][0], acc[0][2*j][1], acc[0][2*j][2], acc[0][2*j][3],
                         fal0[0], fal0[1], fal0[2], fal0[3], fbh[0], fbh[2]);
                mma16816(acc[0][2*j+1][0], acc[0][2*j+1][1], acc[0][2*j+1][2], acc[0][2*j+1][3],
                         fah0[0], fah0[1], fah0[2], fah0[3], fbh[1], fbh[3]);
                mma16816(acc[0][2*j+1][0], acc[0][2*j+1][1], acc[0][2*j+1][2], acc[0][2*j+1][3],
                         fah0[0], fah0[1], fah0[2], fah0[3], fbl[1], fbl[3]);
                mma16816(acc[0][2*j+1][0], acc[0][2*j+1][1], acc[0][2*j+1][2], acc[0][2*j+1][3],
                         fal0[0], fal0[1], fal0[2], fal0[3], fbh[1], fbh[3]);

                mma16816(acc[1][2*j][0], acc[1][2*j][1], acc[1][2*j][2], acc[1][2*j][3],
                         fah1[0], fah1[1], fah1[2], fah1[3], fbh[0], fbh[2]);
                mma16816(acc[1][2*j][0], acc[1][2*j][1], acc[1][2*j][2], acc[1][2*j][3],
                         fah1[0], fah1[1], fah1[2], fah1[3], fbl[0], fbl[2]);
                mma16816(acc[1][2*j][0], acc[1][2*j][1], acc[1][2*j][2], acc[1][2*j][3],
                         fal1[0], fal1[1], fal1[2], fal1[3], fbh[0], fbh[2]);
                mma16816(acc[1][2*j+1][0], acc[1][2*j+1][1], acc[1][2*j+1][2], acc[1][2*j+1][3],
                         fah1[0], fah1[1], fah1[2], fah1[3], fbh[1], fbh[3]);
                mma16816(acc[1][2*j+1][0], acc[1][2*j+1][1], acc[1][2*j+1][2], acc[1][2*j+1][3],
                         fah1[0], fah1[1], fah1[2], fah1[3], fbl[1], fbl[3]);
                mma16816(acc[1][2*j+1][0], acc[1][2*j+1][1], acc[1][2*j+1][2], acc[1][2*j+1][3],
                         fal1[0], fal1[1], fal1[2], fal1[3], fbh[1], fbh[3]);
            }
        }
        __syncthreads();
        if (it + 2 < NIT) {
            int k0 = (it + 2) * 32;
            u32 st2 = sbase + (u32)((it + 2) & 1) * STAGEB;
            cpa16(st2 + OFF_AH + r0c*ROWB + c0c*16, Ahp + (size_t)(m0 + r0c)*K + k0 + c0c*8);
            cpa16(st2 + OFF_AH + r1c*ROWB + c1c*16, Ahp + (size_t)(m0 + r1c)*K + k0 + c1c*8);
            cpa16(st2 + OFF_AL + r0c*ROWB + c0c*16, Alp + (size_t)(m0 + r0c)*K + k0 + c0c*8);
            cpa16(st2 + OFF_AL + r1c*ROWB + c1c*16, Alp + (size_t)(m0 + r1c)*K + k0 + c1c*8);
            cpa16(st2 + OFF_BH + r0c*ROWB + c0c*16, Bhp + (size_t)(n0 + r0c)*K + k0 + c0c*8);
            cpa16(st2 + OFF_BH + r1c*ROWB + c1c*16, Bhp + (size_t)(n0 + r1c)*K + k0 + c1c*8);
            cpa16(st2 + OFF_BL + r0c*ROWB + c0c*16, Blp + (size_t)(n0 + r0c)*K + k0 + c0c*8);
            cpa16(st2 + OFF_BL + r1c*ROWB + c1c*16, Blp + (size_t)(n0 + r1c)*K + k0 + c1c*8);
        }
        cp_commit();
    }
}

// plain fp32 store (z-batched)
__global__ void __launch_bounds__(256)
gemm_tc_store(const __nv_bfloat16* __restrict__ Ahp, const __nv_bfloat16* __restrict__ Alp,
              const __nv_bfloat16* __restrict__ Bhp, const __nv_bfloat16* __restrict__ Blp,
              float* __restrict__ C, int K, int N, int ldc, size_t aZ, size_t cZ)
{
    extern __shared__ char smem[];
    float acc[2][8][4];
    #pragma unroll
    for (int i = 0; i < 2; i++)
        #pragma unroll
        for (int j = 0; j < 8; j++)
            #pragma unroll
            for (int q = 0; q < 4; q++) acc[i][j][q] = 0.f;

    int m0 = blockIdx.y*128, n0 = blockIdx.x*128;
    tc_mainloop(Ahp + (size_t)blockIdx.z*aZ, Alp + (size_t)blockIdx.z*aZ,
                Bhp, Blp, K, m0, n0, smem, acc);
    C += (size_t)blockIdx.z * cZ;

    int lane = threadIdx.x & 31, wid = threadIdx.x >> 5;
    int wm = wid & 3, wn = wid >> 2;
    int gp = lane >> 2, tg = lane & 3;
    #pragma unroll
    for (int mi = 0; mi < 2; mi++) {
        int row = m0 + wm*32 + mi*16 + gp;
        #pragma unroll
        for (int ni = 0; ni < 8; ni++) {
            int col = n0 + wn*64 + ni*8 + tg*2;
            if (col < N) {
                float2 v0; v0.x = acc[mi][ni][0]; v0.y = acc[mi][ni][1];
                float2 v1; v1.x = acc[mi][ni][2]; v1.y = acc[mi][ni][3];
                *(float2*)&C[(size_t)row*ldc + col]       = v0;
                *(float2*)&C[(size_t)(row + 8)*ldc + col] = v1;
            }
        }
    }
}

// transposed store to d_out laid out (B, C, L)
__global__ void __launch_bounds__(256)
gemm_tc_out(const __nv_bfloat16* __restrict__ Ahp, const __nv_bfloat16* __restrict__ Alp,
            const __nv_bfloat16* __restrict__ Bhp, const __nv_bfloat16* __restrict__ Blp,
            int K, int N, float* __restrict__ dout)
{
    extern __shared__ char smem[];
    float acc[2][8][4];
    #pragma unroll
    for (int i = 0; i < 2; i++)
        #pragma unroll
        for (int j = 0; j < 8; j++)
            #pragma unroll
            for (int q = 0; q < 4; q++) acc[i][j][q] = 0.f;

    int m0 = blockIdx.y*128, n0 = blockIdx.x*128;
    tc_mainloop(Ahp, Alp, Bhp, Blp, K, m0, n0, smem, acc);

    cp_wait0();
    __syncthreads();
    float* so = (float*)smem;   // [128][132]
    int lane = threadIdx.x & 31, wid = threadIdx.x >> 5;
    int wm = wid & 3, wn = wid >> 2;
    int gp = lane >> 2, tg = lane & 3;
    #pragma unroll
    for (int mi = 0; mi < 2; mi++) {
        int ml = wm*32 + mi*16 + gp;
        #pragma unroll
        for (int ni = 0; ni < 8; ni++) {
            int nl = wn*64 + ni*8 + tg*2;
            so[(size_t)nl*132 + ml]         = acc[mi][ni][0];
            so[(size_t)(nl+1)*132 + ml]     = acc[mi][ni][1];
            so[(size_t)nl*132 + ml + 8]     = acc[mi][ni][2];
            so[(size_t)(nl+1)*132 + ml + 8] = acc[mi][ni][3];
        }
    }
    __syncthreads();
    int b = m0 >> 12, p0 = m0 & (LL - 1);
    for (int e = threadIdx.x; e < 128*128; e += 256) {
        int nl = e >> 7, mlp = e & 127;
        int n = n0 + nl;
        if (n < N)
            dout[((size_t)(b*CC + n))*LL + p0 + mlp] = so[(size_t)nl*132 + mlp];
    }
}

// ---------------- depthwise causal conv (both directions) + silu -> bf16 hi/lo ----
__global__ void conv_silu_kernel(const float* __restrict__ cw, const float* __restrict__ cb)
{
    __shared__ float s[16 + 6][DI];
    int b = blockIdx.y, t0 = blockIdx.x * 16, d = threadIdx.x;

    #pragma unroll
    for (int j = 0; j < 22; j++) {
        int t = t0 - 3 + j;
        float v = 0.f;
        if (t >= 0 && t < LL) v = g_xz[((size_t)(b*LL + t))*768 + d];
        s[j][d] = v;
    }
    __syncthreads();
    float w0 = cw[d*4+0], w1 = cw[d*4+1], w2 = cw[d*4+2], w3 = cw[d*4+3];
    float bias = cb[d];
    #pragma unroll
    for (int tt = 0; tt < 16; tt++) {
        float of = w0*s[tt][d] + w1*s[tt+1][d] + w2*s[tt+2][d] + w3*s[tt+3][d] + bias;
        float ob = w3*s[tt+3][d] + w2*s[tt+4][d] + w1*s[tt+5][d] + w0*s[tt+6][d] + bias;
        size_t m = (size_t)(b*LL + t0 + tt);
        float vf = silu_f(of), vb = silu_f(ob);
        __nv_bfloat16 h, l;
        split_bf16(vf, h, l); g_xsh[0][m*DI + d] = h; g_xsl[0][m*DI + d] = l;
        split_bf16(vb, h, l); g_xsh[1][m*DI + d] = h; g_xsl[1][m*DI + d] = l;
    }
}

// ---------------- chunked selective scan (dt_proj fused, f32x2, 3-deep prefetch) --
// P3=false: pass1 -> h_end / P_end.
// P3=true : pass3 -> y' = y + D*u
#define SROW 48   // smem row stride in floats (44 padded to 48)
#define NBUF 3

template<bool P3>
__global__ void __launch_bounds__(128)
scan_kernel(const float* __restrict__ A_log,
            const float* __restrict__ dtw,
            const float* __restrict__ dtbv,
            const float* __restrict__ Dv)
{
    __shared__ __align__(16) float sdbl[NBUF][SW][SROW];
    __shared__ __align__(16) __nv_bfloat16 sxh[NBUF][SW][128];
    __shared__ __align__(16) __nv_bfloat16 sxl[NBUF][SW][128];

    int d  = blockIdx.x * 128 + threadIdx.x;
    int d0 = blockIdx.x * 128;
    int c  = blockIdx.y;
    int rb = blockIdx.z;
    int r  = rb >> 2, b = rb & 3;
    int tid = threadIdx.x;

    const int NSEG = P3 ? 11 : 7;          // dbl 16B chunks per row staged
    const float* dblp = g_dbl[r];
    const __nv_bfloat16* xshp = g_xsh[r];
    const __nv_bfloat16* xslp = g_xsl[r];
    u32 sb  = (u32)__cvta_generic_to_shared(&sdbl[0][0][0]);
    u32 sxh_b = (u32)__cvta_generic_to_shared(&sxh[0][0][0]);
    u32 sxl_b = (u32)__cvta_generic_to_shared(&sxl[0][0][0]);

    auto issue_win = [&](int w) {
        u32 buf = (u32)(w % NBUF);
        int nch = SW * NSEG;
        u32 dst0 = sb + buf * (SW*SROW*4);
        for (int q = tid; q < nch; q += 128) {
            int j = q / NSEG, seg = q % NSEG;
            int tau = c*LC + w*SW + j;
            int pos = r ? (LL - 1 - tau) : tau;
            size_t m = (size_t)b*LL + pos;
            cpa16(dst0 + (u32)(j*SROW + seg*4)*4, dblp + m*NDBL + seg*4);
        }
        u32 xh0 = sxh_b + buf * (SW*128*2);
        u32 xl0 = sxl_b + buf * (SW*128*2);
        for (int q = tid; q < SW*16; q += 128) {
            int j = q >> 4, seg = q & 15;
            int tau = c*LC + w*SW + j;
            int pos = r ? (LL - 1 - tau) : tau;
            size_t m = (size_t)b*LL + pos;
            cpa16(xh0 + (u32)(j*128 + seg*8)*2, xshp + m*DI + d0 + seg*8);
            cpa16(xl0 + (u32)(j*128 + seg*8)*2, xslp + m*DI + d0 + seg*8);
        }
        cp_commit();
    };

    float A2[DS], wdt[DTR];
    bool structured = true;
    #pragma unroll
    for (int sIdx = 0; sIdx < DS; sIdx++)
        A2[sIdx] = -__expf(A_log[d*DS + sIdx]) * LOG2E;
    #pragma unroll
    for (int sIdx = 1; sIdx < DS; sIdx++)
        structured &= fabsf(A2[sIdx] - (sIdx+1)*A2[0]) <= 1e-4f*fabsf(A2[sIdx]);
    #pragma unroll
    for (int j = 0; j < DTR; j++) wdt[j] = dtw[d*DTR + j];
    float dtb = dtbv[d];
    float Dval = P3 ? Dv[d] : 0.f;

    u64 wdt2[6];
    #pragma unroll
    for (int k = 0; k < 6; k++) wdt2[k] = pk2(wdt[2*k], wdt[2*k+1]);

    size_t base = (((size_t)rb*NC + c)*DI + d)*DS;
    u64 hp[DS/2];
    #pragma unroll
    for (int k = 0; k < DS/2; k++) {
        if (P3) {
            float2 hv = *(const float2*)&g_hstart[base + 2*k];
            hp[k] = pk2(hv.x, hv.y);
        } else {
            hp[k] = 0ull;
        }
    }

    float* yp = g_y[r];
    float S = 0.f;

    issue_win(0);
    if (NW > 1) issue_win(1);
    if (NW > 2) issue_win(2);

    for (int w = 0; w < NW; w++) {
        if (w + 3 <= NW - 1)      cp_wait2();
        else if (w + 2 <= NW - 1) cp_wait1();
        else                      cp_wait0();
        __syncthreads();
        int buf = w % NBUF;
        const float (*row)[SROW] = sdbl[buf];

        #pragma unroll 4
        for (int j = 0; j < SW; j++) {
            int tau = c*LC + w*SW + j;
            int pos = r ? (LL - 1 - tau) : tau;
            size_t m = (size_t)b*LL + pos;

            u64 acc2 = 0ull;
            #pragma unroll
            for (int k = 0; k < 6; k++) {
                u64 iv = *(const u64*)&row[j][2*k];
                acc2 = fma2_(iv, wdt2[k], acc2);
            }
            float alo, ahi; upk2(alo, ahi, acc2);
            float dt = sp_f(dtb + alo + ahi);

            float u  = b2f(sxh[buf][j][tid]) + b2f(sxl[buf][j][tid]);
            float dtx = dt * u;
            u64 dtx2 = pk2(dtx, dtx);

            float y = 0.f;
            if (structured) {
                float e1 = ex2(dt * A2[0]);
                float ee = e1 * e1;
                u64 eep = pk2(ee, ee);
                u64 ap  = pk2(e1, ee);
                u64 y2  = 0ull;
                #pragma unroll
                for (int k = 0; k < DS/2; k++) {
                    u64 Bp = *(const u64*)&row[j][DTR + 2*k];
                    hp[k] = fma2_(ap, hp[k], mul2_(dtx2, Bp));
                    if (P3) {
                        u64 Cp = *(const u64*)&row[j][DTR + DS + 2*k];
                        y2 = fma2_(hp[k], Cp, y2);
                    }
                    if (k < DS/2 - 1) ap = mul2_(ap, eep);
                }
                if (P3) { float yl, yh; upk2(yl, yh, y2); y = yl + yh; }
            } else {
                #pragma unroll
                for (int k = 0; k < DS/2; k++) {
                    float h0, h1; upk2(h0, h1, hp[k]);
                    float a0 = ex2(dt * A2[2*k]);
                    float a1 = ex2(dt * A2[2*k+1]);
                    float B0 = row[j][DTR + 2*k], B1 = row[j][DTR + 2*k+1];
                    h0 = fmaf(a0, h0, dtx * B0);
                    h1 = fmaf(a1, h1, dtx * B1);
                    if (P3) {
                        y = fmaf(h0, row[j][DTR + DS + 2*k], y);
                        y = fmaf(h1, row[j][DTR + DS + 2*k+1], y);
                    }
                    hp[k] = pk2(h0, h1);
                }
            }
            if (P3) {
                y = fmaf(u, Dval, y);
                yp[m*DI + d] = y;
            } else {
                S += dt;
            }
        }
        __syncthreads();
        if (w + NBUF < NW) issue_win(w + NBUF);
    }

    if (!P3) {
        #pragma unroll
        for (int k = 0; k < DS/2; k++) {
            float h0, h1; upk2(h0, h1, hp[k]);
            float2 hv; hv.x = h0; hv.y = h1;
            *(float2*)&g_hend[base + 2*k] = hv;
            float2 pv;
            pv.x = ex2(A2[2*k]   * S);
            pv.y = ex2(A2[2*k+1] * S);
            *(float2*)&g_pend[base + 2*k] = pv;
        }
    }
}

__global__ void scan_combine()
{
    int g = blockIdx.x * 256 + threadIdx.x;
    if (g >= 2*BB*DI*DS) return;
    int sd = g % (DI*DS);
    int rb = g / (DI*DS);
    float carry = 0.f;
    for (int c = 0; c < NC; c++) {
        size_t idx = ((size_t)rb*NC + c)*(DI*DS) + sd;
        g_hstart[idx] = carry;
        carry = g_pend[idx]*carry + g_hend[idx];
    }
}

// ---------------- fused gate -> bf16 hi/lo (xs-free; 4 elems/thread) ------------
__global__ void combine_G(const float* __restrict__ Dv)
{
    size_t g4 = (size_t)blockIdx.x * 256 + threadIdx.x;
    if (g4 >= (size_t)MM*DI/4) return;
    int d4 = (int)(g4 % (DI/4));
    size_t m = g4 / (DI/4);
    int d = 4*d4;
    size_t gi = m*DI + d;

    float4 z  = *(const float4*)&g_xz[m*768 + DI + d];
    float4 y0 = *(const float4*)&g_y[0][gi];
    float4 y1 = *(const float4*)&g_y[1][gi];

    float v0 = silu_f(z.x) * (y0.x + y1.x);
    float v1 = silu_f(z.y) * (y0.y + y1.y);
    float v2 = silu_f(z.z) * (y0.z + y1.z);
    float v3 = silu_f(z.w) * (y0.w + y1.w);
    __nv_bfloat16 h0, l0, h1, l1, h2, l2, h3, l3;
    split_bf16(v0, h0, l0); split_bf16(v1, h1, l1);
    split_bf16(v2, h2, l2); split_bf16(v3, h3, l3);
    __nv_bfloat162 ph0 = mk2(h0, h1), ph1 = mk2(h2, h3);
    __nv_bfloat162 pl0 = mk2(l0, l1), pl1 = mk2(l2, l3);
    *(u64*)&g_Gh[gi] = ((u64)*(u32*)&ph1 << 32) | *(u32*)&ph0;
    *(u64*)&g_Gl[gi] = ((u64)*(u32*)&pl1 << 32) | *(u32*)&pl0;
}

// ---------------- launch ----------------
static void* sym_addr(const void* sym) {
    void* p = nullptr;
    cudaGetSymbolAddress(&p, sym);
    return p;
}

extern "C" void kernel_launch(void* const* d_in, const int* in_sizes, int n_in,
                              void* d_out, int out_size)
{
    const float* x          = (const float*)d_in[0];
    const float* ln_w       = (const float*)d_in[1];
    const float* ln_b       = (const float*)d_in[2];
    const float* in_proj_w  = (const float*)d_in[3];
    const float* conv_w     = (const float*)d_in[4];
    const float* conv_b     = (const float*)d_in[5];
    const float* x_proj_w   = (const float*)d_in[6];
    const float* dt_proj_w  = (const float*)d_in[7];
    const float* dt_proj_b  = (const float*)d_in[8];
    const float* A_log      = (const float*)d_in[9];
    const float* D_vec      = (const float*)d_in[10];
    const float* out_proj_w = (const float*)d_in[11];
    float* out = (float*)d_out;

    float* p_xz  = (float*)sym_addr(g_xz);
    float* p_dbl = (float*)sym_addr(g_dbl);
    __nv_bfloat16* p_xnh = (__nv_bfloat16*)sym_addr(g_xnh);
    __nv_bfloat16* p_xnl = (__nv_bfloat16*)sym_addr(g_xnl);
    __nv_bfloat16* p_xsh = (__nv_bfloat16*)sym_addr(g_xsh);
    __nv_bfloat16* p_xsl = (__nv_bfloat16*)sym_addr(g_xsl);
    __nv_bfloat16* p_Gh  = (__nv_bfloat16*)sym_addr(g_Gh);
    __nv_bfloat16* p_Gl  = (__nv_bfloat16*)sym_addr(g_Gl);
    __nv_bfloat16* p_wih = (__nv_bfloat16*)sym_addr(g_wih);
    __nv_bfloat16* p_wil = (__nv_bfloat16*)sym_addr(g_wil);
    __nv_bfloat16* p_wxh = (__nv_bfloat16*)sym_addr(g_wxh);
    __nv_bfloat16* p_wxl = (__nv_bfloat16*)sym_addr(g_wxl);
    __nv_bfloat16* p_woh = (__nv_bfloat16*)sym_addr(g_woh);
    __nv_bfloat16* p_wol = (__nv_bfloat16*)sym_addr(g_wol);

    cudaFuncSetAttribute((const void*)gemm_tc_store,
                         cudaFuncAttributeMaxDynamicSharedMemorySize, SMEM_TC);
    cudaFuncSetAttribute((const void*)gemm_tc_out,
                         cudaFuncAttributeMaxDynamicSharedMemorySize, SMEM_TC);

    // 1) LayerNorm -> bf16 hi/lo
    ln_kernel<<<dim3(LL/32, BB), dim3(32, 8)>>>(x, ln_w, ln_b);

    // 1b) weight conversion
    cvt_weights<<<256, 256>>>(in_proj_w, x_proj_w, out_proj_w);

    // 2) in_proj: xz[M,768] = xn @ Wi^T  (tensor cores)
    gemm_tc_store<<<dim3(768/128, MM/128, 1), 256, SMEM_TC>>>(
        p_xnh, p_xnl, p_wih, p_wil, p_xz, CC, 768, 768, 0, 0);

    // 3) conv + silu (both directions) -> bf16 hi/lo
    conv_silu_kernel<<<dim3(LL/16, BB), DI>>>(conv_w, conv_b);

    // 4) x_proj both dirs: dbl[M,44] = xs @ Wx^T  (tensor cores)
    gemm_tc_store<<<dim3(1, MM/128, 2), 256, SMEM_TC>>>(
        p_xsh, p_xsl, p_wxh, p_wxl, p_dbl, DI, NDBL, NDBL,
        (size_t)MM*DI, (size_t)MM*NDBL);

    // 5-8) chunked selective scan (3-deep cp.async prefetch of dbl + xs)
    scan_kernel<false><<<dim3(DI/128, NC, 2*BB), 128>>>(A_log, dt_proj_w, dt_proj_b, D_vec);
    scan_combine<<<dim3((2*BB*DI*DS + 255)/256), 256>>>();
    scan_kernel<true><<<dim3(DI/128, NC, 2*BB), 128>>>(A_log, dt_proj_w, dt_proj_b, D_vec);

    // 9) fused gate -> bf16 hi/lo (xs-free, 4-wide vectorized)
    combine_G<<<dim3((MM*DI/4 + 255)/256), 256>>>(D_vec);

    // 10) out_proj (tensor cores) with transposed store to (B,C,H,W)
    gemm_tc_out<<<dim3(2, MM/128, 1), 256, SMEM_TC>>>(
        p_Gh, p_Gl, p_woh, p_wol, DI, CC, out);
}

// round 16
// speedup vs baseline: 1.4190x; 1.0405x over previous
#include <cuda_runtime.h>
#include <cuda_bf16.h>
#include <cstdint>
#include <math.h>

typedef unsigned int u32;
typedef unsigned long long u64;

// ---------------- problem constants ----------------
#define BB   4
#define CC   192
#define HH   64
#define WW   64
#define LL   (HH*WW)          // 4096
#define MM   (BB*LL)          // 16384
#define DI   384
#define DS   16
#define DTR  12
#define NDBL 44               // DTR + 2*DS
#define NC   32               // scan chunks
#define LC   (LL/NC)          // 128
#define SW   16               // scan smem window (timesteps)
#define NW   (LC/SW)          // 8 windows
#define LOG2E 1.4426950408889634f
#define LN2   0.6931471805599453f

// ---------------- scratch (device globals: allocation-free) ----------------
__device__ __align__(128) float g_xz [(size_t)MM*768];
__device__ __align__(128) float g_dbl[2][(size_t)MM*NDBL];
__device__ __align__(128) float g_y  [2][(size_t)MM*DI];
__device__ float g_hend  [2*BB*NC*DI*DS];
__device__ float g_pend  [2*BB*NC*DI*DS];
__device__ float g_hstart[2*BB*NC*DI*DS];

// bf16 hi/lo pairs for tensor-core GEMMs (k-contiguous natural layouts)
__device__ __align__(128) __nv_bfloat16 g_xnh[(size_t)MM*CC];
__device__ __align__(128) __nv_bfloat16 g_xnl[(size_t)MM*CC];
__device__ __align__(128) __nv_bfloat16 g_xsh[2][(size_t)MM*DI];
__device__ __align__(128) __nv_bfloat16 g_xsl[2][(size_t)MM*DI];
__device__ __align__(128) __nv_bfloat16 g_Gh [(size_t)MM*DI];
__device__ __align__(128) __nv_bfloat16 g_Gl [(size_t)MM*DI];
__device__ __align__(128) __nv_bfloat16 g_wih[768*CC];
__device__ __align__(128) __nv_bfloat16 g_wil[768*CC];
__device__ __align__(128) __nv_bfloat16 g_wxh[64*DI];    // x_proj W padded 44->64 rows
__device__ __align__(128) __nv_bfloat16 g_wxl[64*DI];
__device__ __align__(128) __nv_bfloat16 g_woh[256*DI];   // out_proj W padded 192->256 rows
__device__ __align__(128) __nv_bfloat16 g_wol[256*DI];

__device__ __forceinline__ float ex2(float x){
    float r; asm("ex2.approx.ftz.f32 %0, %1;" : "=f"(r) : "f"(x)); return r;
}
__device__ __forceinline__ float silu_f(float x){
    return x / (1.f + __expf(-x));
}
__device__ __forceinline__ float sp_f(float v){   // softplus
    if (v > 15.f) return v;
    float e = ex2(v * LOG2E);
    return __log2f(1.f + e) * LN2;
}
__device__ __forceinline__ void split_bf16(float v, __nv_bfloat16& h, __nv_bfloat16& l){
    h = __float2bfloat16(v);
    l = __float2bfloat16(v - __bfloat162float(h));
}
__device__ __forceinline__ float b2f(__nv_bfloat16 v){ return __bfloat162float(v); }
__device__ __forceinline__ __nv_bfloat162 mk2(__nv_bfloat16 x, __nv_bfloat16 y){
    __nv_bfloat162 t; t.x = x; t.y = y; return t;
}

// ---------------- packed f32x2 helpers (sm_103a FFMA2 via PTX) ----------------
__device__ __forceinline__ u64 pk2(float lo, float hi){
    u64 d; asm("mov.b64 %0, {%1,%2};" : "=l"(d) : "f"(lo), "f"(hi)); return d;
}
__device__ __forceinline__ void upk2(float& lo, float& hi, u64 v){
    asm("mov.b64 {%0,%1}, %2;" : "=f"(lo), "=f"(hi) : "l"(v));
}
__device__ __forceinline__ u64 fma2_(u64 a, u64 b, u64 c){
    u64 d; asm("fma.rn.f32x2 %0, %1, %2, %3;" : "=l"(d) : "l"(a), "l"(b), "l"(c)); return d;
}
__device__ __forceinline__ u64 mul2_(u64 a, u64 b){
    u64 d; asm("mul.rn.f32x2 %0, %1, %2;" : "=l"(d) : "l"(a), "l"(b)); return d;
}

// ---------------- PTX helpers ----------------
__device__ __forceinline__ void cpa16(u32 dst, const void* src){
    asm volatile("cp.async.ca.shared.global [%0], [%1], 16;" :: "r"(dst), "l"(src));
}
__device__ __forceinline__ void cp_commit(){
    asm volatile("cp.async.commit_group;");
}
__device__ __forceinline__ void cp_wait2(){
    asm volatile("cp.async.wait_group 2;");
}
__device__ __forceinline__ void cp_wait1(){
    asm volatile("cp.async.wait_group 1;");
}
__device__ __forceinline__ void cp_wait0(){
    asm volatile("cp.async.wait_group 0;");
}
__device__ __forceinline__ void ldsm4(u32& x0, u32& x1, u32& x2, u32& x3, u32 addr){
    asm volatile("ldmatrix.sync.aligned.m8n8.x4.shared.b16 {%0,%1,%2,%3}, [%4];"
                 : "=r"(x0), "=r"(x1), "=r"(x2), "=r"(x3) : "r"(addr));
}
__device__ __forceinline__ void mma16816(float& d0, float& d1, float& d2, float& d3,
                                         u32 a0, u32 a1, u32 a2, u32 a3,
                                         u32 v0, u32 v1){
    asm volatile("mma.sync.aligned.m16n8k16.row.col.f32.bf16.bf16.f32 "
                 "{%0,%1,%2,%3},{%4,%5,%6,%7},{%8,%9},{%0,%1,%2,%3};"
                 : "+f"(d0), "+f"(d1), "+f"(d2), "+f"(d3)
                 : "r"(a0), "r"(a1), "r"(a2), "r"(a3), "r"(v0), "r"(v1));
}

// ---------------- 1) LayerNorm over channels -> bf16 hi/lo (paired stores) ------
__global__ void ln_kernel(const float* __restrict__ x,
                          const float* __restrict__ w,
                          const float* __restrict__ bsh)
{
    int b = blockIdx.y, p0 = blockIdx.x * 32;
    int tx = threadIdx.x, ty = threadIdx.y;
    __shared__ float sx[CC][33];
    __shared__ float red[2][8][32];
    __shared__ float smu[32], srs[32];

    float s1 = 0.f, s2 = 0.f;
    for (int c = ty; c < CC; c += 8) {
        float v = x[((size_t)(b*CC + c))*LL + p0 + tx];
        sx[c][tx] = v; s1 += v; s2 += v*v;
    }
    red[0][ty][tx] = s1; red[1][ty][tx] = s2;
    __syncthreads();
    if (ty == 0) {
        float a = 0.f, q = 0.f;
        #pragma unroll
        for (int j = 0; j < 8; j++){ a += red[0][j][tx]; q += red[1][j][tx]; }
        float mu = a / CC;
        float var = q / CC - mu*mu;
        smu[tx] = mu; srs[tx] = rsqrtf(var + 1e-5f);
    }
    __syncthreads();
    int tid = ty*32 + tx;
    for (int e = tid; e < 32*(CC/2); e += 256) {
        int pp = e / (CC/2), cc2 = e % (CC/2);
        int cc = 2*cc2;
        float mu = smu[pp], rs = srs[pp];
        float v0 = (sx[cc][pp]   - mu) * rs * w[cc]   + bsh[cc];
        float v1 = (sx[cc+1][pp] - mu) * rs * w[cc+1] + bsh[cc+1];
        size_t idx = ((size_t)(b*LL + p0 + pp))*CC + cc;
        __nv_bfloat16 h0, l0, h1, l1;
        split_bf16(v0, h0, l0); split_bf16(v1, h1, l1);
        *(__nv_bfloat162*)&g_xnh[idx] = mk2(h0, h1);
        *(__nv_bfloat162*)&g_xnl[idx] = mk2(l0, l1);
    }
}

// ---------------- weight conversion (hi/lo split + zero padding) ----------------
__global__ void cvt_weights(const float* __restrict__ wi,
                            const float* __restrict__ wx,
                            const float* __restrict__ wo)
{
    int stride = gridDim.x * blockDim.x;
    int t = blockIdx.x * blockDim.x + threadIdx.x;
    for (int e = t; e < 768*CC; e += stride) {
        __nv_bfloat16 h, l; split_bf16(wi[e], h, l);
        g_wih[e] = h; g_wil[e] = l;
    }
    for (int e = t; e < 64*DI; e += stride) {
        int n = e / DI, k = e % DI;
        float v = (n < NDBL) ? wx[n*DI + k] : 0.f;
        __nv_bfloat16 h, l; split_bf16(v, h, l);
        g_wxh[e] = h; g_wxl[e] = l;
    }
    for (int e = t; e < 256*DI; e += stride) {
        int n = e / DI, k = e % DI;
        float v = (n < CC) ? wo[n*DI + k] : 0.f;
        __nv_bfloat16 h, l; split_bf16(v, h, l);
        g_woh[e] = h; g_wol[e] = l;
    }
}

// ---------------- tensor-core GEMM mainloop, BN=128 (shared by both kernels) ----
#define ROWB   80
#define OFF_AH 0
#define OFF_AL (128*ROWB)
#define OFF_BH (2*128*ROWB)
#define OFF_BL (3*128*ROWB)
#define STAGEB (4*128*ROWB)
#define SMEM_TC (2*STAGEB)

__device__ __forceinline__ void tc_mainloop(
    const __nv_bfloat16* Ahp, const __nv_bfloat16* Alp,
    const __nv_bfloat16* Bhp, const __nv_bfloat16* Blp,
    int K, int m0, int n0, char* smem, float acc[2][8][4])
{
    u32 sbase = (u32)__cvta_generic_to_shared(smem);
    int tid = threadIdx.x;
    int lane = tid & 31, wid = tid >> 5;
    int wm = wid & 3, wn = wid >> 2;

    int r0c = tid >> 2, c0c = tid & 3;
    int r1c = (tid + 256) >> 2, c1c = (tid + 256) & 3;
    int NIT = K / 32;

    for (int pre = 0; pre < 2 && pre < NIT; pre++) {
        int k0 = pre * 32;
        u32 st = sbase + (u32)(pre & 1) * STAGEB;
        cpa16(st + OFF_AH + r0c*ROWB + c0c*16, Ahp + (size_t)(m0 + r0c)*K + k0 + c0c*8);
        cpa16(st + OFF_AH + r1c*ROWB + c1c*16, Ahp + (size_t)(m0 + r1c)*K + k0 + c1c*8);
        cpa16(st + OFF_AL + r0c*ROWB + c0c*16, Alp + (size_t)(m0 + r0c)*K + k0 + c0c*8);
        cpa16(st + OFF_AL + r1c*ROWB + c1c*16, Alp + (size_t)(m0 + r1c)*K + k0 + c1c*8);
        cpa16(st + OFF_BH + r0c*ROWB + c0c*16, Bhp + (size_t)(n0 + r0c)*K + k0 + c0c*8);
        cpa16(st + OFF_BH + r1c*ROWB + c1c*16, Bhp + (size_t)(n0 + r1c)*K + k0 + c1c*8);
        cpa16(st + OFF_BL + r0c*ROWB + c0c*16, Blp + (size_t)(n0 + r0c)*K + k0 + c0c*8);
        cpa16(st + OFF_BL + r1c*ROWB + c1c*16, Blp + (size_t)(n0 + r1c)*K + k0 + c1c*8);
        cp_commit();
    }

    for (int it = 0; it < NIT; it++) {
        cp_wait1();
        __syncthreads();

        u32 st = sbase + (u32)(it & 1) * STAGEB;
        #pragma unroll
        for (int ks = 0; ks < 2; ks++) {
            u32 fah0[4], fah1[4], fal0[4], fal1[4];
            {
                u32 adr0 = st + OFF_AH + (u32)((wm*32 + (lane & 15))*ROWB
                         + ks*32 + (lane >> 4)*16);
                u32 adr1 = adr0 + 16*ROWB;
                ldsm4(fah0[0], fah0[1], fah0[2], fah0[3], adr0);
                ldsm4(fal0[0], fal0[1], fal0[2], fal0[3], adr0 + (OFF_AL - OFF_AH));
                ldsm4(fah1[0], fah1[1], fah1[2], fah1[3], adr1);
                ldsm4(fal1[0], fal1[1], fal1[2], fal1[3], adr1 + (OFF_AL - OFF_AH));
            }
            #pragma unroll
            for (int j = 0; j < 4; j++) {
                u32 fbh[4], fbl[4];
                u32 bdr = st + OFF_BH + (u32)((wn*64 + j*16 + (lane & 15))*ROWB
                        + ks*32 + (lane >> 4)*16);
                ldsm4(fbh[0], fbh[1], fbh[2], fbh[3], bdr);
                ldsm4(fbl[0], fbl[1], fbl[2], fbl[3], bdr + (OFF_BL - OFF_BH));

                mma16816(acc[0][2*j][0], acc[0][2*j][1], acc[0][2*j][2], acc[0][2*j][3],
                         fah0[0], fah0[1], fah0[2], fah0[3], fbh[0], fbh[2]);
                mma16816(acc[0][2*j][0], acc[0][2*j][1], acc[0][2*j][2], acc[0][2*j][3],
                         fah0[0], fah0[1], fah0[2], fah0[3], fbl[0], fbl[2]);
                mma16816(acc[0][2*j][0], acc[0][2*j][1], acc[0][2*j][2], acc[0][2*j][3],
                         fal0[0], fal0[1], fal0[2], fal0[3], fbh[0], fbh[2]);
                mma16816(acc[0][2*j+1][0], acc[0][2*j+1][1], acc[0][2*j+1][2], acc[0][2*j+1][3],
                         fah0[0], fah0[1], fah0[2], fah0[3], fbh[1], fbh[3]);
                mma16816(acc[0][2*j+1][0], acc[0][2*j+1][1], acc[0][2*j+1][2], acc[0][2*j+1][3],
                         fah0[0], fah0[1], fah0[2], fah0[3], fbl[1], fbl[3]);
                mma16816(acc[0][2*j+1][0], acc[0][2*j+1][1], acc[0][2*j+1][2], acc[0][2*j+1][3],
                         fal0[0], fal0[1], fal0[2], fal0[3], fbh[1], fbh[3]);

                mma16816(acc[1][2*j][0], acc[1][2*j][1], acc[1][2*j][2], acc[1][2*j][3],
                         fah1[0], fah1[1], fah1[2], fah1[3], fbh[0], fbh[2]);
                mma16816(acc[1][2*j][0], acc[1][2*j][1], acc[1][2*j][2], acc[1][2*j][3],
                         fah1[0], fah1[1], fah1[2], fah1[3], fbl[0], fbl[2]);
                mma16816(acc[1][2*j][0], acc[1][2*j][1], acc[1][2*j][2], acc[1][2*j][3],
                         fal1[0], fal1[1], fal1[2], fal1[3], fbh[0], fbh[2]);
                mma16816(acc[1][2*j+1][0], acc[1][2*j+1][1], acc[1][2*j+1][2], acc[1][2*j+1][3],
                         fah1[0], fah1[1], fah1[2], fah1[3], fbh[1], fbh[3]);
                mma16816(acc[1][2*j+1][0], acc[1][2*j+1][1], acc[1][2*j+1][2], acc[1][2*j+1][3],
                         fah1[0], fah1[1], fah1[2], fah1[3], fbl[1], fbl[3]);
                mma16816(acc[1][2*j+1][0], acc[1][2*j+1][1], acc[1][2*j+1][2], acc[1][2*j+1][3],
                         fal1[0], fal1[1], fal1[2], fal1[3], fbh[1], fbh[3]);
            }
        }
        __syncthreads();
        if (it + 2 < NIT) {
            int k0 = (it + 2) * 32;
            u32 st2 = sbase + (u32)((it + 2) & 1) * STAGEB;
            cpa16(st2 + OFF_AH + r0c*ROWB + c0c*16, Ahp + (size_t)(m0 + r0c)*K + k0 + c0c*8);
            cpa16(st2 + OFF_AH + r1c*ROWB + c1c*16, Ahp + (size_t)(m0 + r1c)*K + k0 + c1c*8);
            cpa16(st2 + OFF_AL + r0c*ROWB + c0c*16, Alp + (size_t)(m0 + r0c)*K + k0 + c0c*8);
            cpa16(st2 + OFF_AL + r1c*ROWB + c1c*16, Alp + (size_t)(m0 + r1c)*K + k0 + c1c*8);
            cpa16(st2 + OFF_BH + r0c*ROWB + c0c*16, Bhp + (size_t)(n0 + r0c)*K + k0 + c0c*8);
            cpa16(st2 + OFF_BH + r1c*ROWB + c1c*16, Bhp + (size_t)(n0 + r1c)*K + k0 + c1c*8);
            cpa16(st2 + OFF_BL + r0c*ROWB + c0c*16, Blp + (size_t)(n0 + r0c)*K + k0 + c0c*8);
            cpa16(st2 + OFF_BL + r1c*ROWB + c1c*16, Blp + (size_t)(n0 + r1c)*K + k0 + c1c*8);
        }
        cp_commit();
    }
}

// plain fp32 store (z-batched), BN=128
__global__ void __launch_bounds__(256)
gemm_tc_store(const __nv_bfloat16* __restrict__ Ahp, const __nv_bfloat16* __restrict__ Alp,
              const __nv_bfloat16* __restrict__ Bhp, const __nv_bfloat16* __restrict__ Blp,
              float* __restrict__ C, int K, int N, int ldc, size_t aZ, size_t cZ)
{
    extern __shared__ char smem[];
    float acc[2][8][4];
    #pragma unroll
    for (int i = 0; i < 2; i++)
        #pragma unroll
        for (int j = 0; j < 8; j++)
            #pragma unroll
            for (int q = 0; q < 4; q++) acc[i][j][q] = 0.f;

    int m0 = blockIdx.y*128, n0 = blockIdx.x*128;
    tc_mainloop(Ahp + (size_t)blockIdx.z*aZ, Alp + (size_t)blockIdx.z*aZ,
                Bhp, Blp, K, m0, n0, smem, acc);
    C += (size_t)blockIdx.z * cZ;

    int lane = threadIdx.x & 31, wid = threadIdx.x >> 5;
    int wm = wid & 3, wn = wid >> 2;
    int gp = lane >> 2, tg = lane & 3;
    #pragma unroll
    for (int mi = 0; mi < 2; mi++) {
        int row = m0 + wm*32 + mi*16 + gp;
        #pragma unroll
        for (int ni = 0; ni < 8; ni++) {
            int col = n0 + wn*64 + ni*8 + tg*2;
            if (col < N) {
                float2 v0; v0.x = acc[mi][ni][0]; v0.y = acc[mi][ni][1];
                float2 v1; v1.x = acc[mi][ni][2]; v1.y = acc[mi][ni][3];
                *(float2*)&C[(size_t)row*ldc + col]       = v0;
                *(float2*)&C[(size_t)(row + 8)*ldc + col] = v1;
            }
        }
    }
}

// ---------------- BN=64 tensor-core GEMM (for x_proj, N=44 padded to 64) --------
#define OFF64_AH 0
#define OFF64_AL (128*ROWB)
#define OFF64_BH (2*128*ROWB)
#define OFF64_BL (OFF64_BH + 64*ROWB)
#define STAGE64  (OFF64_BL + 64*ROWB)   // 384*ROWB = 30720 B
#define SMEM_N64 (2*STAGE64)

__global__ void __launch_bounds__(256)
gemm_tc_n64(const __nv_bfloat16* __restrict__ Ahp, const __nv_bfloat16* __restrict__ Alp,
            const __nv_bfloat16* __restrict__ Bhp, const __nv_bfloat16* __restrict__ Blp,
            float* __restrict__ C, int K, int N, int ldc, size_t aZ, size_t cZ)
{
    extern __shared__ char smem[];
    u32 sbase = (u32)__cvta_generic_to_shared(smem);
    int tid = threadIdx.x;
    int lane = tid & 31, wid = tid >> 5;
    int wm = wid & 3, wn = wid >> 2;   // warp tile 32 x 32
    int m0 = blockIdx.y*128;

    Ahp += (size_t)blockIdx.z * aZ;
    Alp += (size_t)blockIdx.z * aZ;
    C   += (size_t)blockIdx.z * cZ;

    float acc[2][4][4];
    #pragma unroll
    for (int i = 0; i < 2; i++)
        #pragma unroll
        for (int j = 0; j < 4; j++)
            #pragma unroll
            for (int q = 0; q < 4; q++) acc[i][j][q] = 0.f;

    int r0c = tid >> 2, c0c = tid & 3;            // A: 2 chunks/thread/array
    int r1c = (tid + 256) >> 2, c1c = (tid + 256) & 3;
    int rbc = tid >> 2, cbc = tid & 3;            // B: 1 chunk/thread/array (64 rows)
    int NIT = K / 32;

    for (int pre = 0; pre < 2 && pre < NIT; pre++) {
        int k0 = pre * 32;
        u32 st = sbase + (u32)(pre & 1) * STAGE64;
        cpa16(st + OFF64_AH + r0c*ROWB + c0c*16, Ahp + (size_t)(m0 + r0c)*K + k0 + c0c*8);
        cpa16(st + OFF64_AH + r1c*ROWB + c1c*16, Ahp + (size_t)(m0 + r1c)*K + k0 + c1c*8);
        cpa16(st + OFF64_AL + r0c*ROWB + c0c*16, Alp + (size_t)(m0 + r0c)*K + k0 + c0c*8);
        cpa16(st + OFF64_AL + r1c*ROWB + c1c*16, Alp + (size_t)(m0 + r1c)*K + k0 + c1c*8);
        if (rbc < 64) {
            cpa16(st + OFF64_BH + rbc*ROWB + cbc*16, Bhp + (size_t)rbc*K + k0 + cbc*8);
            cpa16(st + OFF64_BL + rbc*ROWB + cbc*16, Blp + (size_t)rbc*K + k0 + cbc*8);
        }
        cp_commit();
    }

    for (int it = 0; it < NIT; it++) {
        cp_wait1();
        __syncthreads();

        u32 st = sbase + (u32)(it & 1) * STAGE64;
        #pragma unroll
        for (int ks = 0; ks < 2; ks++) {
            u32 fah0[4], fah1[4], fal0[4], fal1[4];
            {
                u32 adr0 = st + OFF64_AH + (u32)((wm*32 + (lane & 15))*ROWB
                         + ks*32 + (lane >> 4)*16);
                u32 adr1 = adr0 + 16*ROWB;
                ldsm4(fah0[0], fah0[1], fah0[2], fah0[3], adr0);
                ldsm4(fal0[0], fal0[1], fal0[2], fal0[3], adr0 + (OFF64_AL - OFF64_AH));
                ldsm4(fah1[0], fah1[1], fah1[2], fah1[3], adr1);
                ldsm4(fal1[0], fal1[1], fal1[2], fal1[3], adr1 + (OFF64_AL - OFF64_AH));
            }
            #pragma unroll
            for (int j = 0; j < 2; j++) {
                u32 fbh[4], fbl[4];
                u32 bdr = st + OFF64_BH + (u32)((wn*32 + j*16 + (lane & 15))*ROWB
                        + ks*32 + (lane >> 4)*16);
                ldsm4(fbh[0], fbh[1], fbh[2], fbh[3], bdr);
                ldsm4(fbl[0], fbl[1], fbl[2], fbl[3], bdr + (OFF64_BL - OFF64_BH));

                mma16816(acc[0][2*j][0], acc[0][2*j][1], acc[0][2*j][2], acc[0][2*j][3],
                         fah0[0], fah0[1], fah0[2], fah0[3], fbh[0], fbh[2]);
                mma16816(acc[0][2*j][0], acc[0][2*j][1], acc[0][2*j][2], acc[0][2*j][3],
                         fah0[0], fah0[1], fah0[2], fah0[3], fbl[0], fbl[2]);
                mma16816(acc[0][2*j][0], acc[0][2*j][1], acc[0][2*j][2], acc[0][2*j][3],
                         fal0[0], fal0[1], fal0[2], fal0[3], fbh[0], fbh[2]);
                mma16816(acc[0][2*j+1][0], acc[0][2*j+1][1], acc[0][2*j+1][2], acc[0][2*j+1][3],
                         fah0[0], fah0[1], fah0[2], fah0[3], fbh[1], fbh[3]);
                mma16816(acc[0][2*j+1][0], acc[0][2*j+1][1], acc[0][2*j+1][2], acc[0][2*j+1][3],
                         fah0[0], fah0[1], fah0[2], fah0[3], fbl[1], fbl[3]);
                mma16816(acc[0][2*j+1][0], acc[0][2*j+1][1], acc[0][2*j+1][2], acc[0][2*j+1][3],
                         fal0[0], fal0[1], fal0[2], fal0[3], fbh[1], fbh[3]);

                mma16816(acc[1][2*j][0], acc[1][2*j][1], acc[1][2*j][2], acc[1][2*j][3],
                         fah1[0], fah1[1], fah1[2], fah1[3], fbh[0], fbh[2]);
                mma16816(acc[1][2*j][0], acc[1][2*j][1], acc[1][2*j][2], acc[1][2*j][3],
                         fah1[0], fah1[1], fah1[2], fah1[3], fbl[0], fbl[2]);
                mma16816(acc[1][2*j][0], acc[1][2*j][1], acc[1][2*j][2], acc[1][2*j][3],
                         fal1[0], fal1[1], fal1[2], fal1[3], fbh[0], fbh[2]);
                mma16816(acc[1][2*j+1][0], acc[1][2*j+1][1], acc[1][2*j+1][2], acc[1][2*j+1][3],
                         fah1[0], fah1[1], fah1[2], fah1[3], fbh[1], fbh[3]);
                mma16816(acc[1][2*j+1][0], acc[1][2*j+1][1], acc[1][2*j+1][2], acc[1][2*j+1][3],
                         fah1[0], fah1[1], fah1[2], fah1[3], fbl[1], fbl[3]);
                mma16816(acc[1][2*j+1][0], acc[1][2*j+1][1], acc[1][2*j+1][2], acc[1][2*j+1][3],
                         fal1[0], fal1[1], fal1[2], fal1[3], fbh[1], fbh[3]);
            }
        }
        __syncthreads();
        if (it + 2 < NIT) {
            int k0 = (it + 2) * 32;
            u32 st2 = sbase + (u32)((it + 2) & 1) * STAGE64;
            cpa16(st2 + OFF64_AH + r0c*ROWB + c0c*16, Ahp + (size_t)(m0 + r0c)*K + k0 + c0c*8);
            cpa16(st2 + OFF64_AH + r1c*ROWB + c1c*16, Ahp + (size_t)(m0 + r1c)*K + k0 + c1c*8);
            cpa16(st2 + OFF64_AL + r0c*ROWB + c0c*16, Alp + (size_t)(m0 + r0c)*K + k0 + c0c*8);
            cpa16(st2 + OFF64_AL + r1c*ROWB + c1c*16, Alp + (size_t)(m0 + r1c)*K + k0 + c1c*8);
            if (rbc < 64) {
                cpa16(st2 + OFF64_BH + rbc*ROWB + cbc*16, Bhp + (size_t)rbc*K + k0 + cbc*8);
                cpa16(st2 + OFF64_BL + rbc*ROWB + cbc*16, Blp + (size_t)rbc*K + k0 + cbc*8);
            }
        }
        cp_commit();
    }

    int gp = lane >> 2, tg = lane & 3;
    #pragma unroll
    for (int mi = 0; mi < 2; mi++) {
        int row = m0 + wm*32 + mi*16 + gp;
        #pragma unroll
        for (int ni = 0; ni < 4; ni++) {
            int col = wn*32 + ni*8 + tg*2;
            if (col < N) {
                float2 v0; v0.x = acc[mi][ni][0]; v0.y = acc[mi][ni][1];
                float2 v1; v1.x = acc[mi][ni][2]; v1.y = acc[mi][ni][3];
                *(float2*)&C[(size_t)row*ldc + col]       = v0;
                *(float2*)&C[(size_t)(row + 8)*ldc + col] = v1;
            }
        }
    }
}

// transposed store to d_out laid out (B, C, L), BN=128
__global__ void __launch_bounds__(256)
gemm_tc_out(const __nv_bfloat16* __restrict__ Ahp, const __nv_bfloat16* __restrict__ Alp,
            const __nv_bfloat16* __restrict__ Bhp, const __nv_bfloat16* __restrict__ Blp,
            int K, int N, float* __restrict__ dout)
{
    extern __shared__ char smem[];
    float acc[2][8][4];
    #pragma unroll
    for (int i = 0; i < 2; i++)
        #pragma unroll
        for (int j = 0; j < 8; j++)
            #pragma unroll
            for (int q = 0; q < 4; q++) acc[i][j][q] = 0.f;

    int m0 = blockIdx.y*128, n0 = blockIdx.x*128;
    tc_mainloop(Ahp, Alp, Bhp, Blp, K, m0, n0, smem, acc);

    cp_wait0();
    __syncthreads();
    float* so = (float*)smem;   // [128][132]
    int lane = threadIdx.x & 31, wid = threadIdx.x >> 5;
    int wm = wid & 3, wn = wid >> 2;
    int gp = lane >> 2, tg = lane & 3;
    #pragma unroll
    for (int mi = 0; mi < 2; mi++) {
        int ml = wm*32 + mi*16 + gp;
        #pragma unroll
        for (int ni = 0; ni < 8; ni++) {
            int nl = wn*64 + ni*8 + tg*2;
            so[(size_t)nl*132 + ml]         = acc[mi][ni][0];
            so[(size_t)(nl+1)*132 + ml]     = acc[mi][ni][1];
            so[(size_t)nl*132 + ml + 8]     = acc[mi][ni][2];
            so[(size_t)(nl+1)*132 + ml + 8] = acc[mi][ni][3];
        }
    }
    __syncthreads();
    int b = m0 >> 12, p0 = m0 & (LL - 1);
    for (int e = threadIdx.x; e < 128*128; e += 256) {
        int nl = e >> 7, mlp = e & 127;
        int n = n0 + nl;
        if (n < N)
            dout[((size_t)(b*CC + n))*LL + p0 + mlp] = so[(size_t)nl*132 + mlp];
    }
}

// ---------------- depthwise causal conv (both directions) + silu -> bf16 hi/lo ----
__global__ void conv_silu_kernel(const float* __restrict__ cw, const float* __restrict__ cb)
{
    __shared__ float s[16 + 6][DI];
    int b = blockIdx.y, t0 = blockIdx.x * 16, d = threadIdx.x;

    #pragma unroll
    for (int j = 0; j < 22; j++) {
        int t = t0 - 3 + j;
        float v = 0.f;
        if (t >= 0 && t < LL) v = g_xz[((size_t)(b*LL + t))*768 + d];
        s[j][d] = v;
    }
    __syncthreads();
    float w0 = cw[d*4+0], w1 = cw[d*4+1], w2 = cw[d*4+2], w3 = cw[d*4+3];
    float bias = cb[d];
    #pragma unroll
    for (int tt = 0; tt < 16; tt++) {
        float of = w0*s[tt][d] + w1*s[tt+1][d] + w2*s[tt+2][d] + w3*s[tt+3][d] + bias;
        float ob = w3*s[tt+3][d] + w2*s[tt+4][d] + w1*s[tt+5][d] + w0*s[tt+6][d] + bias;
        size_t m = (size_t)(b*LL + t0 + tt);
        float vf = silu_f(of), vb = silu_f(ob);
        __nv_bfloat16 h, l;
        split_bf16(vf, h, l); g_xsh[0][m*DI + d] = h; g_xsl[0][m*DI + d] = l;
        split_bf16(vb, h, l); g_xsh[1][m*DI + d] = h; g_xsl[1][m*DI + d] = l;
    }
}

// ---------------- chunked selective scan (dt_proj fused, f32x2, 3-deep prefetch) --
#define SROW 48   // smem row stride in floats (44 padded to 48)
#define NBUF 3

template<bool P3>
__global__ void __launch_bounds__(128)
scan_kernel(const float* __restrict__ A_log,
            const float* __restrict__ dtw,
            const float* __restrict__ dtbv,
            const float* __restrict__ Dv)
{
    __shared__ __align__(16) float sdbl[NBUF][SW][SROW];
    __shared__ __align__(16) __nv_bfloat16 sxh[NBUF][SW][128];
    __shared__ __align__(16) __nv_bfloat16 sxl[NBUF][SW][128];

    int d  = blockIdx.x * 128 + threadIdx.x;
    int d0 = blockIdx.x * 128;
    int c  = blockIdx.y;
    int rb = blockIdx.z;
    int r  = rb >> 2, b = rb & 3;
    int tid = threadIdx.x;

    const int NSEG = P3 ? 11 : 7;
    const float* dblp = g_dbl[r];
    const __nv_bfloat16* xshp = g_xsh[r];
    const __nv_bfloat16* xslp = g_xsl[r];
    u32 sb  = (u32)__cvta_generic_to_shared(&sdbl[0][0][0]);
    u32 sxh_b = (u32)__cvta_generic_to_shared(&sxh[0][0][0]);
    u32 sxl_b = (u32)__cvta_generic_to_shared(&sxl[0][0][0]);

    auto issue_win = [&](int w) {
        u32 buf = (u32)(w % NBUF);
        int nch = SW * NSEG;
        u32 dst0 = sb + buf * (SW*SROW*4);
        for (int q = tid; q < nch; q += 128) {
            int j = q / NSEG, seg = q % NSEG;
            int tau = c*LC + w*SW + j;
            int pos = r ? (LL - 1 - tau) : tau;
            size_t m = (size_t)b*LL + pos;
            cpa16(dst0 + (u32)(j*SROW + seg*4)*4, dblp + m*NDBL + seg*4);
        }
        u32 xh0 = sxh_b + buf * (SW*128*2);
        u32 xl0 = sxl_b + buf * (SW*128*2);
        for (int q = tid; q < SW*16; q += 128) {
            int j = q >> 4, seg = q & 15;
            int tau = c*LC + w*SW + j;
            int pos = r ? (LL - 1 - tau) : tau;
            size_t m = (size_t)b*LL + pos;
            cpa16(xh0 + (u32)(j*128 + seg*8)*2, xshp + m*DI + d0 + seg*8);
            cpa16(xl0 + (u32)(j*128 + seg*8)*2, xslp + m*DI + d0 + seg*8);
        }
        cp_commit();
    };

    float A2[DS], wdt[DTR];
    bool structured = true;
    #pragma unroll
    for (int sIdx = 0; sIdx < DS; sIdx++)
        A2[sIdx] = -__expf(A_log[d*DS + sIdx]) * LOG2E;
    #pragma unroll
    for (int sIdx = 1; sIdx < DS; sIdx++)
        structured &= fabsf(A2[sIdx] - (sIdx+1)*A2[0]) <= 1e-4f*fabsf(A2[sIdx]);
    #pragma unroll
    for (int j = 0; j < DTR; j++) wdt[j] = dtw[d*DTR + j];
    float dtb = dtbv[d];
    float Dval = P3 ? Dv[d] : 0.f;

    u64 wdt2[6];
    #pragma unroll
    for (int k = 0; k < 6; k++) wdt2[k] = pk2(wdt[2*k], wdt[2*k+1]);

    size_t base = (((size_t)rb*NC + c)*DI + d)*DS;
    u64 hp[DS/2];
    #pragma unroll
    for (int k = 0; k < DS/2; k++) {
        if (P3) {
            float2 hv = *(const float2*)&g_hstart[base + 2*k];
            hp[k] = pk2(hv.x, hv.y);
        } else {
            hp[k] = 0ull;
        }
    }

    float* yp = g_y[r];
    float S = 0.f;

    issue_win(0);
    if (NW > 1) issue_win(1);
    if (NW > 2) issue_win(2);

    for (int w = 0; w < NW; w++) {
        if (w + 3 <= NW - 1)      cp_wait2();
        else if (w + 2 <= NW - 1) cp_wait1();
        else                      cp_wait0();
        __syncthreads();
        int buf = w % NBUF;
        const float (*row)[SROW] = sdbl[buf];

        #pragma unroll 4
        for (int j = 0; j < SW; j++) {
            int tau = c*LC + w*SW + j;
            int pos = r ? (LL - 1 - tau) : tau;
            size_t m = (size_t)b*LL + pos;

            u64 acc2 = 0ull;
            #pragma unroll
            for (int k = 0; k < 6; k++) {
                u64 iv = *(const u64*)&row[j][2*k];
                acc2 = fma2_(iv, wdt2[k], acc2);
            }
            float alo, ahi; upk2(alo, ahi, acc2);
            float dt = sp_f(dtb + alo + ahi);

            float u  = b2f(sxh[buf][j][tid]) + b2f(sxl[buf][j][tid]);
            float dtx = dt * u;
            u64 dtx2 = pk2(dtx, dtx);

            float y = 0.f;
            if (structured) {
                float e1 = ex2(dt * A2[0]);
                float ee = e1 * e1;
                u64 eep = pk2(ee, ee);
                u64 ap  = pk2(e1, ee);
                u64 y2  = 0ull;
                #pragma unroll
                for (int k = 0; k < DS/2; k++) {
                    u64 Bp = *(const u64*)&row[j][DTR + 2*k];
                    hp[k] = fma2_(ap, hp[k], mul2_(dtx2, Bp));
                    if (P3) {
                        u64 Cp = *(const u64*)&row[j][DTR + DS + 2*k];
                        y2 = fma2_(hp[k], Cp, y2);
                    }
                    if (k < DS/2 - 1) ap = mul2_(ap, eep);
                }
                if (P3) { float yl, yh; upk2(yl, yh, y2); y = yl + yh; }
            } else {
                #pragma unroll
                for (int k = 0; k < DS/2; k++) {
                    float h0, h1; upk2(h0, h1, hp[k]);
                    float a0 = ex2(dt * A2[2*k]);
                    float a1 = ex2(dt * A2[2*k+1]);
                    float B0 = row[j][DTR + 2*k], B1 = row[j][DTR + 2*k+1];
                    h0 = fmaf(a0, h0, dtx * B0);
                    h1 = fmaf(a1, h1, dtx * B1);
                    if (P3) {
                        y = fmaf(h0, row[j][DTR + DS + 2*k], y);
                        y = fmaf(h1, row[j][DTR + DS + 2*k+1], y);
                    }
                    hp[k] = pk2(h0, h1);
                }
            }
            if (P3) {
                y = fmaf(u, Dval, y);
                yp[m*DI + d] = y;
            } else {
                S += dt;
            }
        }
        __syncthreads();
        if (w + NBUF < NW) issue_win(w + NBUF);
    }

    if (!P3) {
        #pragma unroll
        for (int k = 0; k < DS/2; k++) {
            float h0, h1; upk2(h0, h1, hp[k]);
            float2 hv; hv.x = h0; hv.y = h1;
            *(float2*)&g_hend[base + 2*k] = hv;
            float2 pv;
            pv.x = ex2(A2[2*k]   * S);
            pv.y = ex2(A2[2*k+1] * S);
            *(float2*)&g_pend[base + 2*k] = pv;
        }
    }
}

__global__ void scan_combine()
{
    int g = blockIdx.x * 256 + threadIdx.x;
    if (g >= 2*BB*DI*DS) return;
    int sd = g % (DI*DS);
    int rb = g / (DI*DS);
    float carry = 0.f;
    for (int c = 0; c < NC; c++) {
        size_t idx = ((size_t)rb*NC + c)*(DI*DS) + sd;
        g_hstart[idx] = carry;
        carry = g_pend[idx]*carry + g_hend[idx];
    }
}

// ---------------- fused gate -> bf16 hi/lo (xs-free; 4 elems/thread) ------------
__global__ void combine_G(const float* __restrict__ Dv)
{
    size_t g4 = (size_t)blockIdx.x * 256 + threadIdx.x;
    if (g4 >= (size_t)MM*DI/4) return;
    int d4 = (int)(g4 % (DI/4));
    size_t m = g4 / (DI/4);
    int d = 4*d4;
    size_t gi = m*DI + d;

    float4 z  = *(const float4*)&g_xz[m*768 + DI + d];
    float4 y0 = *(const float4*)&g_y[0][gi];
    float4 y1 = *(const float4*)&g_y[1][gi];

    float v0 = silu_f(z.x) * (y0.x + y1.x);
    float v1 = silu_f(z.y) * (y0.y + y1.y);
    float v2 = silu_f(z.z) * (y0.z + y1.z);
    float v3 = silu_f(z.w) * (y0.w + y1.w);
    __nv_bfloat16 h0, l0, h1, l1, h2, l2, h3, l3;
    split_bf16(v0, h0, l0); split_bf16(v1, h1, l1);
    split_bf16(v2, h2, l2); split_bf16(v3, h3, l3);
    __nv_bfloat162 ph0 = mk2(h0, h1), ph1 = mk2(h2, h3);
    __nv_bfloat162 pl0 = mk2(l0, l1), pl1 = mk2(l2, l3);
    *(u64*)&g_Gh[gi] = ((u64)*(u32*)&ph1 << 32) | *(u32*)&ph0;
    *(u64*)&g_Gl[gi] = ((u64)*(u32*)&pl1 << 32) | *(u32*)&pl0;
}

// ---------------- launch ----------------
static void* sym_addr(const void* sym) {
    void* p = nullptr;
    cudaGetSymbolAddress(&p, sym);
    return p;
}

extern "C" void kernel_launch(void* const* d_in, const int* in_sizes, int n_in,
                              void* d_out, int out_size)
{
    const float* x          = (const float*)d_in[0];
    const float* ln_w       = (const float*)d_in[1];
    const float* ln_b       = (const float*)d_in[2];
    const float* in_proj_w  = (const float*)d_in[3];
    const float* conv_w     = (const float*)d_in[4];
    const float* conv_b     = (const float*)d_in[5];
    const float* x_proj_w   = (const float*)d_in[6];
    const float* dt_proj_w  = (const float*)d_in[7];
    const float* dt_proj_b  = (const float*)d_in[8];
    const float* A_log      = (const float*)d_in[9];
    const float* D_vec      = (const float*)d_in[10];
    const float* out_proj_w = (const float*)d_in[11];
    float* out = (float*)d_out;

    float* p_xz  = (float*)sym_addr(g_xz);
    float* p_dbl = (float*)sym_addr(g_dbl);
    __nv_bfloat16* p_xnh = (__nv_bfloat16*)sym_addr(g_xnh);
    __nv_bfloat16* p_xnl = (__nv_bfloat16*)sym_addr(g_xnl);
    __nv_bfloat16* p_xsh = (__nv_bfloat16*)sym_addr(g_xsh);
    __nv_bfloat16* p_xsl = (__nv_bfloat16*)sym_addr(g_xsl);
    __nv_bfloat16* p_Gh  = (__nv_bfloat16*)sym_addr(g_Gh);
    __nv_bfloat16* p_Gl  = (__nv_bfloat16*)sym_addr(g_Gl);
    __nv_bfloat16* p_wih = (__nv_bfloat16*)sym_addr(g_wih);
    __nv_bfloat16* p_wil = (__nv_bfloat16*)sym_addr(g_wil);
    __nv_bfloat16* p_wxh = (__nv_bfloat16*)sym_addr(g_wxh);
    __nv_bfloat16* p_wxl = (__nv_bfloat16*)sym_addr(g_wxl);
    __nv_bfloat16* p_woh = (__nv_bfloat16*)sym_addr(g_woh);
    __nv_bfloat16* p_wol = (__nv_bfloat16*)sym_addr(g_wol);

    cudaFuncSetAttribute((const void*)gemm_tc_store,
                         cudaFuncAttributeMaxDynamicSharedMemorySize, SMEM_TC);
    cudaFuncSetAttribute((const void*)gemm_tc_out,
                         cudaFuncAttributeMaxDynamicSharedMemorySize, SMEM_TC);
    cudaFuncSetAttribute((const void*)gemm_tc_n64,
                         cudaFuncAttributeMaxDynamicSharedMemorySize, SMEM_N64);

    // 1) LayerNorm -> bf16 hi/lo
    ln_kernel<<<dim3(LL/32, BB), dim3(32, 8)>>>(x, ln_w, ln_b);

    // 1b) weight conversion
    cvt_weights<<<256, 256>>>(in_proj_w, x_proj_w, out_proj_w);

    // 2) in_proj: xz[M,768] = xn @ Wi^T  (tensor cores)
    gemm_tc_store<<<dim3(768/128, MM/128, 1), 256, SMEM_TC>>>(
        p_xnh, p_xnl, p_wih, p_wil, p_xz, CC, 768, 768, 0, 0);

    // 3) conv + silu (both directions) -> bf16 hi/lo
    conv_silu_kernel<<<dim3(LL/16, BB), DI>>>(conv_w, conv_b);

    // 4) x_proj both dirs: dbl[M,44] = xs @ Wx^T  (BN=64 tensor cores)
    gemm_tc_n64<<<dim3(1, MM/128, 2), 256, SMEM_N64>>>(
        p_xsh, p_xsl, p_wxh, p_wxl, p_dbl, DI, NDBL, NDBL,
        (size_t)MM*DI, (size_t)MM*NDBL);

    // 5-8) chunked selective scan (3-deep cp.async prefetch of dbl + xs)
    scan_kernel<false><<<dim3(DI/128, NC, 2*BB), 128>>>(A_log, dt_proj_w, dt_proj_b, D_vec);
    scan_combine<<<dim3((2*BB*DI*DS + 255)/256), 256>>>();
    scan_kernel<true><<<dim3(DI/128, NC, 2*BB), 128>>>(A_log, dt_proj_w, dt_proj_b, D_vec);

    // 9) fused gate -> bf16 hi/lo (xs-free, 4-wide vectorized)
    combine_G<<<dim3((MM*DI/4 + 255)/256), 256>>>(D_vec);

    // 10) out_proj (tensor cores) with transposed store to (B,C,H,W)
    gemm_tc_out<<<dim3(2, MM/128, 1), 256, SMEM_TC>>>(
        p_Gh, p_Gl, p_woh, p_wol, DI, CC, out);
}

// round 17
// speedup vs baseline: 1.4378x; 1.0133x over previous
#include <cuda_runtime.h>
#include <cuda_bf16.h>
#include <cstdint>
#include <math.h>

typedef unsigned int u32;
typedef unsigned long long u64;

// ---------------- problem constants ----------------
#define BB   4
#define CC   192
#define HH   64
#define WW   64
#define LL   (HH*WW)          // 4096
#define MM   (BB*LL)          // 16384
#define DI   384
#define DS   16
#define DTR  12
#define NDBL 44               // DTR + 2*DS
#define NC   32               // scan chunks
#define LC   (LL/NC)          // 128
#define SW   16               // scan smem window (timesteps)
#define NW   (LC/SW)          // 8 windows
#define LOG2E 1.4426950408889634f
#define LN2   0.6931471805599453f

// ---------------- scratch (device globals: allocation-free) ----------------
__device__ __align__(128) float g_xz [(size_t)MM*768];
__device__ __align__(128) float g_dbl[2][(size_t)MM*NDBL];
__device__ __align__(128) float g_y  [2][(size_t)MM*DI];
__device__ float g_hend  [2*BB*NC*DI*DS];
__device__ float g_pend  [2*BB*NC*DI*DS];
__device__ float g_hstart[2*BB*NC*DI*DS];

// bf16 hi/lo pairs for tensor-core GEMMs (k-contiguous natural layouts)
__device__ __align__(128) __nv_bfloat16 g_xnh[(size_t)MM*CC];
__device__ __align__(128) __nv_bfloat16 g_xnl[(size_t)MM*CC];
__device__ __align__(128) __nv_bfloat16 g_xsh[2][(size_t)MM*DI];
__device__ __align__(128) __nv_bfloat16 g_xsl[2][(size_t)MM*DI];
__device__ __align__(128) __nv_bfloat16 g_Gh [(size_t)MM*DI];
__device__ __align__(128) __nv_bfloat16 g_Gl [(size_t)MM*DI];
__device__ __align__(128) __nv_bfloat16 g_wih[768*CC];
__device__ __align__(128) __nv_bfloat16 g_wil[768*CC];
__device__ __align__(128) __nv_bfloat16 g_wxh[64*DI];    // x_proj W padded 44->64 rows
__device__ __align__(128) __nv_bfloat16 g_wxl[64*DI];
__device__ __align__(128) __nv_bfloat16 g_woh[256*DI];   // out_proj W padded 192->256 rows
__device__ __align__(128) __nv_bfloat16 g_wol[256*DI];

__device__ __forceinline__ float ex2(float x){
    float r; asm("ex2.approx.ftz.f32 %0, %1;" : "=f"(r) : "f"(x)); return r;
}
__device__ __forceinline__ float silu_f(float x){
    return x / (1.f + __expf(-x));
}
__device__ __forceinline__ float sp_f(float v){   // softplus
    if (v > 15.f) return v;
    float e = ex2(v * LOG2E);
    return __log2f(1.f + e) * LN2;
}
__device__ __forceinline__ void split_bf16(float v, __nv_bfloat16& h, __nv_bfloat16& l){
    h = __float2bfloat16(v);
    l = __float2bfloat16(v - __bfloat162float(h));
}
__device__ __forceinline__ float b2f(__nv_bfloat16 v){ return __bfloat162float(v); }
__device__ __forceinline__ __nv_bfloat162 mk2(__nv_bfloat16 x, __nv_bfloat16 y){
    __nv_bfloat162 t; t.x = x; t.y = y; return t;
}

// ---------------- packed f32x2 helpers (sm_103a FFMA2 via PTX) ----------------
__device__ __forceinline__ u64 pk2(float lo, float hi){
    u64 d; asm("mov.b64 %0, {%1,%2};" : "=l"(d) : "f"(lo), "f"(hi)); return d;
}
__device__ __forceinline__ void upk2(float& lo, float& hi, u64 v){
    asm("mov.b64 {%0,%1}, %2;" : "=f"(lo), "=f"(hi) : "l"(v));
}
__device__ __forceinline__ u64 fma2_(u64 a, u64 b, u64 c){
    u64 d; asm("fma.rn.f32x2 %0, %1, %2, %3;" : "=l"(d) : "l"(a), "l"(b), "l"(c)); return d;
}
__device__ __forceinline__ u64 mul2_(u64 a, u64 b){
    u64 d; asm("mul.rn.f32x2 %0, %1, %2;" : "=l"(d) : "l"(a), "l"(b)); return d;
}

// ---------------- PTX helpers ----------------
__device__ __forceinline__ void cpa16(u32 dst, const void* src){
    asm volatile("cp.async.ca.shared.global [%0], [%1], 16;" :: "r"(dst), "l"(src));
}
__device__ __forceinline__ void cp_commit(){
    asm volatile("cp.async.commit_group;");
}
__device__ __forceinline__ void cp_wait2(){
    asm volatile("cp.async.wait_group 2;");
}
__device__ __forceinline__ void cp_wait1(){
    asm volatile("cp.async.wait_group 1;");
}
__device__ __forceinline__ void cp_wait0(){
    asm volatile("cp.async.wait_group 0;");
}
__device__ __forceinline__ void ldsm4(u32& x0, u32& x1, u32& x2, u32& x3, u32 addr){
    asm volatile("ldmatrix.sync.aligned.m8n8.x4.shared.b16 {%0,%1,%2,%3}, [%4];"
                 : "=r"(x0), "=r"(x1), "=r"(x2), "=r"(x3) : "r"(addr));
}
__device__ __forceinline__ void mma16816(float& d0, float& d1, float& d2, float& d3,
                                         u32 a0, u32 a1, u32 a2, u32 a3,
                                         u32 v0, u32 v1){
    asm volatile("mma.sync.aligned.m16n8k16.row.col.f32.bf16.bf16.f32 "
                 "{%0,%1,%2,%3},{%4,%5,%6,%7},{%8,%9},{%0,%1,%2,%3};"
                 : "+f"(d0), "+f"(d1), "+f"(d2), "+f"(d3)
                 : "r"(a0), "r"(a1), "r"(a2), "r"(a3), "r"(v0), "r"(v1));
}

// ---------------- 1) LayerNorm over channels -> bf16 hi/lo (paired stores) ------
__global__ void ln_kernel(const float* __restrict__ x,
                          const float* __restrict__ w,
                          const float* __restrict__ bsh)
{
    int b = blockIdx.y, p0 = blockIdx.x * 32;
    int tx = threadIdx.x, ty = threadIdx.y;
    __shared__ float sx[CC][33];
    __shared__ float red[2][8][32];
    __shared__ float smu[32], srs[32];

    float s1 = 0.f, s2 = 0.f;
    for (int c = ty; c < CC; c += 8) {
        float v = x[((size_t)(b*CC + c))*LL + p0 + tx];
        sx[c][tx] = v; s1 += v; s2 += v*v;
    }
    red[0][ty][tx] = s1; red[1][ty][tx] = s2;
    __syncthreads();
    if (ty == 0) {
        float a = 0.f, q = 0.f;
        #pragma unroll
        for (int j = 0; j < 8; j++){ a += red[0][j][tx]; q += red[1][j][tx]; }
        float mu = a / CC;
        float var = q / CC - mu*mu;
        smu[tx] = mu; srs[tx] = rsqrtf(var + 1e-5f);
    }
    __syncthreads();
    int tid = ty*32 + tx;
    for (int e = tid; e < 32*(CC/2); e += 256) {
        int pp = e / (CC/2), cc2 = e % (CC/2);
        int cc = 2*cc2;
        float mu = smu[pp], rs = srs[pp];
        float v0 = (sx[cc][pp]   - mu) * rs * w[cc]   + bsh[cc];
        float v1 = (sx[cc+1][pp] - mu) * rs * w[cc+1] + bsh[cc+1];
        size_t idx = ((size_t)(b*LL + p0 + pp))*CC + cc;
        __nv_bfloat16 h0, l0, h1, l1;
        split_bf16(v0, h0, l0); split_bf16(v1, h1, l1);
        *(__nv_bfloat162*)&g_xnh[idx] = mk2(h0, h1);
        *(__nv_bfloat162*)&g_xnl[idx] = mk2(l0, l1);
    }
}

// ---------------- weight conversion (hi/lo split + zero padding) ----------------
__global__ void cvt_weights(const float* __restrict__ wi,
                            const float* __restrict__ wx,
                            const float* __restrict__ wo)
{
    int stride = gridDim.x * blockDim.x;
    int t = blockIdx.x * blockDim.x + threadIdx.x;
    for (int e = t; e < 768*CC; e += stride) {
        __nv_bfloat16 h, l; split_bf16(wi[e], h, l);
        g_wih[e] = h; g_wil[e] = l;
    }
    for (int e = t; e < 64*DI; e += stride) {
        int n = e / DI, k = e % DI;
        float v = (n < NDBL) ? wx[n*DI + k] : 0.f;
        __nv_bfloat16 h, l; split_bf16(v, h, l);
        g_wxh[e] = h; g_wxl[e] = l;
    }
    for (int e = t; e < 256*DI; e += stride) {
        int n = e / DI, k = e % DI;
        float v = (n < CC) ? wo[n*DI + k] : 0.f;
        __nv_bfloat16 h, l; split_bf16(v, h, l);
        g_woh[e] = h; g_wol[e] = l;
    }
}

// ---------------- tensor-core GEMM mainloop, BN=128 (shared by both kernels) ----
#define ROWB   80
#define OFF_AH 0
#define OFF_AL (128*ROWB)
#define OFF_BH (2*128*ROWB)
#define OFF_BL (3*128*ROWB)
#define STAGEB (4*128*ROWB)
#define SMEM_TC (2*STAGEB)

__device__ __forceinline__ void tc_mainloop(
    const __nv_bfloat16* Ahp, const __nv_bfloat16* Alp,
    const __nv_bfloat16* Bhp, const __nv_bfloat16* Blp,
    int K, int m0, int n0, char* smem, float acc[2][8][4])
{
    u32 sbase = (u32)__cvta_generic_to_shared(smem);
    int tid = threadIdx.x;
    int lane = tid & 31, wid = tid >> 5;
    int wm = wid & 3, wn = wid >> 2;

    int r0c = tid >> 2, c0c = tid & 3;
    int r1c = (tid + 256) >> 2, c1c = (tid + 256) & 3;
    int NIT = K / 32;

    for (int pre = 0; pre < 2 && pre < NIT; pre++) {
        int k0 = pre * 32;
        u32 st = sbase + (u32)(pre & 1) * STAGEB;
        cpa16(st + OFF_AH + r0c*ROWB + c0c*16, Ahp + (size_t)(m0 + r0c)*K + k0 + c0c*8);
        cpa16(st + OFF_AH + r1c*ROWB + c1c*16, Ahp + (size_t)(m0 + r1c)*K + k0 + c1c*8);
        cpa16(st + OFF_AL + r0c*ROWB + c0c*16, Alp + (size_t)(m0 + r0c)*K + k0 + c0c*8);
        cpa16(st + OFF_AL + r1c*ROWB + c1c*16, Alp + (size_t)(m0 + r1c)*K + k0 + c1c*8);
        cpa16(st + OFF_BH + r0c*ROWB + c0c*16, Bhp + (size_t)(n0 + r0c)*K + k0 + c0c*8);
        cpa16(st + OFF_BH + r1c*ROWB + c1c*16, Bhp + (size_t)(n0 + r1c)*K + k0 + c1c*8);
        cpa16(st + OFF_BL + r0c*ROWB + c0c*16, Blp + (size_t)(n0 + r0c)*K + k0 + c0c*8);
        cpa16(st + OFF_BL + r1c*ROWB + c1c*16, Blp + (size_t)(n0 + r1c)*K + k0 + c1c*8);
        cp_commit();
    }

    for (int it = 0; it < NIT; it++) {
        cp_wait1();
        __syncthreads();

        u32 st = sbase + (u32)(it & 1) * STAGEB;
        #pragma unroll
        for (int ks = 0; ks < 2; ks++) {
            u32 fah0[4], fah1[4], fal0[4], fal1[4];
            {
                u32 adr0 = st + OFF_AH + (u32)((wm*32 + (lane & 15))*ROWB
                         + ks*32 + (lane >> 4)*16);
                u32 adr1 = adr0 + 16*ROWB;
                ldsm4(fah0[0], fah0[1], fah0[2], fah0[3], adr0);
                ldsm4(fal0[0], fal0[1], fal0[2], fal0[3], adr0 + (OFF_AL - OFF_AH));
                ldsm4(fah1[0], fah1[1], fah1[2], fah1[3], adr1);
                ldsm4(fal1[0], fal1[1], fal1[2], fal1[3], adr1 + (OFF_AL - OFF_AH));
            }
            #pragma unroll
            for (int j = 0; j < 4; j++) {
                u32 fbh[4], fbl[4];
                u32 bdr = st + OFF_BH + (u32)((wn*64 + j*16 + (lane & 15))*ROWB
                        + ks*32 + (lane >> 4)*16);
                ldsm4(fbh[0], fbh[1], fbh[2], fbh[3], bdr);
                ldsm4(fbl[0], fbl[1], fbl[2], fbl[3], bdr + (OFF_BL - OFF_BH));

                mma16816(acc[0][2*j][0], acc[0][2*j][1], acc[0][2*j][2], acc[0][2*j][3],
                         fah0[0], fah0[1], fah0[2], fah0[3], fbh[0], fbh[2]);
                mma16816(acc[0][2*j][0], acc[0][2*j][1], acc[0][2*j][2], acc[0][2*j][3],
                         fah0[0], fah0[1], fah0[2], fah0[3], fbl[0], fbl[2]);
                mma16816(acc[0][2*j][0], acc[0][2*j][1], acc[0][2*j][2], acc[0][2*j][3],
                         fal0[0], fal0[1], fal0[2], fal0[3], fbh[0], fbh[2]);
                mma16816(acc[0][2*j+1][0], acc[0][2*j+1][1], acc[0][2*j+1][2], acc[0][2*j+1][3],
                         fah0[0], fah0[1], fah0[2], fah0[3], fbh[1], fbh[3]);
                mma16816(acc[0][2*j+1][0], acc[0][2*j+1][1], acc[0][2*j+1][2], acc[0][2*j+1][3],
                         fah0[0], fah0[1], fah0[2], fah0[3], fbl[1], fbl[3]);
                mma16816(acc[0][2*j+1][0], acc[0][2*j+1][1], acc[0][2*j+1][2], acc[0][2*j+1][3],
                         fal0[0], fal0[1], fal0[2], fal0[3], fbh[1], fbh[3]);

                mma16816(acc[1][2*j][0], acc[1][2*j][1], acc[1][2*j][2], acc[1][2*j][3],
                         fah1[0], fah1[1], fah1[2], fah1[3], fbh[0], fbh[2]);
                mma16816(acc[1][2*j][0], acc[1][2*j][1], acc[1][2*j][2], acc[1][2*j][3],
                         fah1[0], fah1[1], fah1[2], fah1[3], fbl[0], fbl[2]);
                mma16816(acc[1][2*j][0], acc[1][2*j][1], acc[1][2*j][2], acc[1][2*j][3],
                         fal1[0], fal1[1], fal1[2], fal1[3], fbh[0], fbh[2]);
                mma16816(acc[1][2*j+1][0], acc[1][2*j+1][1], acc[1][2*j+1][2], acc[1][2*j+1][3],
                         fah1[0], fah1[1], fah1[2], fah1[3], fbh[1], fbh[3]);
                mma16816(acc[1][2*j+1][0], acc[1][2*j+1][1], acc[1][2*j+1][2], acc[1][2*j+1][3],
                         fah1[0], fah1[1], fah1[2], fah1[3], fbl[1], fbl[3]);
                mma16816(acc[1][2*j+1][0], acc[1][2*j+1][1], acc[1][2*j+1][2], acc[1][2*j+1][3],
                         fal1[0], fal1[1], fal1[2], fal1[3], fbh[1], fbh[3]);
            }
        }
        __syncthreads();
        if (it + 2 < NIT) {
            int k0 = (it + 2) * 32;
            u32 st2 = sbase + (u32)((it + 2) & 1) * STAGEB;
            cpa16(st2 + OFF_AH + r0c*ROWB + c0c*16, Ahp + (size_t)(m0 + r0c)*K + k0 + c0c*8);
            cpa16(st2 + OFF_AH + r1c*ROWB + c1c*16, Ahp + (size_t)(m0 + r1c)*K + k0 + c1c*8);
            cpa16(st2 + OFF_AL + r0c*ROWB + c0c*16, Alp + (size_t)(m0 + r0c)*K + k0 + c0c*8);
            cpa16(st2 + OFF_AL + r1c*ROWB + c1c*16, Alp + (size_t)(m0 + r1c)*K + k0 + c1c*8);
            cpa16(st2 + OFF_BH + r0c*ROWB + c0c*16, Bhp + (size_t)(n0 + r0c)*K + k0 + c0c*8);
            cpa16(st2 + OFF_BH + r1c*ROWB + c1c*16, Bhp + (size_t)(n0 + r1c)*K + k0 + c1c*8);
            cpa16(st2 + OFF_BL + r0c*ROWB + c0c*16, Blp + (size_t)(n0 + r0c)*K + k0 + c0c*8);
            cpa16(st2 + OFF_BL + r1c*ROWB + c1c*16, Blp + (size_t)(n0 + r1c)*K + k0 + c1c*8);
        }
        cp_commit();
    }
}

// plain fp32 store (z-batched), BN=128
__global__ void __launch_bounds__(256)
gemm_tc_store(const __nv_bfloat16* __restrict__ Ahp, const __nv_bfloat16* __restrict__ Alp,
              const __nv_bfloat16* __restrict__ Bhp, const __nv_bfloat16* __restrict__ Blp,
              float* __restrict__ C, int K, int N, int ldc, size_t aZ, size_t cZ)
{
    extern __shared__ char smem[];
    float acc[2][8][4];
    #pragma unroll
    for (int i = 0; i < 2; i++)
        #pragma unroll
        for (int j = 0; j < 8; j++)
            #pragma unroll
            for (int q = 0; q < 4; q++) acc[i][j][q] = 0.f;

    int m0 = blockIdx.y*128, n0 = blockIdx.x*128;
    tc_mainloop(Ahp + (size_t)blockIdx.z*aZ, Alp + (size_t)blockIdx.z*aZ,
                Bhp, Blp, K, m0, n0, smem, acc);
    C += (size_t)blockIdx.z * cZ;

    int lane = threadIdx.x & 31, wid = threadIdx.x >> 5;
    int wm = wid & 3, wn = wid >> 2;
    int gp = lane >> 2, tg = lane & 3;
    #pragma unroll
    for (int mi = 0; mi < 2; mi++) {
        int row = m0 + wm*32 + mi*16 + gp;
        #pragma unroll
        for (int ni = 0; ni < 8; ni++) {
            int col = n0 + wn*64 + ni*8 + tg*2;
            if (col < N) {
                float2 v0; v0.x = acc[mi][ni][0]; v0.y = acc[mi][ni][1];
                float2 v1; v1.x = acc[mi][ni][2]; v1.y = acc[mi][ni][3];
                *(float2*)&C[(size_t)row*ldc + col]       = v0;
                *(float2*)&C[(size_t)(row + 8)*ldc + col] = v1;
            }
        }
    }
}

// ---------------- BN=64 tensor-core GEMM (for x_proj, N=44 padded to 64) --------
#define OFF64_AH 0
#define OFF64_AL (128*ROWB)
#define OFF64_BH (2*128*ROWB)
#define OFF64_BL (OFF64_BH + 64*ROWB)
#define STAGE64  (OFF64_BL + 64*ROWB)   // 384*ROWB = 30720 B
#define SMEM_N64 (2*STAGE64)

__global__ void __launch_bounds__(256)
gemm_tc_n64(const __nv_bfloat16* __restrict__ Ahp, const __nv_bfloat16* __restrict__ Alp,
            const __nv_bfloat16* __restrict__ Bhp, const __nv_bfloat16* __restrict__ Blp,
            float* __restrict__ C, int K, int N, int ldc, size_t aZ, size_t cZ)
{
    extern __shared__ char smem[];
    u32 sbase = (u32)__cvta_generic_to_shared(smem);
    int tid = threadIdx.x;
    int lane = tid & 31, wid = tid >> 5;
    int wm = wid & 3, wn = wid >> 2;   // warp tile 32 x 32
    int m0 = blockIdx.y*128;

    Ahp += (size_t)blockIdx.z * aZ;
    Alp += (size_t)blockIdx.z * aZ;
    C   += (size_t)blockIdx.z * cZ;

    float acc[2][4][4];
    #pragma unroll
    for (int i = 0; i < 2; i++)
        #pragma unroll
        for (int j = 0; j < 4; j++)
            #pragma unroll
            for (int q = 0; q < 4; q++) acc[i][j][q] = 0.f;

    int r0c = tid >> 2, c0c = tid & 3;
    int r1c = (tid + 256) >> 2, c1c = (tid + 256) & 3;
    int rbc = tid >> 2, cbc = tid & 3;
    int NIT = K / 32;

    for (int pre = 0; pre < 2 && pre < NIT; pre++) {
        int k0 = pre * 32;
        u32 st = sbase + (u32)(pre & 1) * STAGE64;
        cpa16(st + OFF64_AH + r0c*ROWB + c0c*16, Ahp + (size_t)(m0 + r0c)*K + k0 + c0c*8);
        cpa16(st + OFF64_AH + r1c*ROWB + c1c*16, Ahp + (size_t)(m0 + r1c)*K + k0 + c1c*8);
        cpa16(st + OFF64_AL + r0c*ROWB + c0c*16, Alp + (size_t)(m0 + r0c)*K + k0 + c0c*8);
        cpa16(st + OFF64_AL + r1c*ROWB + c1c*16, Alp + (size_t)(m0 + r1c)*K + k0 + c1c*8);
        if (rbc < 64) {
            cpa16(st + OFF64_BH + rbc*ROWB + cbc*16, Bhp + (size_t)rbc*K + k0 + cbc*8);
            cpa16(st + OFF64_BL + rbc*ROWB + cbc*16, Blp + (size_t)rbc*K + k0 + cbc*8);
        }
        cp_commit();
    }

    for (int it = 0; it < NIT; it++) {
        cp_wait1();
        __syncthreads();

        u32 st = sbase + (u32)(it & 1) * STAGE64;
        #pragma unroll
        for (int ks = 0; ks < 2; ks++) {
            u32 fah0[4], fah1[4], fal0[4], fal1[4];
            {
                u32 adr0 = st + OFF64_AH + (u32)((wm*32 + (lane & 15))*ROWB
                         + ks*32 + (lane >> 4)*16);
                u32 adr1 = adr0 + 16*ROWB;
                ldsm4(fah0[0], fah0[1], fah0[2], fah0[3], adr0);
                ldsm4(fal0[0], fal0[1], fal0[2], fal0[3], adr0 + (OFF64_AL - OFF64_AH));
                ldsm4(fah1[0], fah1[1], fah1[2], fah1[3], adr1);
                ldsm4(fal1[0], fal1[1], fal1[2], fal1[3], adr1 + (OFF64_AL - OFF64_AH));
            }
            #pragma unroll
            for (int j = 0; j < 2; j++) {
                u32 fbh[4], fbl[4];
                u32 bdr = st + OFF64_BH + (u32)((wn*32 + j*16 + (lane & 15))*ROWB
                        + ks*32 + (lane >> 4)*16);
                ldsm4(fbh[0], fbh[1], fbh[2], fbh[3], bdr);
                ldsm4(fbl[0], fbl[1], fbl[2], fbl[3], bdr + (OFF64_BL - OFF64_BH));

                mma16816(acc[0][2*j][0], acc[0][2*j][1], acc[0][2*j][2], acc[0][2*j][3],
                         fah0[0], fah0[1], fah0[2], fah0[3], fbh[0], fbh[2]);
                mma16816(acc[0][2*j][0], acc[0][2*j][1], acc[0][2*j][2], acc[0][2*j][3],
                         fah0[0], fah0[1], fah0[2], fah0[3], fbl[0], fbl[2]);
                mma16816(acc[0][2*j][0], acc[0][2*j][1], acc[0][2*j][2], acc[0][2*j][3],
                         fal0[0], fal0[1], fal0[2], fal0[3], fbh[0], fbh[2]);
                mma16816(acc[0][2*j+1][0], acc[0][2*j+1][1], acc[0][2*j+1][2], acc[0][2*j+1][3],
                         fah0[0], fah0[1], fah0[2], fah0[3], fbh[1], fbh[3]);
                mma16816(acc[0][2*j+1][0], acc[0][2*j+1][1], acc[0][2*j+1][2], acc[0][2*j+1][3],
                         fah0[0], fah0[1], fah0[2], fah0[3], fbl[1], fbl[3]);
                mma16816(acc[0][2*j+1][0], acc[0][2*j+1][1], acc[0][2*j+1][2], acc[0][2*j+1][3],
                         fal0[0], fal0[1], fal0[2], fal0[3], fbh[1], fbh[3]);

                mma16816(acc[1][2*j][0], acc[1][2*j][1], acc[1][2*j][2], acc[1][2*j][3],
                         fah1[0], fah1[1], fah1[2], fah1[3], fbh[0], fbh[2]);
                mma16816(acc[1][2*j][0], acc[1][2*j][1], acc[1][2*j][2], acc[1][2*j][3],
                         fah1[0], fah1[1], fah1[2], fah1[3], fbl[0], fbl[2]);
                mma16816(acc[1][2*j][0], acc[1][2*j][1], acc[1][2*j][2], acc[1][2*j][3],
                         fal1[0], fal1[1], fal1[2], fal1[3], fbh[0], fbh[2]);
                mma16816(acc[1][2*j+1][0], acc[1][2*j+1][1], acc[1][2*j+1][2], acc[1][2*j+1][3],
                         fah1[0], fah1[1], fah1[2], fah1[3], fbh[1], fbh[3]);
                mma16816(acc[1][2*j+1][0], acc[1][2*j+1][1], acc[1][2*j+1][2], acc[1][2*j+1][3],
                         fah1[0], fah1[1], fah1[2], fah1[3], fbl[1], fbl[3]);
                mma16816(acc[1][2*j+1][0], acc[1][2*j+1][1], acc[1][2*j+1][2], acc[1][2*j+1][3],
                         fal1[0], fal1[1], fal1[2], fal1[3], fbh[1], fbh[3]);
            }
        }
        __syncthreads();
        if (it + 2 < NIT) {
            int k0 = (it + 2) * 32;
            u32 st2 = sbase + (u32)((it + 2) & 1) * STAGE64;
            cpa16(st2 + OFF64_AH + r0c*ROWB + c0c*16, Ahp + (size_t)(m0 + r0c)*K + k0 + c0c*8);
            cpa16(st2 + OFF64_AH + r1c*ROWB + c1c*16, Ahp + (size_t)(m0 + r1c)*K + k0 + c1c*8);
            cpa16(st2 + OFF64_AL + r0c*ROWB + c0c*16, Alp + (size_t)(m0 + r0c)*K + k0 + c0c*8);
            cpa16(st2 + OFF64_AL + r1c*ROWB + c1c*16, Alp + (size_t)(m0 + r1c)*K + k0 + c1c*8);
            if (rbc < 64) {
                cpa16(st2 + OFF64_BH + rbc*ROWB + cbc*16, Bhp + (size_t)rbc*K + k0 + cbc*8);
                cpa16(st2 + OFF64_BL + rbc*ROWB + cbc*16, Blp + (size_t)rbc*K + k0 + cbc*8);
            }
        }
        cp_commit();
    }

    int gp = lane >> 2, tg = lane & 3;
    #pragma unroll
    for (int mi = 0; mi < 2; mi++) {
        int row = m0 + wm*32 + mi*16 + gp;
        #pragma unroll
        for (int ni = 0; ni < 4; ni++) {
            int col = wn*32 + ni*8 + tg*2;
            if (col < N) {
                float2 v0; v0.x = acc[mi][ni][0]; v0.y = acc[mi][ni][1];
                float2 v1; v1.x = acc[mi][ni][2]; v1.y = acc[mi][ni][3];
                *(float2*)&C[(size_t)row*ldc + col]       = v0;
                *(float2*)&C[(size_t)(row + 8)*ldc + col] = v1;
            }
        }
    }
}

// transposed store to d_out laid out (B, C, L), BN=128
__global__ void __launch_bounds__(256)
gemm_tc_out(const __nv_bfloat16* __restrict__ Ahp, const __nv_bfloat16* __restrict__ Alp,
            const __nv_bfloat16* __restrict__ Bhp, const __nv_bfloat16* __restrict__ Blp,
            int K, int N, float* __restrict__ dout)
{
    extern __shared__ char smem[];
    float acc[2][8][4];
    #pragma unroll
    for (int i = 0; i < 2; i++)
        #pragma unroll
        for (int j = 0; j < 8; j++)
            #pragma unroll
            for (int q = 0; q < 4; q++) acc[i][j][q] = 0.f;

    int m0 = blockIdx.y*128, n0 = blockIdx.x*128;
    tc_mainloop(Ahp, Alp, Bhp, Blp, K, m0, n0, smem, acc);

    cp_wait0();
    __syncthreads();
    float* so = (float*)smem;   // [128][132]
    int lane = threadIdx.x & 31, wid = threadIdx.x >> 5;
    int wm = wid & 3, wn = wid >> 2;
    int gp = lane >> 2, tg = lane & 3;
    #pragma unroll
    for (int mi = 0; mi < 2; mi++) {
        int ml = wm*32 + mi*16 + gp;
        #pragma unroll
        for (int ni = 0; ni < 8; ni++) {
            int nl = wn*64 + ni*8 + tg*2;
            so[(size_t)nl*132 + ml]         = acc[mi][ni][0];
            so[(size_t)(nl+1)*132 + ml]     = acc[mi][ni][1];
            so[(size_t)nl*132 + ml + 8]     = acc[mi][ni][2];
            so[(size_t)(nl+1)*132 + ml + 8] = acc[mi][ni][3];
        }
    }
    __syncthreads();
    int b = m0 >> 12, p0 = m0 & (LL - 1);
    for (int e = threadIdx.x; e < 128*128; e += 256) {
        int nl = e >> 7, mlp = e & 127;
        int n = n0 + nl;
        if (n < N)
            dout[((size_t)(b*CC + n))*LL + p0 + mlp] = so[(size_t)nl*132 + mlp];
    }
}

// ---------------- depthwise causal conv (both directions) + silu -> bf16 hi/lo ----
__global__ void conv_silu_kernel(const float* __restrict__ cw, const float* __restrict__ cb)
{
    __shared__ float s[16 + 6][DI];
    int b = blockIdx.y, t0 = blockIdx.x * 16, d = threadIdx.x;

    #pragma unroll
    for (int j = 0; j < 22; j++) {
        int t = t0 - 3 + j;
        float v = 0.f;
        if (t >= 0 && t < LL) v = g_xz[((size_t)(b*LL + t))*768 + d];
        s[j][d] = v;
    }
    __syncthreads();
    float w0 = cw[d*4+0], w1 = cw[d*4+1], w2 = cw[d*4+2], w3 = cw[d*4+3];
    float bias = cb[d];
    #pragma unroll
    for (int tt = 0; tt < 16; tt++) {
        float of = w0*s[tt][d] + w1*s[tt+1][d] + w2*s[tt+2][d] + w3*s[tt+3][d] + bias;
        float ob = w3*s[tt+3][d] + w2*s[tt+4][d] + w1*s[tt+5][d] + w0*s[tt+6][d] + bias;
        size_t m = (size_t)(b*LL + t0 + tt);
        float vf = silu_f(of), vb = silu_f(ob);
        __nv_bfloat16 h, l;
        split_bf16(vf, h, l); g_xsh[0][m*DI + d] = h; g_xsl[0][m*DI + d] = l;
        split_bf16(vb, h, l); g_xsh[1][m*DI + d] = h; g_xsl[1][m*DI + d] = l;
    }
}

// ---------------- chunked selective scan (phase-split: dt batch + h recurrence) --
#define SROW 48   // smem row stride in floats (44 padded to 48)
#define NBUF 3
#define TB   4    // timestep batch for dt precompute

template<bool P3>
__global__ void __launch_bounds__(128)
scan_kernel(const float* __restrict__ A_log,
            const float* __restrict__ dtw,
            const float* __restrict__ dtbv,
            const float* __restrict__ Dv)
{
    __shared__ __align__(16) float sdbl[NBUF][SW][SROW];
    __shared__ __align__(16) __nv_bfloat16 sxh[NBUF][SW][128];
    __shared__ __align__(16) __nv_bfloat16 sxl[NBUF][SW][128];

    int d  = blockIdx.x * 128 + threadIdx.x;
    int d0 = blockIdx.x * 128;
    int c  = blockIdx.y;
    int rb = blockIdx.z;
    int r  = rb >> 2, b = rb & 3;
    int tid = threadIdx.x;

    const int NSEG = P3 ? 11 : 7;
    const float* dblp = g_dbl[r];
    const __nv_bfloat16* xshp = g_xsh[r];
    const __nv_bfloat16* xslp = g_xsl[r];
    u32 sb  = (u32)__cvta_generic_to_shared(&sdbl[0][0][0]);
    u32 sxh_b = (u32)__cvta_generic_to_shared(&sxh[0][0][0]);
    u32 sxl_b = (u32)__cvta_generic_to_shared(&sxl[0][0][0]);

    auto issue_win = [&](int w) {
        u32 buf = (u32)(w % NBUF);
        int nch = SW * NSEG;
        u32 dst0 = sb + buf * (SW*SROW*4);
        for (int q = tid; q < nch; q += 128) {
            int j = q / NSEG, seg = q % NSEG;
            int tau = c*LC + w*SW + j;
            int pos = r ? (LL - 1 - tau) : tau;
            size_t m = (size_t)b*LL + pos;
            cpa16(dst0 + (u32)(j*SROW + seg*4)*4, dblp + m*NDBL + seg*4);
        }
        u32 xh0 = sxh_b + buf * (SW*128*2);
        u32 xl0 = sxl_b + buf * (SW*128*2);
        for (int q = tid; q < SW*16; q += 128) {
            int j = q >> 4, seg = q & 15;
            int tau = c*LC + w*SW + j;
            int pos = r ? (LL - 1 - tau) : tau;
            size_t m = (size_t)b*LL + pos;
            cpa16(xh0 + (u32)(j*128 + seg*8)*2, xshp + m*DI + d0 + seg*8);
            cpa16(xl0 + (u32)(j*128 + seg*8)*2, xslp + m*DI + d0 + seg*8);
        }
        cp_commit();
    };

    float A2[DS], wdt[DTR];
    bool structured = true;
    #pragma unroll
    for (int sIdx = 0; sIdx < DS; sIdx++)
        A2[sIdx] = -__expf(A_log[d*DS + sIdx]) * LOG2E;
    #pragma unroll
    for (int sIdx = 1; sIdx < DS; sIdx++)
        structured &= fabsf(A2[sIdx] - (sIdx+1)*A2[0]) <= 1e-4f*fabsf(A2[sIdx]);
    #pragma unroll
    for (int j = 0; j < DTR; j++) wdt[j] = dtw[d*DTR + j];
    float dtb = dtbv[d];
    float Dval = P3 ? Dv[d] : 0.f;

    u64 wdt2[6];
    #pragma unroll
    for (int k = 0; k < 6; k++) wdt2[k] = pk2(wdt[2*k], wdt[2*k+1]);

    size_t base = (((size_t)rb*NC + c)*DI + d)*DS;
    u64 hp[DS/2];
    #pragma unroll
    for (int k = 0; k < DS/2; k++) {
        if (P3) {
            float2 hv = *(const float2*)&g_hstart[base + 2*k];
            hp[k] = pk2(hv.x, hv.y);
        } else {
            hp[k] = 0ull;
        }
    }

    float* yp = g_y[r];
    float S = 0.f;

    issue_win(0);
    if (NW > 1) issue_win(1);
    if (NW > 2) issue_win(2);

    for (int w = 0; w < NW; w++) {
        if (w + 3 <= NW - 1)      cp_wait2();
        else if (w + 2 <= NW - 1) cp_wait1();
        else                      cp_wait0();
        __syncthreads();
        int buf = w % NBUF;
        const float (*row)[SROW] = sdbl[buf];

        for (int jb = 0; jb < SW; jb += TB) {
            // ---- phase A: TB independent dt / u / e1 chains (ILP) ----
            float e1a[TB], ua[TB];
            u64 dtx2a[TB];
            #pragma unroll
            for (int q = 0; q < TB; q++) {
                int j = jb + q;
                u64 acc2 = 0ull;
                #pragma unroll
                for (int k = 0; k < 6; k++) {
                    u64 iv = *(const u64*)&row[j][2*k];
                    acc2 = fma2_(iv, wdt2[k], acc2);
                }
                float alo, ahi; upk2(alo, ahi, acc2);
                float dt = sp_f(dtb + alo + ahi);
                float u  = b2f(sxh[buf][j][tid]) + b2f(sxl[buf][j][tid]);
                float dtx = dt * u;
                dtx2a[q] = pk2(dtx, dtx);
                e1a[q]   = ex2(dt * A2[0]);
                ua[q]    = u;
                if (!P3) S += dt;
                if (!structured) { ua[q] = u; e1a[q] = dt; } // carry dt for fallback
            }
            // ---- phase B: h recurrence with precomputed coefficients ----
            #pragma unroll
            for (int q = 0; q < TB; q++) {
                int j = jb + q;
                float y = 0.f;
                if (structured) {
                    float e1 = e1a[q];
                    float ee = e1 * e1;
                    u64 eep = pk2(ee, ee);
                    u64 ap  = pk2(e1, ee);
                    u64 dtx2 = dtx2a[q];
                    u64 y2 = 0ull;
                    #pragma unroll
                    for (int k = 0; k < DS/2; k++) {
                        u64 Bp = *(const u64*)&row[j][DTR + 2*k];
                        hp[k] = fma2_(ap, hp[k], mul2_(dtx2, Bp));
                        if (P3) {
                            u64 Cp = *(const u64*)&row[j][DTR + DS + 2*k];
                            y2 = fma2_(hp[k], Cp, y2);
                        }
                        if (k < DS/2 - 1) ap = mul2_(ap, eep);
                    }
                    if (P3) { float yl, yh; upk2(yl, yh, y2); y = yl + yh; }
                } else {
                    float dt = e1a[q];           // fallback: e1a carries dt
                    float dtxl, dtxh; upk2(dtxl, dtxh, dtx2a[q]);
                    #pragma unroll
                    for (int k = 0; k < DS/2; k++) {
                        float h0, h1; upk2(h0, h1, hp[k]);
                        float a0 = ex2(dt * A2[2*k]);
                        float a1 = ex2(dt * A2[2*k+1]);
                        float B0 = row[j][DTR + 2*k], B1 = row[j][DTR + 2*k+1];
                        h0 = fmaf(a0, h0, dtxl * B0);
                        h1 = fmaf(a1, h1, dtxl * B1);
                        if (P3) {
                            y = fmaf(h0, row[j][DTR + DS + 2*k], y);
                            y = fmaf(h1, row[j][DTR + DS + 2*k+1], y);
                        }
                        hp[k] = pk2(h0, h1);
                    }
                }
                if (P3) {
                    int tau = c*LC + w*SW + j;
                    int pos = r ? (LL - 1 - tau) : tau;
                    size_t m = (size_t)b*LL + pos;
                    y = fmaf(ua[q], Dval, y);
                    yp[m*DI + d] = y;
                }
            }
        }
        __syncthreads();
        if (w + NBUF < NW) issue_win(w + NBUF);
    }

    if (!P3) {
        #pragma unroll
        for (int k = 0; k < DS/2; k++) {
            float h0, h1; upk2(h0, h1, hp[k]);
            float2 hv; hv.x = h0; hv.y = h1;
            *(float2*)&g_hend[base + 2*k] = hv;
            float2 pv;
            pv.x = ex2(A2[2*k]   * S);
            pv.y = ex2(A2[2*k+1] * S);
            *(float2*)&g_pend[base + 2*k] = pv;
        }
    }
}

__global__ void scan_combine()
{
    int g = blockIdx.x * 256 + threadIdx.x;
    if (g >= 2*BB*DI*DS) return;
    int sd = g % (DI*DS);
    int rb = g / (DI*DS);
    float carry = 0.f;
    for (int c = 0; c < NC; c++) {
        size_t idx = ((size_t)rb*NC + c)*(DI*DS) + sd;
        g_hstart[idx] = carry;
        carry = g_pend[idx]*carry + g_hend[idx];
    }
}

// ---------------- fused gate -> bf16 hi/lo (xs-free; 4 elems/thread) ------------
__global__ void combine_G(const float* __restrict__ Dv)
{
    size_t g4 = (size_t)blockIdx.x * 256 + threadIdx.x;
    if (g4 >= (size_t)MM*DI/4) return;
    int d4 = (int)(g4 % (DI/4));
    size_t m = g4 / (DI/4);
    int d = 4*d4;
    size_t gi = m*DI + d;

    float4 z  = *(const float4*)&g_xz[m*768 + DI + d];
    float4 y0 = *(const float4*)&g_y[0][gi];
    float4 y1 = *(const float4*)&g_y[1][gi];

    float v0 = silu_f(z.x) * (y0.x + y1.x);
    float v1 = silu_f(z.y) * (y0.y + y1.y);
    float v2 = silu_f(z.z) * (y0.z + y1.z);
    float v3 = silu_f(z.w) * (y0.w + y1.w);
    __nv_bfloat16 h0, l0, h1, l1, h2, l2, h3, l3;
    split_bf16(v0, h0, l0); split_bf16(v1, h1, l1);
    split_bf16(v2, h2, l2); split_bf16(v3, h3, l3);
    __nv_bfloat162 ph0 = mk2(h0, h1), ph1 = mk2(h2, h3);
    __nv_bfloat162 pl0 = mk2(l0, l1), pl1 = mk2(l2, l3);
    *(u64*)&g_Gh[gi] = ((u64)*(u32*)&ph1 << 32) | *(u32*)&ph0;
    *(u64*)&g_Gl[gi] = ((u64)*(u32*)&pl1 << 32) | *(u32*)&pl0;
}

// ---------------- launch ----------------
static void* sym_addr(const void* sym) {
    void* p = nullptr;
    cudaGetSymbolAddress(&p, sym);
    return p;
}

extern "C" void kernel_launch(void* const* d_in, const int* in_sizes, int n_in,
                              void* d_out, int out_size)
{
    const float* x          = (const float*)d_in[0];
    const float* ln_w       = (const float*)d_in[1];
    const float* ln_b       = (const float*)d_in[2];
    const float* in_proj_w  = (const float*)d_in[3];
    const float* conv_w     = (const float*)d_in[4];
    const float* conv_b     = (const float*)d_in[5];
    const float* x_proj_w   = (const float*)d_in[6];
    const float* dt_proj_w  = (const float*)d_in[7];
    const float* dt_proj_b  = (const float*)d_in[8];
    const float* A_log      = (const float*)d_in[9];
    const float* D_vec      = (const float*)d_in[10];
    const float* out_proj_w = (const float*)d_in[11];
    float* out = (float*)d_out;

    float* p_xz  = (float*)sym_addr(g_xz);
    float* p_dbl = (float*)sym_addr(g_dbl);
    __nv_bfloat16* p_xnh = (__nv_bfloat16*)sym_addr(g_xnh);
    __nv_bfloat16* p_xnl = (__nv_bfloat16*)sym_addr(g_xnl);
    __nv_bfloat16* p_xsh = (__nv_bfloat16*)sym_addr(g_xsh);
    __nv_bfloat16* p_xsl = (__nv_bfloat16*)sym_addr(g_xsl);
    __nv_bfloat16* p_Gh  = (__nv_bfloat16*)sym_addr(g_Gh);
    __nv_bfloat16* p_Gl  = (__nv_bfloat16*)sym_addr(g_Gl);
    __nv_bfloat16* p_wih = (__nv_bfloat16*)sym_addr(g_wih);
    __nv_bfloat16* p_wil = (__nv_bfloat16*)sym_addr(g_wil);
    __nv_bfloat16* p_wxh = (__nv_bfloat16*)sym_addr(g_wxh);
    __nv_bfloat16* p_wxl = (__nv_bfloat16*)sym_addr(g_wxl);
    __nv_bfloat16* p_woh = (__nv_bfloat16*)sym_addr(g_woh);
    __nv_bfloat16* p_wol = (__nv_bfloat16*)sym_addr(g_wol);

    cudaFuncSetAttribute((const void*)gemm_tc_store,
                         cudaFuncAttributeMaxDynamicSharedMemorySize, SMEM_TC);
    cudaFuncSetAttribute((const void*)gemm_tc_out,
                         cudaFuncAttributeMaxDynamicSharedMemorySize, SMEM_TC);
    cudaFuncSetAttribute((const void*)gemm_tc_n64,
                         cudaFuncAttributeMaxDynamicSharedMemorySize, SMEM_N64);

    // 1) LayerNorm -> bf16 hi/lo
    ln_kernel<<<dim3(LL/32, BB), dim3(32, 8)>>>(x, ln_w, ln_b);

    // 1b) weight conversion
    cvt_weights<<<256, 256>>>(in_proj_w, x_proj_w, out_proj_w);

    // 2) in_proj: xz[M,768] = xn @ Wi^T  (tensor cores)
    gemm_tc_store<<<dim3(768/128, MM/128, 1), 256, SMEM_TC>>>(
        p_xnh, p_xnl, p_wih, p_wil, p_xz, CC, 768, 768, 0, 0);

    // 3) conv + silu (both directions) -> bf16 hi/lo
    conv_silu_kernel<<<dim3(LL/16, BB), DI>>>(conv_w, conv_b);

    // 4) x_proj both dirs: dbl[M,44] = xs @ Wx^T  (BN=64 tensor cores)
    gemm_tc_n64<<<dim3(1, MM/128, 2), 256, SMEM_N64>>>(
        p_xsh, p_xsl, p_wxh, p_wxl, p_dbl, DI, NDBL, NDBL,
        (size_t)MM*DI, (size_t)MM*NDBL);

    // 5-8) chunked selective scan (phase-split dt precompute, 3-deep prefetch)
    scan_kernel<false><<<dim3(DI/128, NC, 2*BB), 128>>>(A_log, dt_proj_w, dt_proj_b, D_vec);
    scan_combine<<<dim3((2*BB*DI*DS + 255)/256), 256>>>();
    scan_kernel<true><<<dim3(DI/128, NC, 2*BB), 128>>>(A_log, dt_proj_w, dt_proj_b, D_vec);

    // 9) fused gate -> bf16 hi/lo (xs-free, 4-wide vectorized)
    combine_G<<<dim3((MM*DI/4 + 255)/256), 256>>>(D_vec);

    // 10) out_proj (tensor cores) with transposed store to (B,C,H,W)
    gemm_tc_out<<<dim3(2, MM/128, 1), 256, SMEM_TC>>>(
        p_Gh, p_Gl, p_woh, p_wol, DI, CC, out);
}